// round 12
// baseline (speedup 1.0000x reference)
#include <cuda_runtime.h>
#include <cuda_fp16.h>
#include <math.h>
#include <stdint.h>

// ---------------- problem constants ----------------
#define Bb   4
#define Ss   4096
#define Dd   768
#define Hh   12
#define Mm   256
#define DhD  64
#define NROWS (Bb*Ss)        // 16384
#define NBH   (Bb*Hh)        // 48
#define NHR   (NBH*Ss)       // 196608
#define FFH   (4*Dd)         // 3072

#define NORM_C   0.35355339059327373f
#define RATIO_C  0.0625f
#define DIAG_C   0.0625f
#define EPS_K    1e-4f
#define LN_EPS   1e-5f

// ---------------- scratch (device globals; allocation-free) ----------------
__device__ __half g_wqkvh[3*Dd*Dd];
__device__ float  g_bqkv[3*Dd];
__device__ __half g_woh[Dd*Dd];
__device__ __half g_w1h[FFH*Dd];
__device__ __half g_w2h[Dd*FFH];
__device__ __half g_projh[Mm*DhD];
__device__ __half g_h1h[NROWS*Dd];
__device__ __half g_qkvh[3*(size_t)NHR*DhD];      // q,k,v in [sel][b,h,s,dh]
__device__ __half g_qkph[2*(size_t)NHR*Mm];       // [qp | kp(exp(dd-rowmax))]
__device__ __half g_midh[(size_t)NROWS*FFH];
__device__ __half g_ctxTh[NBH*DhD*Mm];            // [bh][dh][m]
__device__ __half g_attn2h[(size_t)NROWS*Dd];     // [b,s,D]
__device__ float  g_x2[NROWS*Dd];
__device__ float  g_diag[2*NHR];                  // [q rows | k rows]
__device__ float  g_rowf[NHR];                    // rowmax(dd_k) - diag_k
__device__ float  g_ksum[NBH*Mm];
__device__ float  g_dinv[NHR];
__device__ unsigned g_gmax_u;

// ---------------- epilogue modes ----------------
enum { EPI_BIAS_RES=1, EPI_BIAS_GELU=2, EPI_QKV=5, EPI_FEAT=6, EPI_ATTN=8 };

__device__ __forceinline__ void cpa16(uint32_t smem_dst, const void* gsrc){
    asm volatile("cp.async.cg.shared.global [%0], [%1], 16;" :: "r"(smem_dst), "l"(gsrc));
}
#define CP_COMMIT() asm volatile("cp.async.commit_group;" ::: "memory")
#define CP_WAIT0()  asm volatile("cp.async.wait_group 0;" ::: "memory")
#define CP_WAIT1()  asm volatile("cp.async.wait_group 1;" ::: "memory")

__device__ __forceinline__ uint32_t smem_u32(const void* p){
    uint32_t a;
    asm("{ .reg .u64 t; cvta.to.shared.u64 t, %1; cvt.u32.u64 %0, t; }" : "=r"(a) : "l"(p));
    return a;
}

__device__ __forceinline__ void mma_f16(float* d, const uint32_t* a, const uint32_t* b){
    asm volatile("mma.sync.aligned.m16n8k16.row.col.f32.f16.f16.f32 "
        "{%0,%1,%2,%3}, {%4,%5,%6,%7}, {%8,%9}, {%0,%1,%2,%3};"
        : "+f"(d[0]),"+f"(d[1]),"+f"(d[2]),"+f"(d[3])
        : "r"(a[0]),"r"(a[1]),"r"(a[2]),"r"(a[3]), "r"(b[0]),"r"(b[1]));
}
#define LDSM4(r0,r1,r2,r3,addr) \
    asm volatile("ldmatrix.sync.aligned.m8n8.x4.shared.b16 {%0,%1,%2,%3}, [%4];" \
        : "=r"(r0),"=r"(r1),"=r"(r2),"=r"(r3) : "r"(addr))
#define LDSM4T(r0,r1,r2,r3,addr) \
    asm volatile("ldmatrix.sync.aligned.m8n8.x4.trans.shared.b16 {%0,%1,%2,%3}, [%4];" \
        : "=r"(r0),"=r"(r1),"=r"(r2),"=r"(r3) : "r"(addr))

__device__ __forceinline__ float gmax_decode(unsigned u){
    return (u & 0x80000000u) ? __uint_as_float(u ^ 0x80000000u) : __uint_as_float(~u);
}

// ================= fp16 NT GEMM: mma.sync m16n8k16, BK=64, 2-stage cp.async ============
template<int BM,int BN,int EPI,bool OUTH>
__global__ void __launch_bounds__(32*(BM/64)*(BN/32), (BM==128 && BN==64) ? 3 : 2)
hgemm(const __half* __restrict__ A, int lda, long long strA,
      const __half* __restrict__ B, int ldb, long long strB,
      void* __restrict__ Cv, int ldc, long long strC,
      int M, int N, int K,
      const float* __restrict__ bias,
      const float* __restrict__ res,
      const float* __restrict__ rowscale,
      float alpha)
{
    constexpr int WY = BM/64, WX = BN/32, THREADS = 32*WY*WX;
    constexpr int LDKW = 36;                 // 32 data words (64 halfs) + 4 pad
    constexpr int AW = BM*LDKW;
    constexpr int SW = (BM+BN)*LDKW;
    constexpr int ALD = (BM*8)/THREADS;
    constexpr int BLD = (BN*8)/THREADS;

    extern __shared__ uint32_t sh[];
    const uint32_t smb = smem_u32(sh);

    const int z = blockIdx.z;
    A += (long long)z*strA;  B += (long long)z*strB;
    float*  Cf = (float*)Cv  + (long long)z*strC;
    __half* Ch = (__half*)Cv + (long long)z*strC;

    const int brow = blockIdx.y*BM;
    const int bcol = blockIdx.x*BN;
    const int tid  = threadIdx.x;
    const int wid  = tid >> 5;
    const int lane = tid & 31;
    const int wx   = wid % WX, wy = wid / WX;
    const int warp_m = wy*64, warp_n = wx*32;
    const int g = lane >> 2, t = lane & 3;

    const uint32_t aoff = (uint32_t)(((warp_m + (lane&15))*LDKW + (lane>>4)*4))*4u;
    const uint32_t boff = (uint32_t)((AW + (warp_n + (lane>>4)*8 + (lane&7))*LDKW + ((lane>>3)&1)*4))*4u;

    float acc[4][4][4];
    #pragma unroll
    for (int i=0;i<4;i++)
        #pragma unroll
        for (int j=0;j<4;j++)
            #pragma unroll
            for (int u=0;u<4;u++) acc[i][j][u]=0.f;

    const int nc = K >> 6;

    #define HISSUE(chunk) do{                                                  \
        const uint32_t bA_ = smb + (uint32_t)(((chunk)&1)*SW)*4u;              \
        const uint32_t bB_ = bA_ + (uint32_t)AW*4u;                            \
        const __half* Ap_ = A + (long long)brow*lda + (chunk)*64;              \
        const __half* Bp_ = B + (long long)bcol*ldb + (chunk)*64;              \
        _Pragma("unroll")                                                      \
        for (int l=0;l<ALD;l++){                                               \
            const int idx = tid + l*THREADS, r = idx>>3, c4 = idx&7;           \
            cpa16(bA_ + (uint32_t)(r*LDKW + c4*4)*4u,                          \
                  Ap_ + (long long)r*lda + c4*8);                              \
        }                                                                      \
        _Pragma("unroll")                                                      \
        for (int l=0;l<BLD;l++){                                               \
            const int idx = tid + l*THREADS, r = idx>>3, c4 = idx&7;           \
            cpa16(bB_ + (uint32_t)(r*LDKW + c4*4)*4u,                          \
                  Bp_ + (long long)r*ldb + c4*8);                              \
        }                                                                      \
    }while(0)

    HISSUE(0);
    CP_COMMIT();

    for (int i=0; i<nc; ++i){
        CP_WAIT0();
        __syncthreads();
        if (i+1 < nc){ HISSUE(i+1); CP_COMMIT(); }

        const uint32_t stg = smb + (uint32_t)((i&1)*SW)*4u;

        #pragma unroll
        for (int kk=0; kk<4; ++kk){
            uint32_t af[4][4], bf[4][2];
            #pragma unroll
            for (int mt=0; mt<4; ++mt)
                LDSM4(af[mt][0],af[mt][1],af[mt][2],af[mt][3],
                      stg + aoff + (uint32_t)((mt*16*LDKW + kk*8))*4u);
            LDSM4(bf[0][0],bf[0][1],bf[1][0],bf[1][1],
                  stg + boff + (uint32_t)(kk*8)*4u);
            LDSM4(bf[2][0],bf[2][1],bf[3][0],bf[3][1],
                  stg + boff + (uint32_t)((16*LDKW + kk*8))*4u);
            #pragma unroll
            for (int mt=0; mt<4; ++mt)
                #pragma unroll
                for (int nt=0; nt<4; ++nt)
                    mma_f16(acc[mt][nt], af[mt], bf[nt]);
        }
        __syncthreads();
    }
    #undef HISSUE

    // ================= epilogues =================
    if (EPI==EPI_FEAT){
        // z==0: q features (RATIO*(exp(dd-diag-rowmax)+eps));
        // z==1: k features (exp(dd-rowmax)), rowf = rowmax-diag, gmax atomic.
        float mxs[4][2];
        #pragma unroll
        for (int mt=0; mt<4; ++mt){
            float m0=-3.402823466e38f, m1=m0;
            #pragma unroll
            for (int nt=0; nt<4; ++nt){
                #pragma unroll
                for (int u=0;u<4;u++) acc[mt][nt][u]*=alpha;
                m0 = fmaxf(m0, fmaxf(acc[mt][nt][0], acc[mt][nt][1]));
                m1 = fmaxf(m1, fmaxf(acc[mt][nt][2], acc[mt][nt][3]));
            }
            m0 = fmaxf(m0, __shfl_xor_sync(0xffffffffu,m0,1));
            m0 = fmaxf(m0, __shfl_xor_sync(0xffffffffu,m0,2));
            m1 = fmaxf(m1, __shfl_xor_sync(0xffffffffu,m1,1));
            m1 = fmaxf(m1, __shfl_xor_sync(0xffffffffu,m1,2));
            mxs[mt][0]=m0; mxs[mt][1]=m1;
        }
        __syncthreads();
        float* red = (float*)sh;               // [64][8]
        if (t==0){
            #pragma unroll
            for (int mt=0; mt<4; ++mt){
                red[(mt*16+g)*8 + wid]   = mxs[mt][0];
                red[(mt*16+8+g)*8 + wid] = mxs[mt][1];
            }
        }
        __syncthreads();
        #pragma unroll
        for (int mt=0; mt<4; ++mt){
            const int grow = brow + mt*16 + g;
            float mx0 = red[(mt*16+g)*8], mx1 = red[(mt*16+8+g)*8];
            #pragma unroll
            for (int w=1; w<8; ++w){
                mx0 = fmaxf(mx0, red[(mt*16+g)*8+w]);
                mx1 = fmaxf(mx1, red[(mt*16+8+g)*8+w]);
            }
            mxs[mt][0]=mx0; mxs[mt][1]=mx1;
            float d0, d1;
            if (z==0){ d0 = rowscale[grow] + mx0; d1 = rowscale[grow+8] + mx1; }
            else     { d0 = mx0;                  d1 = mx1; }
            #pragma unroll
            for (int nt=0; nt<4; ++nt){
                const int c0 = warp_n + nt*8 + 2*t;
                __half2 o0, o1;
                if (z==0){
                    o0 = __floats2half2_rn(RATIO_C*(__expf(acc[mt][nt][0]-d0)+EPS_K),
                                           RATIO_C*(__expf(acc[mt][nt][1]-d0)+EPS_K));
                    o1 = __floats2half2_rn(RATIO_C*(__expf(acc[mt][nt][2]-d1)+EPS_K),
                                           RATIO_C*(__expf(acc[mt][nt][3]-d1)+EPS_K));
                } else {
                    o0 = __floats2half2_rn(__expf(acc[mt][nt][0]-d0), __expf(acc[mt][nt][1]-d0));
                    o1 = __floats2half2_rn(__expf(acc[mt][nt][2]-d1), __expf(acc[mt][nt][3]-d1));
                }
                *reinterpret_cast<__half2*>(Ch + (long long)grow*ldc + c0)     = o0;
                *reinterpret_cast<__half2*>(Ch + (long long)(grow+8)*ldc + c0) = o1;
            }
            if (z==1 && wid==0 && t==0){
                float* rowf = const_cast<float*>(res);
                rowf[grow]   = mx0 - rowscale[(long long)NHR + grow];
                rowf[grow+8] = mx1 - rowscale[(long long)NHR + grow+8];
            }
        }
        if (z==1 && wid==0){
            float bm = fmaxf(fmaxf(mxs[0][0],mxs[0][1]), fmaxf(mxs[1][0],mxs[1][1]));
            bm = fmaxf(bm, fmaxf(fmaxf(mxs[2][0],mxs[2][1]), fmaxf(mxs[3][0],mxs[3][1])));
            #pragma unroll
            for (int o=16;o;o>>=1) bm = fmaxf(bm, __shfl_xor_sync(0xffffffffu,bm,o));
            if (lane==0){
                unsigned b = __float_as_uint(bm);
                unsigned u = (b & 0x80000000u) ? ~b : (b | 0x80000000u);
                atomicMax(&g_gmax_u, u);
            }
        }
        return;
    }

    float sq[4][2];
    if (EPI==EPI_QKV){
        #pragma unroll
        for (int mt=0; mt<4; ++mt){ sq[mt][0]=0.f; sq[mt][1]=0.f; }
    }

    #pragma unroll
    for (int mt=0; mt<4; ++mt){
        const int r0 = brow + warp_m + mt*16 + g;
        const int r1 = r0 + 8;
        float rs0 = 1.f, rs1 = 1.f;
        if (EPI==EPI_ATTN){
            rs0 = rowscale[(long long)z*M + r0];
            rs1 = rowscale[(long long)z*M + r1];
        }
        #pragma unroll
        for (int nt=0; nt<4; ++nt){
            const int c0 = bcol + warp_n + nt*8 + 2*t;
            float v00 = acc[mt][nt][0], v01 = acc[mt][nt][1];
            float v10 = acc[mt][nt][2], v11 = acc[mt][nt][3];
            if (EPI==EPI_BIAS_RES || EPI==EPI_BIAS_GELU || EPI==EPI_QKV){
                const float b0 = bias[c0], b1 = bias[c0+1];
                v00 += b0; v01 += b1; v10 += b0; v11 += b1;
            }
            if (EPI==EPI_BIAS_RES){
                v00 += res[(long long)r0*ldc + c0];   v01 += res[(long long)r0*ldc + c0+1];
                v10 += res[(long long)r1*ldc + c0];   v11 += res[(long long)r1*ldc + c0+1];
            }
            if (EPI==EPI_BIAS_GELU){
                v00 = 0.5f*v00*(1.0f+erff(v00*0.70710678118654752f));
                v01 = 0.5f*v01*(1.0f+erff(v01*0.70710678118654752f));
                v10 = 0.5f*v10*(1.0f+erff(v10*0.70710678118654752f));
                v11 = 0.5f*v11*(1.0f+erff(v11*0.70710678118654752f));
            }
            if (EPI==EPI_ATTN){ v00*=rs0; v01*=rs0; v10*=rs1; v11*=rs1; }

            if (EPI==EPI_QKV){
                sq[mt][0] += v00*v00 + v01*v01;
                sq[mt][1] += v10*v10 + v11*v11;
                const int sel = c0/Dd, cc = c0 - sel*Dd;
                const int h_ = cc>>6, dh_ = cc&63;
                const int b0_ = r0>>12, s0_ = r0&4095;
                const int b1_ = r1>>12, s1_ = r1&4095;
                __half* base = (__half*)Cv + (size_t)sel*NHR*DhD;
                *reinterpret_cast<__half2*>(base + ((((long long)(b0_*Hh+h_))<<12)+s0_)*DhD + dh_) = __floats2half2_rn(v00,v01);
                *reinterpret_cast<__half2*>(base + ((((long long)(b1_*Hh+h_))<<12)+s1_)*DhD + dh_) = __floats2half2_rn(v10,v11);
            } else if (EPI==EPI_ATTN){
                const int bb = z/Hh, hh = z - (z/Hh)*Hh;
                __half* base = (__half*)Cv;
                const long long o0 = ((long long)(bb*Ss + r0))*Dd + hh*64 + c0;
                const long long o1 = ((long long)(bb*Ss + r1))*Dd + hh*64 + c0;
                *reinterpret_cast<__half2*>(base + o0) = __floats2half2_rn(v00,v01);
                *reinterpret_cast<__half2*>(base + o1) = __floats2half2_rn(v10,v11);
            } else if (OUTH){
                *reinterpret_cast<__half2*>(Ch + (long long)r0*ldc + c0) = __floats2half2_rn(v00,v01);
                *reinterpret_cast<__half2*>(Ch + (long long)r1*ldc + c0) = __floats2half2_rn(v10,v11);
            } else {
                float2 o0; o0.x=v00; o0.y=v01;
                float2 o1; o1.x=v10; o1.y=v11;
                *reinterpret_cast<float2*>(Cf + (long long)r0*ldc + c0) = o0;
                *reinterpret_cast<float2*>(Cf + (long long)r1*ldc + c0) = o1;
            }
        }
    }

    // fused diag for q/k tiles: g_diag[sel*NHR + row] = DIAG_C * sum(head 64 cols of v^2)
    if (EPI==EPI_QKV){
        const int sel_t = bcol/Dd;
        const int cc0   = bcol - sel_t*Dd;
        float* red = (float*)sh;               // [128 rows][4 wx]
        #pragma unroll
        for (int mt=0; mt<4; ++mt){
            #pragma unroll
            for (int j=0;j<2;j++){
                float v = sq[mt][j];
                v += __shfl_xor_sync(0xffffffffu, v, 1);
                v += __shfl_xor_sync(0xffffffffu, v, 2);
                if (t==0) red[(warp_m + mt*16 + j*8 + g)*4 + wx] = v;
            }
        }
        __syncthreads();
        if (sel_t < 2){
            const int row  = tid >> 1;
            const int head = tid & 1;
            const float ssum = red[row*4 + 2*head] + red[row*4 + 2*head + 1];
            const int gr = brow + row;
            const int b_ = gr>>12, s_ = gr&4095;
            const int h_ = (cc0>>6) + head;
            g_diag[(size_t)sel_t*NHR + (((long long)(b_*Hh+h_))<<12) + s_] = DIAG_C*ssum;
        }
    }
}

#define SMEM_H128x128 (2*(128+128)*36*4)   // 73728
#define SMEM_H64x256  (2*(64+256)*36*4)    // 92160
#define SMEM_H128x64  (2*(128+64)*36*4)    // 55296

// ================ ctx TN mma kernel, 4-way m split (BK=32, 3-stage) ====================
#define CTX_LDV 36
#define CTX_LDP 36
#define CTX_VW  (32*CTX_LDV)
#define CTX_PW  (32*CTX_LDP)
#define SMEM_CTX (3*(CTX_VW+CTX_PW)*4)     // 27648

__global__ void __launch_bounds__(256, 2)
ctx_mma(const __half* __restrict__ kpe, const __half* __restrict__ vh,
        const float* __restrict__ rowf,
        __half* __restrict__ ctxT, float* __restrict__ ksum)
{
    extern __shared__ uint32_t sh[];
    const uint32_t smb = smem_u32(sh);
    const uint32_t pbase = smb + (uint32_t)(3*CTX_VW)*4u;

    const int z = blockIdx.y;
    const int ntile = blockIdx.x;               // 0..3, 64 m-cols each
    const int tid = threadIdx.x, wid = tid>>5, lane = tid&31;
    const int warp_m = (wid & 3)*16;            // dh tile
    const int warp_n = (wid >> 2)*32;           // m tile
    const int g = lane>>2, t = lane&3;
    const int quad = lane>>3, r8 = lane&7;

    const __half* kpb = kpe + (long long)z*Ss*Mm + ntile*64;
    const __half* vhb = vh  + (long long)z*Ss*DhD;
    const float*  rfb = rowf + (long long)z*Ss;

    const float gmax = gmax_decode(g_gmax_u);
    const float epsr = RATIO_C*EPS_K;

    const uint32_t a_off0 = (uint32_t)((r8 + ((quad>>1)&1)*8)*CTX_LDV + (warp_m + (quad&1)*8)/2);
    const uint32_t b_off0 = (uint32_t)((r8 + (quad&1)*8)*CTX_LDP + (warp_n + (quad>>1)*8)/2);

    const int srow = tid >> 3;     // 0..31
    const int c8   = tid & 7;      // 8-half group

    float acc[4][4];
    #pragma unroll
    for (int j=0;j<4;j++)
        #pragma unroll
        for (int u=0;u<4;u++) acc[j][u]=0.f;
    float ks[8];
    #pragma unroll
    for (int j=0;j<8;j++) ks[j]=0.f;

    #define VISSUE(c) do{ \
        const uint32_t bV = smb + (uint32_t)(((c)%3)*CTX_VW)*4u; \
        cpa16(bV + (uint32_t)(srow*CTX_LDV + c8*4)*4u, \
              vhb + (long long)((c)*32 + srow)*DhD + c8*8); \
    }while(0)

    uint4 cur; float curf;
    cur  = *reinterpret_cast<const uint4*>(kpb + (long long)srow*Mm + c8*8);
    curf = rfb[srow];
    VISSUE(0); CP_COMMIT();
    VISSUE(1); CP_COMMIT();

    for (int i=0; i<Ss/32; ++i){
        {
            const float As = RATIO_C*__expf(curf - gmax);
            uint32_t rw[4] = {cur.x,cur.y,cur.z,cur.w};
            uint32_t ow[4];
            #pragma unroll
            for (int j=0;j<4;j++){
                float2 f = __half22float2(*reinterpret_cast<__half2*>(&rw[j]));
                f.x = fmaf(f.x, As, epsr);
                f.y = fmaf(f.y, As, epsr);
                __half2 h = __floats2half2_rn(f.x, f.y);
                float2 fr = __half22float2(h);
                ks[2*j]   += fr.x;
                ks[2*j+1] += fr.y;
                ow[j] = *reinterpret_cast<uint32_t*>(&h);
            }
            const uint32_t bP = pbase + (uint32_t)((i%3)*CTX_PW)*4u
                              + (uint32_t)(srow*CTX_LDP + c8*4)*4u;
            uint4 s0 = {ow[0],ow[1],ow[2],ow[3]};
            *reinterpret_cast<uint4*>((char*)sh + (bP - smb)) = s0;
        }
        CP_WAIT1();
        __syncthreads();
        if (i+2 < Ss/32) VISSUE(i+2);
        CP_COMMIT();
        if (i+1 < Ss/32){
            cur  = *reinterpret_cast<const uint4*>(kpb + (long long)((i+1)*32 + srow)*Mm + c8*8);
            curf = rfb[(i+1)*32 + srow];
        }

        const uint32_t vstg = smb + (uint32_t)((i%3)*CTX_VW)*4u;
        const uint32_t pstg = pbase + (uint32_t)((i%3)*CTX_PW)*4u;

        #pragma unroll
        for (int kk=0; kk<2; ++kk){
            uint32_t af[4], bf[4][2];
            LDSM4T(af[0],af[1],af[2],af[3],
                   vstg + (a_off0 + (uint32_t)(kk*16*CTX_LDV))*4u);
            #pragma unroll
            for (int pp2=0; pp2<2; ++pp2)
                LDSM4T(bf[2*pp2][0],bf[2*pp2][1],bf[2*pp2+1][0],bf[2*pp2+1][1],
                       pstg + (b_off0 + (uint32_t)(kk*16*CTX_LDP + pp2*8))*4u);
            #pragma unroll
            for (int nt=0; nt<4; ++nt)
                mma_f16(acc[nt], af, bf[nt]);
        }
    }
    #undef VISSUE

    const int dh0 = warp_m + g;
    const int dh1 = dh0 + 8;
    #pragma unroll
    for (int nt=0; nt<4; ++nt){
        const int col = ntile*64 + warp_n + nt*8 + 2*t;
        *reinterpret_cast<__half2*>(ctxT + (long long)z*DhD*Mm + (long long)dh0*Mm + col)
            = __floats2half2_rn(acc[nt][0], acc[nt][1]);
        *reinterpret_cast<__half2*>(ctxT + (long long)z*DhD*Mm + (long long)dh1*Mm + col)
            = __floats2half2_rn(acc[nt][2], acc[nt][3]);
    }

    __syncthreads();
    float* red = (float*)sh;                // [32][64]
    #pragma unroll
    for (int j=0;j<8;j++) red[srow*64 + c8*8 + j] = ks[j];
    __syncthreads();
    if (tid < 64){
        float s = 0.f;
        #pragma unroll
        for (int r=0;r<32;r++) s += red[r*64 + tid];
        ksum[z*Mm + ntile*64 + tid] = s;
    }
}

// ---------------- single setup kernel: all weight f2h + bias pack + gmax reset --------
__global__ void setup_kernel(const float* __restrict__ wq, const float* __restrict__ wk,
                             const float* __restrict__ wv, const float* __restrict__ wo,
                             const float* __restrict__ w1, const float* __restrict__ w2,
                             const float* __restrict__ proj,
                             const float* __restrict__ bq, const float* __restrict__ bk,
                             const float* __restrict__ bv)
{
    const long long i = (long long)blockIdx.x*256 + threadIdx.x;
    const long long Q = Dd*Dd/4;
    const long long W = (long long)FFH*Dd/4;
    const long long P = Mm*DhD/4;
    const long long T0 = 4*Q, T1 = T0 + 2*W + P, T2 = T1 + 3*Dd;
    if (i < T0){
        const int seg = (int)(i/Q), off = (int)(i - seg*Q);
        const float* s = (seg==0)?wq:(seg==1)?wk:(seg==2)?wv:wo;
        __half* d = (seg<3) ? (g_wqkvh + (size_t)seg*Dd*Dd) : g_woh;
        float4 v = reinterpret_cast<const float4*>(s)[off];
        __half2* o = reinterpret_cast<__half2*>(d) + 2*off;
        o[0] = __floats2half2_rn(v.x, v.y);
        o[1] = __floats2half2_rn(v.z, v.w);
    } else if (i < T1){
        long long j = i - T0;
        const float* s; __half* d; int off;
        if (j < W)          { s = w1;   d = g_w1h;   off = (int)j; }
        else if (j < 2*W)   { s = w2;   d = g_w2h;   off = (int)(j - W); }
        else                { s = proj; d = g_projh; off = (int)(j - 2*W); }
        float4 v = reinterpret_cast<const float4*>(s)[off];
        __half2* o = reinterpret_cast<__half2*>(d) + 2*off;
        o[0] = __floats2half2_rn(v.x, v.y);
        o[1] = __floats2half2_rn(v.z, v.w);
    } else if (i < T2){
        const int j = (int)(i - T1);
        const int sel = j/Dd, c = j - sel*Dd;
        g_bqkv[j] = sel==0 ? bq[c] : (sel==1 ? bk[c] : bv[c]);
    } else if (i == T2){
        g_gmax_u = 0u;
    }
}
#define SETUP_N (4LL*(Dd*Dd/4) + 2LL*((long long)FFH*Dd/4) + Mm*DhD/4 + 3*Dd + 1)

// ---------------- LayerNorm (row=768), half output ----------------
__global__ void ln_kernel(const float* __restrict__ x, const float* __restrict__ g,
                          const float* __restrict__ b, __half* __restrict__ out)
{
    const int row = blockIdx.x;
    const float* xr = x + (long long)row*Dd;
    float v[3]; float s=0.f, ss=0.f;
    #pragma unroll
    for (int i=0;i<3;i++){ v[i]=xr[threadIdx.x + i*256]; s+=v[i]; ss+=v[i]*v[i]; }
    #pragma unroll
    for (int o=16;o;o>>=1){ s+=__shfl_xor_sync(0xffffffffu,s,o); ss+=__shfl_xor_sync(0xffffffffu,ss,o); }
    __shared__ float rs_[8], rss_[8];
    const int lane = threadIdx.x & 31, w = threadIdx.x >> 5;
    if (lane==0){ rs_[w]=s; rss_[w]=ss; }
    __syncthreads();
    s=0.f; ss=0.f;
    #pragma unroll
    for (int i=0;i<8;i++){ s+=rs_[i]; ss+=rss_[i]; }
    const float mu  = s*(1.0f/Dd);
    const float var = ss*(1.0f/Dd) - mu*mu;
    const float rstd = rsqrtf(var + LN_EPS);
    __half* outr = out + (long long)row*Dd;
    #pragma unroll
    for (int i=0;i<3;i++){
        int c = threadIdx.x + i*256;
        outr[c] = __float2half((v[i]-mu)*rstd*g[c] + b[c]);
    }
}

// ---------------- d_inv: half qp, fp32 ksum (warp per row) ----------------
__global__ void dinv_kernel(const __half* __restrict__ qp, float* __restrict__ dinv)
{
    const int lane = threadIdx.x & 31, w = threadIdx.x >> 5;
    const long long row = (long long)blockIdx.x*8 + w;
    const int bh = (int)(row >> 12);
    const __half2* p = reinterpret_cast<const __half2*>(qp + row*Mm);
    const float4* ks = reinterpret_cast<const float4*>(g_ksum + (long long)bh*Mm);
    float s = 0.f;
    #pragma unroll
    for (int h=0; h<2; ++h){
        const int li = lane + h*32;
        float2 a0 = __half22float2(p[2*li]), a1 = __half22float2(p[2*li+1]);
        float4 k4 = ks[li];
        s += a0.x*k4.x + a0.y*k4.y + a1.x*k4.z + a1.y*k4.w;
    }
    #pragma unroll
    for (int o=16;o;o>>=1) s += __shfl_xor_sync(0xffffffffu,s,o);
    if (lane==0) dinv[row] = 1.0f/s;
}

// ---------------- host ----------------
extern "C" void kernel_launch(void* const* d_in, const int* in_sizes, int n_in,
                              void* d_out, int out_size)
{
    const float* x    = (const float*)d_in[0];
    const float* proj = (const float*)d_in[1];
    const float* wq   = (const float*)d_in[2];
    const float* bq   = (const float*)d_in[3];
    const float* wk   = (const float*)d_in[4];
    const float* bk   = (const float*)d_in[5];
    const float* wv   = (const float*)d_in[6];
    const float* bv   = (const float*)d_in[7];
    const float* wo   = (const float*)d_in[8];
    const float* bo   = (const float*)d_in[9];
    const float* ln1g = (const float*)d_in[10];
    const float* ln1b = (const float*)d_in[11];
    const float* ln2g = (const float*)d_in[12];
    const float* ln2b = (const float*)d_in[13];
    const float* w1   = (const float*)d_in[14];
    const float* b1   = (const float*)d_in[15];
    const float* w2   = (const float*)d_in[16];
    const float* b2   = (const float*)d_in[17];
    float* out = (float*)d_out;

    void *p;
    __half *wqkvh, *h1h, *qkvh, *qkph, *midh, *ctxTh, *attn2h, *woh, *w1h, *w2h, *projh;
    float *ddiag, *rowf, *x2, *dinv, *ksum, *bqkv;
    cudaGetSymbolAddress(&p, g_wqkvh);  wqkvh  = (__half*)p;
    cudaGetSymbolAddress(&p, g_woh);    woh    = (__half*)p;
    cudaGetSymbolAddress(&p, g_w1h);    w1h    = (__half*)p;
    cudaGetSymbolAddress(&p, g_w2h);    w2h    = (__half*)p;
    cudaGetSymbolAddress(&p, g_projh);  projh  = (__half*)p;
    cudaGetSymbolAddress(&p, g_h1h);    h1h    = (__half*)p;
    cudaGetSymbolAddress(&p, g_qkvh);   qkvh   = (__half*)p;
    cudaGetSymbolAddress(&p, g_qkph);   qkph   = (__half*)p;
    cudaGetSymbolAddress(&p, g_midh);   midh   = (__half*)p;
    cudaGetSymbolAddress(&p, g_ctxTh);  ctxTh  = (__half*)p;
    cudaGetSymbolAddress(&p, g_attn2h); attn2h = (__half*)p;
    cudaGetSymbolAddress(&p, g_x2);     x2     = (float*)p;
    cudaGetSymbolAddress(&p, g_diag);   ddiag  = (float*)p;
    cudaGetSymbolAddress(&p, g_rowf);   rowf   = (float*)p;
    cudaGetSymbolAddress(&p, g_dinv);   dinv   = (float*)p;
    cudaGetSymbolAddress(&p, g_ksum);   ksum   = (float*)p;
    cudaGetSymbolAddress(&p, g_bqkv);   bqkv   = (float*)p;

    __half* qh = qkvh;
    __half* vh = qkvh + 2*(size_t)NHR*DhD;
    __half* qph = qkph;
    __half* kph = qkph + (size_t)NHR*Mm;

    cudaFuncSetAttribute(hgemm<128,128,EPI_QKV,true>,       cudaFuncAttributeMaxDynamicSharedMemorySize, SMEM_H128x128);
    cudaFuncSetAttribute(hgemm<64,256,EPI_FEAT,true>,       cudaFuncAttributeMaxDynamicSharedMemorySize, SMEM_H64x256);
    cudaFuncSetAttribute(hgemm<128,64,EPI_ATTN,true>,       cudaFuncAttributeMaxDynamicSharedMemorySize, SMEM_H128x64);
    cudaFuncSetAttribute(hgemm<128,128,EPI_BIAS_RES,false>, cudaFuncAttributeMaxDynamicSharedMemorySize, SMEM_H128x128);
    cudaFuncSetAttribute(hgemm<128,128,EPI_BIAS_GELU,true>, cudaFuncAttributeMaxDynamicSharedMemorySize, SMEM_H128x128);

    // setup: one launch (weights fp16, bias pack, gmax reset)
    setup_kernel<<<(int)((SETUP_N + 255)/256), 256>>>(wq,wk,wv,wo,w1,w2,proj,bq,bk,bv);
    ln_kernel<<<NROWS, 256>>>(x, ln1g, ln1b, h1h);

    // fused QKV (N=2304) + fused diag (q,k)
    hgemm<128,128,EPI_QKV,true><<<dim3(18,128,1),256,SMEM_H128x128>>>(
        h1h,Dd,0, wqkvh,Dd,0, qkvh,DhD,0, NROWS,3*Dd,Dd, bqkv,nullptr,nullptr,0.f);

    // q+k features in ONE launch (z=0: q, z=1: k); GEMM + rowmax + __expf
    hgemm<64,256,EPI_FEAT,true><<<dim3(1,NHR/64,2),256,SMEM_H64x256>>>(
        qh,DhD,(long long)NHR*DhD, projh,DhD,0, qkph,Mm,(long long)NHR*Mm,
        NHR,Mm,DhD, nullptr,rowf,ddiag,NORM_C);

    // ctx (tensor mma, TN, 4-way m split) + fused ksum
    ctx_mma<<<dim3(4,NBH), 256, SMEM_CTX>>>(kph, vh, rowf, ctxTh, ksum);

    // d_inv
    dinv_kernel<<<NHR/8, 256>>>(qph, dinv);

    // attn = d_inv * (qp @ ctx), fused transpose -> attn2h [b,s,D]
    hgemm<128,64,EPI_ATTN,true><<<dim3(1,Ss/128,NBH),128,SMEM_H128x64>>>(
        qph,Mm,(long long)Ss*Mm, ctxTh,Mm,(long long)DhD*Mm, attn2h,DhD,0,
        Ss,DhD,Mm, nullptr,nullptr,dinv,0.f);

    // x2 = x + attn @ wo^T + bo (fp32)
    hgemm<128,128,EPI_BIAS_RES,false><<<dim3(6,128,1),256,SMEM_H128x128>>>(
        attn2h,Dd,0, woh,Dd,0, x2,Dd,0, NROWS,Dd,Dd, bo,x,nullptr,0.f);

    // LN2 -> half
    ln_kernel<<<NROWS, 256>>>(x2, ln2g, ln2b, h1h);

    // mid = gelu(h1 @ w1^T + b1) -> half
    hgemm<128,128,EPI_BIAS_GELU,true><<<dim3(FFH/128,128,1),256,SMEM_H128x128>>>(
        h1h,Dd,0, w1h,Dd,0, midh,FFH,0, NROWS,FFH,Dd, b1,nullptr,nullptr,0.f);

    // out = x2 + mid @ w2^T + b2 (fp32)
    hgemm<128,128,EPI_BIAS_RES,false><<<dim3(6,128,1),256,SMEM_H128x128>>>(
        midh,FFH,0, w2h,FFH,0, out,Dd,0, NROWS,Dd,FFH, b2,x2,nullptr,0.f);
}

// round 13
// speedup vs baseline: 1.0113x; 1.0113x over previous
#include <cuda_runtime.h>
#include <cuda_fp16.h>
#include <math.h>
#include <stdint.h>

// ---------------- problem constants ----------------
#define Bb   4
#define Ss   4096
#define Dd   768
#define Hh   12
#define Mm   256
#define DhD  64
#define NROWS (Bb*Ss)        // 16384
#define NBH   (Bb*Hh)        // 48
#define NHR   (NBH*Ss)       // 196608
#define FFH   (4*Dd)         // 3072

#define NORM_C   0.35355339059327373f
#define RATIO_C  0.0625f
#define DIAG_C   0.0625f
#define EPS_K    1e-4f
#define LN_EPS   1e-5f

// ---------------- scratch (device globals; allocation-free) ----------------
__device__ __half g_wqkvh[3*Dd*Dd];
__device__ float  g_bqkv[3*Dd];
__device__ __half g_woh[Dd*Dd];
__device__ __half g_w1h[FFH*Dd];
__device__ __half g_w2h[Dd*FFH];
__device__ __half g_projh[Mm*DhD];
__device__ __half g_h1h[NROWS*Dd];
__device__ __half g_qkvh[3*(size_t)NHR*DhD];      // q,k,v in [sel][b,h,s,dh]
__device__ __half g_qkph[2*(size_t)NHR*Mm];       // [qp | kp(exp(dd-rowmax))]
__device__ __half g_midh[(size_t)NROWS*FFH];
__device__ __half g_ctxTh[NBH*DhD*Mm];            // [bh][dh][m]
__device__ __half g_attn2h[(size_t)NROWS*Dd];     // [b,s,D]
__device__ float  g_x2[NROWS*Dd];
__device__ float  g_diag[2*NHR];                  // [q rows | k rows]
__device__ float  g_rowf[NHR];                    // rowmax(dd_k) - diag_k
__device__ float  g_ksum[NBH*Mm];
__device__ float  g_dinv[NHR];
__device__ unsigned g_gmax_u;

// ---------------- epilogue modes ----------------
enum { EPI_BIAS_RES=1, EPI_BIAS_GELU=2, EPI_QKV=5, EPI_FEAT=6, EPI_ATTN=8 };

__device__ __forceinline__ void cpa16(uint32_t smem_dst, const void* gsrc){
    asm volatile("cp.async.cg.shared.global [%0], [%1], 16;" :: "r"(smem_dst), "l"(gsrc));
}
#define CP_COMMIT() asm volatile("cp.async.commit_group;" ::: "memory")
#define CP_WAIT0()  asm volatile("cp.async.wait_group 0;" ::: "memory")
#define CP_WAIT1()  asm volatile("cp.async.wait_group 1;" ::: "memory")

__device__ __forceinline__ uint32_t smem_u32(const void* p){
    uint32_t a;
    asm("{ .reg .u64 t; cvta.to.shared.u64 t, %1; cvt.u32.u64 %0, t; }" : "=r"(a) : "l"(p));
    return a;
}

__device__ __forceinline__ void mma_f16(float* d, const uint32_t* a, const uint32_t* b){
    asm volatile("mma.sync.aligned.m16n8k16.row.col.f32.f16.f16.f32 "
        "{%0,%1,%2,%3}, {%4,%5,%6,%7}, {%8,%9}, {%0,%1,%2,%3};"
        : "+f"(d[0]),"+f"(d[1]),"+f"(d[2]),"+f"(d[3])
        : "r"(a[0]),"r"(a[1]),"r"(a[2]),"r"(a[3]), "r"(b[0]),"r"(b[1]));
}
#define LDSM4(r0,r1,r2,r3,addr) \
    asm volatile("ldmatrix.sync.aligned.m8n8.x4.shared.b16 {%0,%1,%2,%3}, [%4];" \
        : "=r"(r0),"=r"(r1),"=r"(r2),"=r"(r3) : "r"(addr))
#define LDSM4T(r0,r1,r2,r3,addr) \
    asm volatile("ldmatrix.sync.aligned.m8n8.x4.trans.shared.b16 {%0,%1,%2,%3}, [%4];" \
        : "=r"(r0),"=r"(r1),"=r"(r2),"=r"(r3) : "r"(addr))

__device__ __forceinline__ float gmax_decode(unsigned u){
    return (u & 0x80000000u) ? __uint_as_float(u ^ 0x80000000u) : __uint_as_float(~u);
}

// ================= fp16 NT GEMM: mma.sync m16n8k16, BK=64, 2-stage cp.async ============
template<int BM,int BN,int EPI,bool OUTH>
__global__ void __launch_bounds__(32*(BM/64)*(BN/32), (BM==128 && BN==64) ? 3 : 2)
hgemm(const __half* __restrict__ A, int lda, long long strA,
      const __half* __restrict__ B, int ldb, long long strB,
      void* __restrict__ Cv, int ldc, long long strC,
      int M, int N, int K,
      const float* __restrict__ bias,
      const float* __restrict__ res,
      const float* __restrict__ rowscale,
      float alpha)
{
    constexpr int WY = BM/64, WX = BN/32, THREADS = 32*WY*WX;
    constexpr int LDKW = 36;                 // 32 data words (64 halfs) + 4 pad
    constexpr int AW = BM*LDKW;
    constexpr int SW = (BM+BN)*LDKW;
    constexpr int ALD = (BM*8)/THREADS;
    constexpr int BLD = (BN*8)/THREADS;

    extern __shared__ uint32_t sh[];
    const uint32_t smb = smem_u32(sh);

    const int z = blockIdx.z;
    A += (long long)z*strA;  B += (long long)z*strB;
    float*  Cf = (float*)Cv  + (long long)z*strC;
    __half* Ch = (__half*)Cv + (long long)z*strC;

    const int brow = blockIdx.y*BM;
    const int bcol = blockIdx.x*BN;
    const int tid  = threadIdx.x;
    const int wid  = tid >> 5;
    const int lane = tid & 31;
    const int wx   = wid % WX, wy = wid / WX;
    const int warp_m = wy*64, warp_n = wx*32;
    const int g = lane >> 2, t = lane & 3;

    const uint32_t aoff = (uint32_t)(((warp_m + (lane&15))*LDKW + (lane>>4)*4))*4u;
    const uint32_t boff = (uint32_t)((AW + (warp_n + (lane>>4)*8 + (lane&7))*LDKW + ((lane>>3)&1)*4))*4u;

    float acc[4][4][4];
    #pragma unroll
    for (int i=0;i<4;i++)
        #pragma unroll
        for (int j=0;j<4;j++)
            #pragma unroll
            for (int u=0;u<4;u++) acc[i][j][u]=0.f;

    const int nc = K >> 6;

    #define HISSUE(chunk) do{                                                  \
        const uint32_t bA_ = smb + (uint32_t)(((chunk)&1)*SW)*4u;              \
        const uint32_t bB_ = bA_ + (uint32_t)AW*4u;                            \
        const __half* Ap_ = A + (long long)brow*lda + (chunk)*64;              \
        const __half* Bp_ = B + (long long)bcol*ldb + (chunk)*64;              \
        _Pragma("unroll")                                                      \
        for (int l=0;l<ALD;l++){                                               \
            const int idx = tid + l*THREADS, r = idx>>3, c4 = idx&7;           \
            cpa16(bA_ + (uint32_t)(r*LDKW + c4*4)*4u,                          \
                  Ap_ + (long long)r*lda + c4*8);                              \
        }                                                                      \
        _Pragma("unroll")                                                      \
        for (int l=0;l<BLD;l++){                                               \
            const int idx = tid + l*THREADS, r = idx>>3, c4 = idx&7;           \
            cpa16(bB_ + (uint32_t)(r*LDKW + c4*4)*4u,                          \
                  Bp_ + (long long)r*ldb + c4*8);                              \
        }                                                                      \
    }while(0)

    HISSUE(0);
    CP_COMMIT();

    for (int i=0; i<nc; ++i){
        CP_WAIT0();
        __syncthreads();
        if (i+1 < nc){ HISSUE(i+1); CP_COMMIT(); }

        const uint32_t stg = smb + (uint32_t)((i&1)*SW)*4u;

        #pragma unroll
        for (int kk=0; kk<4; ++kk){
            uint32_t af[4][4], bf[4][2];
            #pragma unroll
            for (int mt=0; mt<4; ++mt)
                LDSM4(af[mt][0],af[mt][1],af[mt][2],af[mt][3],
                      stg + aoff + (uint32_t)((mt*16*LDKW + kk*8))*4u);
            LDSM4(bf[0][0],bf[0][1],bf[1][0],bf[1][1],
                  stg + boff + (uint32_t)(kk*8)*4u);
            LDSM4(bf[2][0],bf[2][1],bf[3][0],bf[3][1],
                  stg + boff + (uint32_t)((16*LDKW + kk*8))*4u);
            #pragma unroll
            for (int mt=0; mt<4; ++mt)
                #pragma unroll
                for (int nt=0; nt<4; ++nt)
                    mma_f16(acc[mt][nt], af[mt], bf[nt]);
        }
        __syncthreads();
    }
    #undef HISSUE

    // ================= epilogues =================
    if (EPI==EPI_FEAT){
        // z==0: q features (RATIO*(exp(dd-diag-rowmax)+eps));
        // z==1: k features (exp(dd-rowmax)), rowf = rowmax-diag, gmax atomic.
        // Staged smem store for coalesced output.
        constexpr int LDS_C = 264;             // 256 + 8 pad (halfs)
        float mxs[4][2];
        #pragma unroll
        for (int mt=0; mt<4; ++mt){
            float m0=-3.402823466e38f, m1=m0;
            #pragma unroll
            for (int nt=0; nt<4; ++nt){
                #pragma unroll
                for (int u=0;u<4;u++) acc[mt][nt][u]*=alpha;
                m0 = fmaxf(m0, fmaxf(acc[mt][nt][0], acc[mt][nt][1]));
                m1 = fmaxf(m1, fmaxf(acc[mt][nt][2], acc[mt][nt][3]));
            }
            m0 = fmaxf(m0, __shfl_xor_sync(0xffffffffu,m0,1));
            m0 = fmaxf(m0, __shfl_xor_sync(0xffffffffu,m0,2));
            m1 = fmaxf(m1, __shfl_xor_sync(0xffffffffu,m1,1));
            m1 = fmaxf(m1, __shfl_xor_sync(0xffffffffu,m1,2));
            mxs[mt][0]=m0; mxs[mt][1]=m1;
        }
        __syncthreads();
        float* red = (float*)sh;               // [64][8]
        if (t==0){
            #pragma unroll
            for (int mt=0; mt<4; ++mt){
                red[(mt*16+g)*8 + wid]   = mxs[mt][0];
                red[(mt*16+8+g)*8 + wid] = mxs[mt][1];
            }
        }
        __syncthreads();
        float dd0[4], dd1[4];
        #pragma unroll
        for (int mt=0; mt<4; ++mt){
            const int grow = brow + mt*16 + g;
            float mx0 = red[(mt*16+g)*8], mx1 = red[(mt*16+8+g)*8];
            #pragma unroll
            for (int w=1; w<8; ++w){
                mx0 = fmaxf(mx0, red[(mt*16+g)*8+w]);
                mx1 = fmaxf(mx1, red[(mt*16+8+g)*8+w]);
            }
            mxs[mt][0]=mx0; mxs[mt][1]=mx1;
            if (z==0){ dd0[mt] = rowscale[grow] + mx0; dd1[mt] = rowscale[grow+8] + mx1; }
            else     { dd0[mt] = mx0;                  dd1[mt] = mx1; }
            if (z==1 && wid==0 && t==0){
                float* rowf = const_cast<float*>(res);
                rowf[grow]   = mx0 - rowscale[(long long)NHR + grow];
                rowf[grow+8] = mx1 - rowscale[(long long)NHR + grow+8];
            }
        }
        if (z==1 && wid==0){
            float bm = fmaxf(fmaxf(mxs[0][0],mxs[0][1]), fmaxf(mxs[1][0],mxs[1][1]));
            bm = fmaxf(bm, fmaxf(fmaxf(mxs[2][0],mxs[2][1]), fmaxf(mxs[3][0],mxs[3][1])));
            #pragma unroll
            for (int o=16;o;o>>=1) bm = fmaxf(bm, __shfl_xor_sync(0xffffffffu,bm,o));
            if (lane==0){
                unsigned b = __float_as_uint(bm);
                unsigned u = (b & 0x80000000u) ? ~b : (b | 0x80000000u);
                atomicMax(&g_gmax_u, u);
            }
        }
        __syncthreads();                      // red reads done before tile overwrite
        __half* sm16 = (__half*)sh;           // [64][LDS_C]
        #pragma unroll
        for (int mt=0; mt<4; ++mt){
            #pragma unroll
            for (int nt=0; nt<4; ++nt){
                const int c0 = warp_n + nt*8 + 2*t;
                __half2 o0, o1;
                if (z==0){
                    o0 = __floats2half2_rn(RATIO_C*(__expf(acc[mt][nt][0]-dd0[mt])+EPS_K),
                                           RATIO_C*(__expf(acc[mt][nt][1]-dd0[mt])+EPS_K));
                    o1 = __floats2half2_rn(RATIO_C*(__expf(acc[mt][nt][2]-dd1[mt])+EPS_K),
                                           RATIO_C*(__expf(acc[mt][nt][3]-dd1[mt])+EPS_K));
                } else {
                    o0 = __floats2half2_rn(__expf(acc[mt][nt][0]-dd0[mt]), __expf(acc[mt][nt][1]-dd0[mt]));
                    o1 = __floats2half2_rn(__expf(acc[mt][nt][2]-dd1[mt]), __expf(acc[mt][nt][3]-dd1[mt]));
                }
                *reinterpret_cast<__half2*>(sm16 + (mt*16+g)*LDS_C + c0)   = o0;
                *reinterpret_cast<__half2*>(sm16 + (mt*16+8+g)*LDS_C + c0) = o1;
            }
        }
        __syncthreads();
        #pragma unroll
        for (int it=0; it<8; ++it){
            const int idx = tid + it*256;
            const int row = idx >> 5, cc = idx & 31;
            uint4 v4 = *reinterpret_cast<const uint4*>(sm16 + row*LDS_C + cc*8);
            *reinterpret_cast<uint4*>(Ch + (long long)(brow+row)*ldc + cc*8) = v4;
        }
        return;
    }

    float sq[4][2];
    if (EPI==EPI_QKV){
        #pragma unroll
        for (int mt=0; mt<4; ++mt){ sq[mt][0]=0.f; sq[mt][1]=0.f; }
    }
    __half* sm16q = (__half*)sh;               // QKV stage: [128][136]

    #pragma unroll
    for (int mt=0; mt<4; ++mt){
        const int r0 = brow + warp_m + mt*16 + g;
        const int r1 = r0 + 8;
        float rs0 = 1.f, rs1 = 1.f;
        if (EPI==EPI_ATTN){
            rs0 = rowscale[(long long)z*M + r0];
            rs1 = rowscale[(long long)z*M + r1];
        }
        #pragma unroll
        for (int nt=0; nt<4; ++nt){
            const int c0 = bcol + warp_n + nt*8 + 2*t;
            float v00 = acc[mt][nt][0], v01 = acc[mt][nt][1];
            float v10 = acc[mt][nt][2], v11 = acc[mt][nt][3];
            if (EPI==EPI_BIAS_RES || EPI==EPI_BIAS_GELU || EPI==EPI_QKV){
                const float b0 = bias[c0], b1 = bias[c0+1];
                v00 += b0; v01 += b1; v10 += b0; v11 += b1;
            }
            if (EPI==EPI_BIAS_RES){
                v00 += res[(long long)r0*ldc + c0];   v01 += res[(long long)r0*ldc + c0+1];
                v10 += res[(long long)r1*ldc + c0];   v11 += res[(long long)r1*ldc + c0+1];
            }
            if (EPI==EPI_BIAS_GELU){
                v00 = 0.5f*v00*(1.0f+erff(v00*0.70710678118654752f));
                v01 = 0.5f*v01*(1.0f+erff(v01*0.70710678118654752f));
                v10 = 0.5f*v10*(1.0f+erff(v10*0.70710678118654752f));
                v11 = 0.5f*v11*(1.0f+erff(v11*0.70710678118654752f));
            }
            if (EPI==EPI_ATTN){ v00*=rs0; v01*=rs0; v10*=rs1; v11*=rs1; }

            if (EPI==EPI_QKV){
                sq[mt][0] += v00*v00 + v01*v01;
                sq[mt][1] += v10*v10 + v11*v11;
                const int rl0 = warp_m + mt*16 + g;
                const int cl  = warp_n + nt*8 + 2*t;
                *reinterpret_cast<__half2*>(sm16q + rl0*136 + cl)     = __floats2half2_rn(v00,v01);
                *reinterpret_cast<__half2*>(sm16q + (rl0+8)*136 + cl) = __floats2half2_rn(v10,v11);
            } else if (EPI==EPI_ATTN){
                const int bb = z/Hh, hh = z - (z/Hh)*Hh;
                __half* base = (__half*)Cv;
                const long long o0 = ((long long)(bb*Ss + r0))*Dd + hh*64 + c0;
                const long long o1 = ((long long)(bb*Ss + r1))*Dd + hh*64 + c0;
                *reinterpret_cast<__half2*>(base + o0) = __floats2half2_rn(v00,v01);
                *reinterpret_cast<__half2*>(base + o1) = __floats2half2_rn(v10,v11);
            } else if (OUTH){
                *reinterpret_cast<__half2*>(Ch + (long long)r0*ldc + c0) = __floats2half2_rn(v00,v01);
                *reinterpret_cast<__half2*>(Ch + (long long)r1*ldc + c0) = __floats2half2_rn(v10,v11);
            } else {
                float2 o0; o0.x=v00; o0.y=v01;
                float2 o1; o1.x=v10; o1.y=v11;
                *reinterpret_cast<float2*>(Cf + (long long)r0*ldc + c0) = o0;
                *reinterpret_cast<float2*>(Cf + (long long)r1*ldc + c0) = o1;
            }
        }
    }

    // QKV: diag reduce + coalesced copy-out of the staged tile (2 heads x 128 rows)
    if (EPI==EPI_QKV){
        const int sel_t = bcol/Dd;
        const int cc0   = bcol - sel_t*Dd;
        float* red = (float*)(sh + 8704);      // after 128*68-word tile
        #pragma unroll
        for (int mt=0; mt<4; ++mt){
            #pragma unroll
            for (int j=0;j<2;j++){
                float v = sq[mt][j];
                v += __shfl_xor_sync(0xffffffffu, v, 1);
                v += __shfl_xor_sync(0xffffffffu, v, 2);
                if (t==0) red[(warp_m + mt*16 + j*8 + g)*4 + wx] = v;
            }
        }
        __syncthreads();
        if (sel_t < 2){
            const int row  = tid >> 1;
            const int head = tid & 1;
            const float ssum = red[row*4 + 2*head] + red[row*4 + 2*head + 1];
            const int gr = brow + row;
            const int b_ = gr>>12, s_ = gr&4095;
            const int h_ = (cc0>>6) + head;
            g_diag[(size_t)sel_t*NHR + (((long long)(b_*Hh+h_))<<12) + s_] = DIAG_C*ssum;
        }
        const int b_ = brow>>12, s0 = brow&4095;
        __half* base = (__half*)Cv + (size_t)sel_t*NHR*DhD;
        #pragma unroll
        for (int it=0; it<8; ++it){
            const int idx = tid + it*256;          // 0..2047
            const int head = idx >> 10;
            const int rem = idx & 1023;
            const int row = rem >> 3, ch = rem & 7;
            uint4 v4 = *reinterpret_cast<const uint4*>(sm16q + row*136 + head*64 + ch*8);
            const int h_ = (cc0>>6) + head;
            *reinterpret_cast<uint4*>(base + ((((long long)(b_*Hh+h_))<<12) + s0 + row)*DhD + ch*8) = v4;
        }
    }
}

#define SMEM_H128x128 (2*(128+128)*36*4)   // 73728
#define SMEM_H64x256  (2*(64+256)*36*4)    // 92160
#define SMEM_H128x64  (2*(128+64)*36*4)    // 55296

// ================ ctx TN mma kernel, 4-way m split (BK=32, 3-stage) ====================
#define CTX_LDV 36
#define CTX_LDP 36
#define CTX_VW  (32*CTX_LDV)
#define CTX_PW  (32*CTX_LDP)
#define SMEM_CTX (3*(CTX_VW+CTX_PW)*4)     // 27648

__global__ void __launch_bounds__(256, 2)
ctx_mma(const __half* __restrict__ kpe, const __half* __restrict__ vh,
        const float* __restrict__ rowf,
        __half* __restrict__ ctxT, float* __restrict__ ksum)
{
    extern __shared__ uint32_t sh[];
    const uint32_t smb = smem_u32(sh);
    const uint32_t pbase = smb + (uint32_t)(3*CTX_VW)*4u;

    const int z = blockIdx.y;
    const int ntile = blockIdx.x;               // 0..3, 64 m-cols each
    const int tid = threadIdx.x, wid = tid>>5, lane = tid&31;
    const int warp_m = (wid & 3)*16;            // dh tile
    const int warp_n = (wid >> 2)*32;           // m tile
    const int g = lane>>2, t = lane&3;
    const int quad = lane>>3, r8 = lane&7;

    const __half* kpb = kpe + (long long)z*Ss*Mm + ntile*64;
    const __half* vhb = vh  + (long long)z*Ss*DhD;
    const float*  rfb = rowf + (long long)z*Ss;

    const float gmax = gmax_decode(g_gmax_u);
    const float epsr = RATIO_C*EPS_K;

    const uint32_t a_off0 = (uint32_t)((r8 + ((quad>>1)&1)*8)*CTX_LDV + (warp_m + (quad&1)*8)/2);
    const uint32_t b_off0 = (uint32_t)((r8 + (quad&1)*8)*CTX_LDP + (warp_n + (quad>>1)*8)/2);

    const int srow = tid >> 3;     // 0..31
    const int c8   = tid & 7;      // 8-half group

    float acc[4][4];
    #pragma unroll
    for (int j=0;j<4;j++)
        #pragma unroll
        for (int u=0;u<4;u++) acc[j][u]=0.f;
    float ks[8];
    #pragma unroll
    for (int j=0;j<8;j++) ks[j]=0.f;

    #define VISSUE(c) do{ \
        const uint32_t bV = smb + (uint32_t)(((c)%3)*CTX_VW)*4u; \
        cpa16(bV + (uint32_t)(srow*CTX_LDV + c8*4)*4u, \
              vhb + (long long)((c)*32 + srow)*DhD + c8*8); \
    }while(0)

    uint4 cur; float curf;
    cur  = *reinterpret_cast<const uint4*>(kpb + (long long)srow*Mm + c8*8);
    curf = rfb[srow];
    VISSUE(0); CP_COMMIT();
    VISSUE(1); CP_COMMIT();

    for (int i=0; i<Ss/32; ++i){
        {
            const float As = RATIO_C*__expf(curf - gmax);
            uint32_t rw[4] = {cur.x,cur.y,cur.z,cur.w};
            uint32_t ow[4];
            #pragma unroll
            for (int j=0;j<4;j++){
                float2 f = __half22float2(*reinterpret_cast<__half2*>(&rw[j]));
                f.x = fmaf(f.x, As, epsr);
                f.y = fmaf(f.y, As, epsr);
                __half2 h = __floats2half2_rn(f.x, f.y);
                float2 fr = __half22float2(h);
                ks[2*j]   += fr.x;
                ks[2*j+1] += fr.y;
                ow[j] = *reinterpret_cast<uint32_t*>(&h);
            }
            const uint32_t bP = pbase + (uint32_t)((i%3)*CTX_PW)*4u
                              + (uint32_t)(srow*CTX_LDP + c8*4)*4u;
            uint4 s0 = {ow[0],ow[1],ow[2],ow[3]};
            *reinterpret_cast<uint4*>((char*)sh + (bP - smb)) = s0;
        }
        CP_WAIT1();
        __syncthreads();
        if (i+2 < Ss/32) VISSUE(i+2);
        CP_COMMIT();
        if (i+1 < Ss/32){
            cur  = *reinterpret_cast<const uint4*>(kpb + (long long)((i+1)*32 + srow)*Mm + c8*8);
            curf = rfb[(i+1)*32 + srow];
        }

        const uint32_t vstg = smb + (uint32_t)((i%3)*CTX_VW)*4u;
        const uint32_t pstg = pbase + (uint32_t)((i%3)*CTX_PW)*4u;

        #pragma unroll
        for (int kk=0; kk<2; ++kk){
            uint32_t af[4], bf[4][2];
            LDSM4T(af[0],af[1],af[2],af[3],
                   vstg + (a_off0 + (uint32_t)(kk*16*CTX_LDV))*4u);
            #pragma unroll
            for (int pp2=0; pp2<2; ++pp2)
                LDSM4T(bf[2*pp2][0],bf[2*pp2][1],bf[2*pp2+1][0],bf[2*pp2+1][1],
                       pstg + (b_off0 + (uint32_t)(kk*16*CTX_LDP + pp2*8))*4u);
            #pragma unroll
            for (int nt=0; nt<4; ++nt)
                mma_f16(acc[nt], af, bf[nt]);
        }
    }
    #undef VISSUE

    const int dh0 = warp_m + g;
    const int dh1 = dh0 + 8;
    #pragma unroll
    for (int nt=0; nt<4; ++nt){
        const int col = ntile*64 + warp_n + nt*8 + 2*t;
        *reinterpret_cast<__half2*>(ctxT + (long long)z*DhD*Mm + (long long)dh0*Mm + col)
            = __floats2half2_rn(acc[nt][0], acc[nt][1]);
        *reinterpret_cast<__half2*>(ctxT + (long long)z*DhD*Mm + (long long)dh1*Mm + col)
            = __floats2half2_rn(acc[nt][2], acc[nt][3]);
    }

    __syncthreads();
    float* red = (float*)sh;                // [32][64]
    #pragma unroll
    for (int j=0;j<8;j++) red[srow*64 + c8*8 + j] = ks[j];
    __syncthreads();
    if (tid < 64){
        float s = 0.f;
        #pragma unroll
        for (int r=0;r<32;r++) s += red[r*64 + tid];
        ksum[z*Mm + ntile*64 + tid] = s;
    }
}

// ---------------- single setup kernel: all weight f2h + bias pack + gmax reset --------
__global__ void setup_kernel(const float* __restrict__ wq, const float* __restrict__ wk,
                             const float* __restrict__ wv, const float* __restrict__ wo,
                             const float* __restrict__ w1, const float* __restrict__ w2,
                             const float* __restrict__ proj,
                             const float* __restrict__ bq, const float* __restrict__ bk,
                             const float* __restrict__ bv)
{
    const long long i = (long long)blockIdx.x*256 + threadIdx.x;
    const long long Q = Dd*Dd/4;
    const long long W = (long long)FFH*Dd/4;
    const long long P = Mm*DhD/4;
    const long long T0 = 4*Q, T1 = T0 + 2*W + P, T2 = T1 + 3*Dd;
    if (i < T0){
        const int seg = (int)(i/Q), off = (int)(i - seg*Q);
        const float* s = (seg==0)?wq:(seg==1)?wk:(seg==2)?wv:wo;
        __half* d = (seg<3) ? (g_wqkvh + (size_t)seg*Dd*Dd) : g_woh;
        float4 v = reinterpret_cast<const float4*>(s)[off];
        __half2* o = reinterpret_cast<__half2*>(d) + 2*off;
        o[0] = __floats2half2_rn(v.x, v.y);
        o[1] = __floats2half2_rn(v.z, v.w);
    } else if (i < T1){
        long long j = i - T0;
        const float* s; __half* d; int off;
        if (j < W)          { s = w1;   d = g_w1h;   off = (int)j; }
        else if (j < 2*W)   { s = w2;   d = g_w2h;   off = (int)(j - W); }
        else                { s = proj; d = g_projh; off = (int)(j - 2*W); }
        float4 v = reinterpret_cast<const float4*>(s)[off];
        __half2* o = reinterpret_cast<__half2*>(d) + 2*off;
        o[0] = __floats2half2_rn(v.x, v.y);
        o[1] = __floats2half2_rn(v.z, v.w);
    } else if (i < T2){
        const int j = (int)(i - T1);
        const int sel = j/Dd, c = j - sel*Dd;
        g_bqkv[j] = sel==0 ? bq[c] : (sel==1 ? bk[c] : bv[c]);
    } else if (i == T2){
        g_gmax_u = 0u;
    }
}
#define SETUP_N (4LL*(Dd*Dd/4) + 2LL*((long long)FFH*Dd/4) + Mm*DhD/4 + 3*Dd + 1)

// ---------------- LayerNorm (row=768), half output ----------------
__global__ void ln_kernel(const float* __restrict__ x, const float* __restrict__ g,
                          const float* __restrict__ b, __half* __restrict__ out)
{
    const int row = blockIdx.x;
    const float* xr = x + (long long)row*Dd;
    float v[3]; float s=0.f, ss=0.f;
    #pragma unroll
    for (int i=0;i<3;i++){ v[i]=xr[threadIdx.x + i*256]; s+=v[i]; ss+=v[i]*v[i]; }
    #pragma unroll
    for (int o=16;o;o>>=1){ s+=__shfl_xor_sync(0xffffffffu,s,o); ss+=__shfl_xor_sync(0xffffffffu,ss,o); }
    __shared__ float rs_[8], rss_[8];
    const int lane = threadIdx.x & 31, w = threadIdx.x >> 5;
    if (lane==0){ rs_[w]=s; rss_[w]=ss; }
    __syncthreads();
    s=0.f; ss=0.f;
    #pragma unroll
    for (int i=0;i<8;i++){ s+=rs_[i]; ss+=rss_[i]; }
    const float mu  = s*(1.0f/Dd);
    const float var = ss*(1.0f/Dd) - mu*mu;
    const float rstd = rsqrtf(var + LN_EPS);
    __half* outr = out + (long long)row*Dd;
    #pragma unroll
    for (int i=0;i<3;i++){
        int c = threadIdx.x + i*256;
        outr[c] = __float2half((v[i]-mu)*rstd*g[c] + b[c]);
    }
}

// ---------------- d_inv: half qp, fp32 ksum (warp per row) ----------------
__global__ void dinv_kernel(const __half* __restrict__ qp, float* __restrict__ dinv)
{
    const int lane = threadIdx.x & 31, w = threadIdx.x >> 5;
    const long long row = (long long)blockIdx.x*8 + w;
    const int bh = (int)(row >> 12);
    const __half2* p = reinterpret_cast<const __half2*>(qp + row*Mm);
    const float4* ks = reinterpret_cast<const float4*>(g_ksum + (long long)bh*Mm);
    float s = 0.f;
    #pragma unroll
    for (int h=0; h<2; ++h){
        const int li = lane + h*32;
        float2 a0 = __half22float2(p[2*li]), a1 = __half22float2(p[2*li+1]);
        float4 k4 = ks[li];
        s += a0.x*k4.x + a0.y*k4.y + a1.x*k4.z + a1.y*k4.w;
    }
    #pragma unroll
    for (int o=16;o;o>>=1) s += __shfl_xor_sync(0xffffffffu,s,o);
    if (lane==0) dinv[row] = 1.0f/s;
}

// ---------------- host ----------------
extern "C" void kernel_launch(void* const* d_in, const int* in_sizes, int n_in,
                              void* d_out, int out_size)
{
    const float* x    = (const float*)d_in[0];
    const float* proj = (const float*)d_in[1];
    const float* wq   = (const float*)d_in[2];
    const float* bq   = (const float*)d_in[3];
    const float* wk   = (const float*)d_in[4];
    const float* bk   = (const float*)d_in[5];
    const float* wv   = (const float*)d_in[6];
    const float* bv   = (const float*)d_in[7];
    const float* wo   = (const float*)d_in[8];
    const float* bo   = (const float*)d_in[9];
    const float* ln1g = (const float*)d_in[10];
    const float* ln1b = (const float*)d_in[11];
    const float* ln2g = (const float*)d_in[12];
    const float* ln2b = (const float*)d_in[13];
    const float* w1   = (const float*)d_in[14];
    const float* b1   = (const float*)d_in[15];
    const float* w2   = (const float*)d_in[16];
    const float* b2   = (const float*)d_in[17];
    float* out = (float*)d_out;

    void *p;
    __half *wqkvh, *h1h, *qkvh, *qkph, *midh, *ctxTh, *attn2h, *woh, *w1h, *w2h, *projh;
    float *ddiag, *rowf, *x2, *dinv, *ksum, *bqkv;
    cudaGetSymbolAddress(&p, g_wqkvh);  wqkvh  = (__half*)p;
    cudaGetSymbolAddress(&p, g_woh);    woh    = (__half*)p;
    cudaGetSymbolAddress(&p, g_w1h);    w1h    = (__half*)p;
    cudaGetSymbolAddress(&p, g_w2h);    w2h    = (__half*)p;
    cudaGetSymbolAddress(&p, g_projh);  projh  = (__half*)p;
    cudaGetSymbolAddress(&p, g_h1h);    h1h    = (__half*)p;
    cudaGetSymbolAddress(&p, g_qkvh);   qkvh   = (__half*)p;
    cudaGetSymbolAddress(&p, g_qkph);   qkph   = (__half*)p;
    cudaGetSymbolAddress(&p, g_midh);   midh   = (__half*)p;
    cudaGetSymbolAddress(&p, g_ctxTh);  ctxTh  = (__half*)p;
    cudaGetSymbolAddress(&p, g_attn2h); attn2h = (__half*)p;
    cudaGetSymbolAddress(&p, g_x2);     x2     = (float*)p;
    cudaGetSymbolAddress(&p, g_diag);   ddiag  = (float*)p;
    cudaGetSymbolAddress(&p, g_rowf);   rowf   = (float*)p;
    cudaGetSymbolAddress(&p, g_dinv);   dinv   = (float*)p;
    cudaGetSymbolAddress(&p, g_ksum);   ksum   = (float*)p;
    cudaGetSymbolAddress(&p, g_bqkv);   bqkv   = (float*)p;

    __half* qh = qkvh;
    __half* vh = qkvh + 2*(size_t)NHR*DhD;
    __half* qph = qkph;
    __half* kph = qkph + (size_t)NHR*Mm;

    cudaFuncSetAttribute(hgemm<128,128,EPI_QKV,true>,       cudaFuncAttributeMaxDynamicSharedMemorySize, SMEM_H128x128);
    cudaFuncSetAttribute(hgemm<64,256,EPI_FEAT,true>,       cudaFuncAttributeMaxDynamicSharedMemorySize, SMEM_H64x256);
    cudaFuncSetAttribute(hgemm<128,64,EPI_ATTN,true>,       cudaFuncAttributeMaxDynamicSharedMemorySize, SMEM_H128x64);
    cudaFuncSetAttribute(hgemm<128,128,EPI_BIAS_RES,false>, cudaFuncAttributeMaxDynamicSharedMemorySize, SMEM_H128x128);
    cudaFuncSetAttribute(hgemm<128,128,EPI_BIAS_GELU,true>, cudaFuncAttributeMaxDynamicSharedMemorySize, SMEM_H128x128);

    // setup: one launch (weights fp16, bias pack, gmax reset)
    setup_kernel<<<(int)((SETUP_N + 255)/256), 256>>>(wq,wk,wv,wo,w1,w2,proj,bq,bk,bv);
    ln_kernel<<<NROWS, 256>>>(x, ln1g, ln1b, h1h);

    // fused QKV (N=2304) + fused diag (q,k), staged coalesced stores
    hgemm<128,128,EPI_QKV,true><<<dim3(18,128,1),256,SMEM_H128x128>>>(
        h1h,Dd,0, wqkvh,Dd,0, qkvh,DhD,0, NROWS,3*Dd,Dd, bqkv,nullptr,nullptr,0.f);

    // q+k features in ONE launch (z=0: q, z=1: k); GEMM + rowmax + __expf, staged stores
    hgemm<64,256,EPI_FEAT,true><<<dim3(1,NHR/64,2),256,SMEM_H64x256>>>(
        qh,DhD,(long long)NHR*DhD, projh,DhD,0, qkph,Mm,(long long)NHR*Mm,
        NHR,Mm,DhD, nullptr,rowf,ddiag,NORM_C);

    // ctx (tensor mma, TN, 4-way m split) + fused ksum
    ctx_mma<<<dim3(4,NBH), 256, SMEM_CTX>>>(kph, vh, rowf, ctxTh, ksum);

    // d_inv
    dinv_kernel<<<NHR/8, 256>>>(qph, dinv);

    // attn = d_inv * (qp @ ctx), fused transpose -> attn2h [b,s,D]
    hgemm<128,64,EPI_ATTN,true><<<dim3(1,Ss/128,NBH),128,SMEM_H128x64>>>(
        qph,Mm,(long long)Ss*Mm, ctxTh,Mm,(long long)DhD*Mm, attn2h,DhD,0,
        Ss,DhD,Mm, nullptr,nullptr,dinv,0.f);

    // x2 = x + attn @ wo^T + bo (fp32)
    hgemm<128,128,EPI_BIAS_RES,false><<<dim3(6,128,1),256,SMEM_H128x128>>>(
        attn2h,Dd,0, woh,Dd,0, x2,Dd,0, NROWS,Dd,Dd, bo,x,nullptr,0.f);

    // LN2 -> half
    ln_kernel<<<NROWS, 256>>>(x2, ln2g, ln2b, h1h);

    // mid = gelu(h1 @ w1^T + b1) -> half
    hgemm<128,128,EPI_BIAS_GELU,true><<<dim3(FFH/128,128,1),256,SMEM_H128x128>>>(
        h1h,Dd,0, w1h,Dd,0, midh,FFH,0, NROWS,FFH,Dd, b1,nullptr,nullptr,0.f);

    // out = x2 + mid @ w2^T + b2 (fp32)
    hgemm<128,128,EPI_BIAS_RES,false><<<dim3(6,128,1),256,SMEM_H128x128>>>(
        midh,FFH,0, w2h,FFH,0, out,Dd,0, NROWS,Dd,FFH, b2,x2,nullptr,0.f);
}

// round 14
// speedup vs baseline: 1.0144x; 1.0031x over previous
#include <cuda_runtime.h>
#include <cuda_fp16.h>
#include <math.h>
#include <stdint.h>

// ---------------- problem constants ----------------
#define Bb   4
#define Ss   4096
#define Dd   768
#define Hh   12
#define Mm   256
#define DhD  64
#define NROWS (Bb*Ss)        // 16384
#define NBH   (Bb*Hh)        // 48
#define NHR   (NBH*Ss)       // 196608
#define FFH   (4*Dd)         // 3072

#define NORM_C   0.35355339059327373f
#define RATIO_C  0.0625f
#define DIAG_C   0.0625f
#define EPS_K    1e-4f
#define EPSR_C   (RATIO_C*EPS_K)
#define LN_EPS   1e-5f

// ---------------- scratch (device globals; allocation-free) ----------------
__device__ __half g_wqkvh[3*Dd*Dd];
__device__ float  g_bqkv[3*Dd];
__device__ __half g_woh[Dd*Dd];
__device__ __half g_w1h[FFH*Dd];
__device__ __half g_w2h[Dd*FFH];
__device__ __half g_projh[Mm*DhD];               // pre-scaled by NORM_C
__device__ __half g_h1h[NROWS*Dd];
__device__ __half g_qkvh[3*(size_t)NHR*DhD];      // q,k,v in [sel][b,h,s,dh]
__device__ __half g_qkph[2*(size_t)NHR*Mm];       // [qp | kp(exp(dd-rowmax))]
__device__ __half g_midh[(size_t)NROWS*FFH];
__device__ __half g_ctxTh[NBH*DhD*Mm];            // [bh][dh][m]
__device__ __half g_attn2h[(size_t)NROWS*Dd];     // [b,s,D]
__device__ float  g_x2[NROWS*Dd];
__device__ float  g_diag[2*NHR];                  // [q rows | k rows]
__device__ float  g_rowf[NHR];                    // rowmax(dd_k) - diag_k
__device__ float  g_ksum[NBH*Mm];
__device__ float  g_dinv[NHR];
__device__ unsigned g_gmax_u;

// ---------------- epilogue modes ----------------
enum { EPI_BIAS_RES=1, EPI_BIAS_GELU=2, EPI_QKV=5, EPI_FEAT=6, EPI_ATTN=8 };

__device__ __forceinline__ void cpa16(uint32_t smem_dst, const void* gsrc){
    asm volatile("cp.async.cg.shared.global [%0], [%1], 16;" :: "r"(smem_dst), "l"(gsrc));
}
#define CP_COMMIT() asm volatile("cp.async.commit_group;" ::: "memory")
#define CP_WAIT0()  asm volatile("cp.async.wait_group 0;" ::: "memory")
#define CP_WAIT1()  asm volatile("cp.async.wait_group 1;" ::: "memory")

__device__ __forceinline__ uint32_t smem_u32(const void* p){
    uint32_t a;
    asm("{ .reg .u64 t; cvta.to.shared.u64 t, %1; cvt.u32.u64 %0, t; }" : "=r"(a) : "l"(p));
    return a;
}

__device__ __forceinline__ void mma_f16(float* d, const uint32_t* a, const uint32_t* b){
    asm volatile("mma.sync.aligned.m16n8k16.row.col.f32.f16.f16.f32 "
        "{%0,%1,%2,%3}, {%4,%5,%6,%7}, {%8,%9}, {%0,%1,%2,%3};"
        : "+f"(d[0]),"+f"(d[1]),"+f"(d[2]),"+f"(d[3])
        : "r"(a[0]),"r"(a[1]),"r"(a[2]),"r"(a[3]), "r"(b[0]),"r"(b[1]));
}
#define LDSM4(r0,r1,r2,r3,addr) \
    asm volatile("ldmatrix.sync.aligned.m8n8.x4.shared.b16 {%0,%1,%2,%3}, [%4];" \
        : "=r"(r0),"=r"(r1),"=r"(r2),"=r"(r3) : "r"(addr))
#define LDSM4T(r0,r1,r2,r3,addr) \
    asm volatile("ldmatrix.sync.aligned.m8n8.x4.trans.shared.b16 {%0,%1,%2,%3}, [%4];" \
        : "=r"(r0),"=r"(r1),"=r"(r2),"=r"(r3) : "r"(addr))

__device__ __forceinline__ float gmax_decode(unsigned u){
    return (u & 0x80000000u) ? __uint_as_float(u ^ 0x80000000u) : __uint_as_float(~u);
}

// ================= fp16 NT GEMM: mma.sync m16n8k16, BK=64, 2-stage cp.async ============
template<int BM,int BN,int EPI,bool OUTH>
__global__ void __launch_bounds__(32*(BM/64)*(BN/32), (BM==128 && BN==64) ? 3 : 2)
hgemm(const __half* __restrict__ A, int lda, long long strA,
      const __half* __restrict__ B, int ldb, long long strB,
      void* __restrict__ Cv, int ldc, long long strC,
      int M, int N, int K,
      const float* __restrict__ bias,
      const float* __restrict__ res,
      const float* __restrict__ rowscale,
      float alpha)
{
    constexpr int WY = BM/64, WX = BN/32, THREADS = 32*WY*WX;
    constexpr int LDKW = 36;                 // 32 data words (64 halfs) + 4 pad
    constexpr int AW = BM*LDKW;
    constexpr int SW = (BM+BN)*LDKW;
    constexpr int ALD = (BM*8)/THREADS;
    constexpr int BLD = (BN*8)/THREADS;

    extern __shared__ uint32_t sh[];
    const uint32_t smb = smem_u32(sh);

    const int z = blockIdx.z;
    A += (long long)z*strA;  B += (long long)z*strB;
    float*  Cf = (float*)Cv  + (long long)z*strC;
    __half* Ch = (__half*)Cv + (long long)z*strC;

    const int brow = blockIdx.y*BM;
    const int bcol = blockIdx.x*BN;
    const int tid  = threadIdx.x;
    const int wid  = tid >> 5;
    const int lane = tid & 31;
    const int wx   = wid % WX, wy = wid / WX;
    const int warp_m = wy*64, warp_n = wx*32;
    const int g = lane >> 2, t = lane & 3;

    const uint32_t aoff = (uint32_t)(((warp_m + (lane&15))*LDKW + (lane>>4)*4))*4u;
    const uint32_t boff = (uint32_t)((AW + (warp_n + (lane>>4)*8 + (lane&7))*LDKW + ((lane>>3)&1)*4))*4u;

    float acc[4][4][4];
    #pragma unroll
    for (int i=0;i<4;i++)
        #pragma unroll
        for (int j=0;j<4;j++)
            #pragma unroll
            for (int u=0;u<4;u++) acc[i][j][u]=0.f;

    const int nc = K >> 6;

    #define HISSUE(chunk) do{                                                  \
        const uint32_t bA_ = smb + (uint32_t)(((chunk)&1)*SW)*4u;              \
        const uint32_t bB_ = bA_ + (uint32_t)AW*4u;                            \
        const __half* Ap_ = A + (long long)brow*lda + (chunk)*64;              \
        const __half* Bp_ = B + (long long)bcol*ldb + (chunk)*64;              \
        _Pragma("unroll")                                                      \
        for (int l=0;l<ALD;l++){                                               \
            const int idx = tid + l*THREADS, r = idx>>3, c4 = idx&7;           \
            cpa16(bA_ + (uint32_t)(r*LDKW + c4*4)*4u,                          \
                  Ap_ + (long long)r*lda + c4*8);                              \
        }                                                                      \
        _Pragma("unroll")                                                      \
        for (int l=0;l<BLD;l++){                                               \
            const int idx = tid + l*THREADS, r = idx>>3, c4 = idx&7;           \
            cpa16(bB_ + (uint32_t)(r*LDKW + c4*4)*4u,                          \
                  Bp_ + (long long)r*ldb + c4*8);                              \
        }                                                                      \
    }while(0)

    HISSUE(0);
    CP_COMMIT();

    for (int i=0; i<nc; ++i){
        // issue next chunk BEFORE waiting on current (stage safe: end-of-iter sync)
        if (i+1 < nc){ HISSUE(i+1); CP_COMMIT(); CP_WAIT1(); }
        else         { CP_WAIT0(); }
        __syncthreads();

        const uint32_t stg = smb + (uint32_t)((i&1)*SW)*4u;

        #pragma unroll
        for (int kk=0; kk<4; ++kk){
            uint32_t af[4][4], bf[4][2];
            #pragma unroll
            for (int mt=0; mt<4; ++mt)
                LDSM4(af[mt][0],af[mt][1],af[mt][2],af[mt][3],
                      stg + aoff + (uint32_t)((mt*16*LDKW + kk*8))*4u);
            LDSM4(bf[0][0],bf[0][1],bf[1][0],bf[1][1],
                  stg + boff + (uint32_t)(kk*8)*4u);
            LDSM4(bf[2][0],bf[2][1],bf[3][0],bf[3][1],
                  stg + boff + (uint32_t)((16*LDKW + kk*8))*4u);
            #pragma unroll
            for (int mt=0; mt<4; ++mt)
                #pragma unroll
                for (int nt=0; nt<4; ++nt)
                    mma_f16(acc[mt][nt], af[mt], bf[nt]);
        }
        __syncthreads();
    }
    #undef HISSUE

    // ================= epilogues =================
    if (EPI==EPI_FEAT){
        // proj pre-scaled by NORM_C: acc already = dd.
        // z==0: q features fma(exp(dd-diag-rowmax), RATIO, RATIO*eps);
        // z==1: k features exp(dd-rowmax), rowf = rowmax-diag, gmax atomic.
        constexpr int LDS_C = 264;             // 256 + 8 pad (halfs)
        float mxs[4][2];
        #pragma unroll
        for (int mt=0; mt<4; ++mt){
            float m0=-3.402823466e38f, m1=m0;
            #pragma unroll
            for (int nt=0; nt<4; ++nt){
                m0 = fmaxf(m0, fmaxf(acc[mt][nt][0], acc[mt][nt][1]));
                m1 = fmaxf(m1, fmaxf(acc[mt][nt][2], acc[mt][nt][3]));
            }
            m0 = fmaxf(m0, __shfl_xor_sync(0xffffffffu,m0,1));
            m0 = fmaxf(m0, __shfl_xor_sync(0xffffffffu,m0,2));
            m1 = fmaxf(m1, __shfl_xor_sync(0xffffffffu,m1,1));
            m1 = fmaxf(m1, __shfl_xor_sync(0xffffffffu,m1,2));
            mxs[mt][0]=m0; mxs[mt][1]=m1;
        }
        __syncthreads();
        float* red = (float*)sh;               // [64][8]
        if (t==0){
            #pragma unroll
            for (int mt=0; mt<4; ++mt){
                red[(mt*16+g)*8 + wid]   = mxs[mt][0];
                red[(mt*16+8+g)*8 + wid] = mxs[mt][1];
            }
        }
        __syncthreads();
        float dd0[4], dd1[4];
        #pragma unroll
        for (int mt=0; mt<4; ++mt){
            const int grow = brow + mt*16 + g;
            float mx0 = red[(mt*16+g)*8], mx1 = red[(mt*16+8+g)*8];
            #pragma unroll
            for (int w=1; w<8; ++w){
                mx0 = fmaxf(mx0, red[(mt*16+g)*8+w]);
                mx1 = fmaxf(mx1, red[(mt*16+8+g)*8+w]);
            }
            mxs[mt][0]=mx0; mxs[mt][1]=mx1;
            if (z==0){ dd0[mt] = rowscale[grow] + mx0; dd1[mt] = rowscale[grow+8] + mx1; }
            else     { dd0[mt] = mx0;                  dd1[mt] = mx1; }
            if (z==1 && wid==0 && t==0){
                float* rowf = const_cast<float*>(res);
                rowf[grow]   = mx0 - rowscale[(long long)NHR + grow];
                rowf[grow+8] = mx1 - rowscale[(long long)NHR + grow+8];
            }
        }
        if (z==1 && wid==0){
            float bm = fmaxf(fmaxf(mxs[0][0],mxs[0][1]), fmaxf(mxs[1][0],mxs[1][1]));
            bm = fmaxf(bm, fmaxf(fmaxf(mxs[2][0],mxs[2][1]), fmaxf(mxs[3][0],mxs[3][1])));
            #pragma unroll
            for (int o=16;o;o>>=1) bm = fmaxf(bm, __shfl_xor_sync(0xffffffffu,bm,o));
            if (lane==0){
                unsigned b = __float_as_uint(bm);
                unsigned u = (b & 0x80000000u) ? ~b : (b | 0x80000000u);
                atomicMax(&g_gmax_u, u);
            }
        }
        __syncthreads();                      // red reads done before tile overwrite
        __half* sm16 = (__half*)sh;           // [64][LDS_C]
        #pragma unroll
        for (int mt=0; mt<4; ++mt){
            #pragma unroll
            for (int nt=0; nt<4; ++nt){
                const int c0 = warp_n + nt*8 + 2*t;
                __half2 o0, o1;
                if (z==0){
                    o0 = __floats2half2_rn(fmaf(__expf(acc[mt][nt][0]-dd0[mt]), RATIO_C, EPSR_C),
                                           fmaf(__expf(acc[mt][nt][1]-dd0[mt]), RATIO_C, EPSR_C));
                    o1 = __floats2half2_rn(fmaf(__expf(acc[mt][nt][2]-dd1[mt]), RATIO_C, EPSR_C),
                                           fmaf(__expf(acc[mt][nt][3]-dd1[mt]), RATIO_C, EPSR_C));
                } else {
                    o0 = __floats2half2_rn(__expf(acc[mt][nt][0]-dd0[mt]), __expf(acc[mt][nt][1]-dd0[mt]));
                    o1 = __floats2half2_rn(__expf(acc[mt][nt][2]-dd1[mt]), __expf(acc[mt][nt][3]-dd1[mt]));
                }
                *reinterpret_cast<__half2*>(sm16 + (mt*16+g)*LDS_C + c0)   = o0;
                *reinterpret_cast<__half2*>(sm16 + (mt*16+8+g)*LDS_C + c0) = o1;
            }
        }
        __syncthreads();
        #pragma unroll
        for (int it=0; it<8; ++it){
            const int idx = tid + it*256;
            const int row = idx >> 5, cc = idx & 31;
            uint4 v4 = *reinterpret_cast<const uint4*>(sm16 + row*LDS_C + cc*8);
            *reinterpret_cast<uint4*>(Ch + (long long)(brow+row)*ldc + cc*8) = v4;
        }
        return;
    }

    float sq[4][2];
    if (EPI==EPI_QKV){
        #pragma unroll
        for (int mt=0; mt<4; ++mt){ sq[mt][0]=0.f; sq[mt][1]=0.f; }
    }
    __half* sm16q = (__half*)sh;               // QKV stage: [128][136]

    #pragma unroll
    for (int mt=0; mt<4; ++mt){
        const int r0 = brow + warp_m + mt*16 + g;
        const int r1 = r0 + 8;
        float rs0 = 1.f, rs1 = 1.f;
        if (EPI==EPI_ATTN){
            rs0 = rowscale[(long long)z*M + r0];
            rs1 = rowscale[(long long)z*M + r1];
        }
        #pragma unroll
        for (int nt=0; nt<4; ++nt){
            const int c0 = bcol + warp_n + nt*8 + 2*t;
            float v00 = acc[mt][nt][0], v01 = acc[mt][nt][1];
            float v10 = acc[mt][nt][2], v11 = acc[mt][nt][3];
            if (EPI==EPI_BIAS_RES || EPI==EPI_BIAS_GELU || EPI==EPI_QKV){
                const float b0 = bias[c0], b1 = bias[c0+1];
                v00 += b0; v01 += b1; v10 += b0; v11 += b1;
            }
            if (EPI==EPI_BIAS_RES){
                v00 += res[(long long)r0*ldc + c0];   v01 += res[(long long)r0*ldc + c0+1];
                v10 += res[(long long)r1*ldc + c0];   v11 += res[(long long)r1*ldc + c0+1];
            }
            if (EPI==EPI_BIAS_GELU){
                v00 = 0.5f*v00*(1.0f+erff(v00*0.70710678118654752f));
                v01 = 0.5f*v01*(1.0f+erff(v01*0.70710678118654752f));
                v10 = 0.5f*v10*(1.0f+erff(v10*0.70710678118654752f));
                v11 = 0.5f*v11*(1.0f+erff(v11*0.70710678118654752f));
            }
            if (EPI==EPI_ATTN){ v00*=rs0; v01*=rs0; v10*=rs1; v11*=rs1; }

            if (EPI==EPI_QKV){
                sq[mt][0] += v00*v00 + v01*v01;
                sq[mt][1] += v10*v10 + v11*v11;
                const int rl0 = warp_m + mt*16 + g;
                const int cl  = warp_n + nt*8 + 2*t;
                *reinterpret_cast<__half2*>(sm16q + rl0*136 + cl)     = __floats2half2_rn(v00,v01);
                *reinterpret_cast<__half2*>(sm16q + (rl0+8)*136 + cl) = __floats2half2_rn(v10,v11);
            } else if (EPI==EPI_ATTN){
                const int bb = z/Hh, hh = z - (z/Hh)*Hh;
                __half* base = (__half*)Cv;
                const long long o0 = ((long long)(bb*Ss + r0))*Dd + hh*64 + c0;
                const long long o1 = ((long long)(bb*Ss + r1))*Dd + hh*64 + c0;
                *reinterpret_cast<__half2*>(base + o0) = __floats2half2_rn(v00,v01);
                *reinterpret_cast<__half2*>(base + o1) = __floats2half2_rn(v10,v11);
            } else if (OUTH){
                *reinterpret_cast<__half2*>(Ch + (long long)r0*ldc + c0) = __floats2half2_rn(v00,v01);
                *reinterpret_cast<__half2*>(Ch + (long long)r1*ldc + c0) = __floats2half2_rn(v10,v11);
            } else {
                float2 o0; o0.x=v00; o0.y=v01;
                float2 o1; o1.x=v10; o1.y=v11;
                *reinterpret_cast<float2*>(Cf + (long long)r0*ldc + c0) = o0;
                *reinterpret_cast<float2*>(Cf + (long long)r1*ldc + c0) = o1;
            }
        }
    }

    // QKV: diag reduce + coalesced copy-out of the staged tile (2 heads x 128 rows)
    if (EPI==EPI_QKV){
        const int sel_t = bcol/Dd;
        const int cc0   = bcol - sel_t*Dd;
        float* red = (float*)(sh + 8704);      // after 128*68-word tile
        #pragma unroll
        for (int mt=0; mt<4; ++mt){
            #pragma unroll
            for (int j=0;j<2;j++){
                float v = sq[mt][j];
                v += __shfl_xor_sync(0xffffffffu, v, 1);
                v += __shfl_xor_sync(0xffffffffu, v, 2);
                if (t==0) red[(warp_m + mt*16 + j*8 + g)*4 + wx] = v;
            }
        }
        __syncthreads();
        if (sel_t < 2){
            const int row  = tid >> 1;
            const int head = tid & 1;
            const float ssum = red[row*4 + 2*head] + red[row*4 + 2*head + 1];
            const int gr = brow + row;
            const int b_ = gr>>12, s_ = gr&4095;
            const int h_ = (cc0>>6) + head;
            g_diag[(size_t)sel_t*NHR + (((long long)(b_*Hh+h_))<<12) + s_] = DIAG_C*ssum;
        }
        const int b_ = brow>>12, s0 = brow&4095;
        __half* base = (__half*)Cv + (size_t)sel_t*NHR*DhD;
        #pragma unroll
        for (int it=0; it<8; ++it){
            const int idx = tid + it*256;          // 0..2047
            const int head = idx >> 10;
            const int rem = idx & 1023;
            const int row = rem >> 3, ch = rem & 7;
            uint4 v4 = *reinterpret_cast<const uint4*>(sm16q + row*136 + head*64 + ch*8);
            const int h_ = (cc0>>6) + head;
            *reinterpret_cast<uint4*>(base + ((((long long)(b_*Hh+h_))<<12) + s0 + row)*DhD + ch*8) = v4;
        }
    }
}

#define SMEM_H128x128 (2*(128+128)*36*4)   // 73728
#define SMEM_H64x256  (2*(64+256)*36*4)    // 92160
#define SMEM_H128x64  (2*(128+64)*36*4)    // 55296

// ================ ctx TN mma kernel, 4-way m split (BK=32, 3-stage) ====================
#define CTX_LDV 36
#define CTX_LDP 36
#define CTX_VW  (32*CTX_LDV)
#define CTX_PW  (32*CTX_LDP)
#define SMEM_CTX (3*(CTX_VW+CTX_PW)*4)     // 27648

__global__ void __launch_bounds__(256, 2)
ctx_mma(const __half* __restrict__ kpe, const __half* __restrict__ vh,
        const float* __restrict__ rowf,
        __half* __restrict__ ctxT, float* __restrict__ ksum)
{
    extern __shared__ uint32_t sh[];
    const uint32_t smb = smem_u32(sh);
    const uint32_t pbase = smb + (uint32_t)(3*CTX_VW)*4u;

    const int z = blockIdx.y;
    const int ntile = blockIdx.x;               // 0..3, 64 m-cols each
    const int tid = threadIdx.x, wid = tid>>5, lane = tid&31;
    const int warp_m = (wid & 3)*16;            // dh tile
    const int warp_n = (wid >> 2)*32;           // m tile
    const int g = lane>>2, t = lane&3;
    const int quad = lane>>3, r8 = lane&7;

    const __half* kpb = kpe + (long long)z*Ss*Mm + ntile*64;
    const __half* vhb = vh  + (long long)z*Ss*DhD;
    const float*  rfb = rowf + (long long)z*Ss;

    const float gmax = gmax_decode(g_gmax_u);
    const float epsr = EPSR_C;

    const uint32_t a_off0 = (uint32_t)((r8 + ((quad>>1)&1)*8)*CTX_LDV + (warp_m + (quad&1)*8)/2);
    const uint32_t b_off0 = (uint32_t)((r8 + (quad&1)*8)*CTX_LDP + (warp_n + (quad>>1)*8)/2);

    const int srow = tid >> 3;     // 0..31
    const int c8   = tid & 7;      // 8-half group

    float acc[4][4];
    #pragma unroll
    for (int j=0;j<4;j++)
        #pragma unroll
        for (int u=0;u<4;u++) acc[j][u]=0.f;
    float ks[8];
    #pragma unroll
    for (int j=0;j<8;j++) ks[j]=0.f;

    #define VISSUE(c) do{ \
        const uint32_t bV = smb + (uint32_t)(((c)%3)*CTX_VW)*4u; \
        cpa16(bV + (uint32_t)(srow*CTX_LDV + c8*4)*4u, \
              vhb + (long long)((c)*32 + srow)*DhD + c8*8); \
    }while(0)

    uint4 cur; float curf;
    cur  = *reinterpret_cast<const uint4*>(kpb + (long long)srow*Mm + c8*8);
    curf = rfb[srow];
    VISSUE(0); CP_COMMIT();
    VISSUE(1); CP_COMMIT();

    for (int i=0; i<Ss/32; ++i){
        {
            const float As = RATIO_C*__expf(curf - gmax);
            uint32_t rw[4] = {cur.x,cur.y,cur.z,cur.w};
            uint32_t ow[4];
            #pragma unroll
            for (int j=0;j<4;j++){
                float2 f = __half22float2(*reinterpret_cast<__half2*>(&rw[j]));
                f.x = fmaf(f.x, As, epsr);
                f.y = fmaf(f.y, As, epsr);
                __half2 h = __floats2half2_rn(f.x, f.y);
                float2 fr = __half22float2(h);
                ks[2*j]   += fr.x;
                ks[2*j+1] += fr.y;
                ow[j] = *reinterpret_cast<uint32_t*>(&h);
            }
            const uint32_t bP = pbase + (uint32_t)((i%3)*CTX_PW)*4u
                              + (uint32_t)(srow*CTX_LDP + c8*4)*4u;
            uint4 s0 = {ow[0],ow[1],ow[2],ow[3]};
            *reinterpret_cast<uint4*>((char*)sh + (bP - smb)) = s0;
        }
        CP_WAIT1();
        __syncthreads();
        if (i+2 < Ss/32) VISSUE(i+2);
        CP_COMMIT();
        if (i+1 < Ss/32){
            cur  = *reinterpret_cast<const uint4*>(kpb + (long long)((i+1)*32 + srow)*Mm + c8*8);
            curf = rfb[(i+1)*32 + srow];
        }

        const uint32_t vstg = smb + (uint32_t)((i%3)*CTX_VW)*4u;
        const uint32_t pstg = pbase + (uint32_t)((i%3)*CTX_PW)*4u;

        #pragma unroll
        for (int kk=0; kk<2; ++kk){
            uint32_t af[4], bf[4][2];
            LDSM4T(af[0],af[1],af[2],af[3],
                   vstg + (a_off0 + (uint32_t)(kk*16*CTX_LDV))*4u);
            #pragma unroll
            for (int pp2=0; pp2<2; ++pp2)
                LDSM4T(bf[2*pp2][0],bf[2*pp2][1],bf[2*pp2+1][0],bf[2*pp2+1][1],
                       pstg + (b_off0 + (uint32_t)(kk*16*CTX_LDP + pp2*8))*4u);
            #pragma unroll
            for (int nt=0; nt<4; ++nt)
                mma_f16(acc[nt], af, bf[nt]);
        }
    }
    #undef VISSUE

    const int dh0 = warp_m + g;
    const int dh1 = dh0 + 8;
    #pragma unroll
    for (int nt=0; nt<4; ++nt){
        const int col = ntile*64 + warp_n + nt*8 + 2*t;
        *reinterpret_cast<__half2*>(ctxT + (long long)z*DhD*Mm + (long long)dh0*Mm + col)
            = __floats2half2_rn(acc[nt][0], acc[nt][1]);
        *reinterpret_cast<__half2*>(ctxT + (long long)z*DhD*Mm + (long long)dh1*Mm + col)
            = __floats2half2_rn(acc[nt][2], acc[nt][3]);
    }

    __syncthreads();
    float* red = (float*)sh;                // [32][64]
    #pragma unroll
    for (int j=0;j<8;j++) red[srow*64 + c8*8 + j] = ks[j];
    __syncthreads();
    if (tid < 64){
        float s = 0.f;
        #pragma unroll
        for (int r=0;r<32;r++) s += red[r*64 + tid];
        ksum[z*Mm + ntile*64 + tid] = s;
    }
}

// ---------------- single setup kernel: all weight f2h + bias pack + gmax reset --------
__global__ void setup_kernel(const float* __restrict__ wq, const float* __restrict__ wk,
                             const float* __restrict__ wv, const float* __restrict__ wo,
                             const float* __restrict__ w1, const float* __restrict__ w2,
                             const float* __restrict__ proj,
                             const float* __restrict__ bq, const float* __restrict__ bk,
                             const float* __restrict__ bv)
{
    const long long i = (long long)blockIdx.x*256 + threadIdx.x;
    const long long Q = Dd*Dd/4;
    const long long W = (long long)FFH*Dd/4;
    const long long P = Mm*DhD/4;
    const long long T0 = 4*Q, T1 = T0 + 2*W + P, T2 = T1 + 3*Dd;
    if (i < T0){
        const int seg = (int)(i/Q), off = (int)(i - seg*Q);
        const float* s = (seg==0)?wq:(seg==1)?wk:(seg==2)?wv:wo;
        __half* d = (seg<3) ? (g_wqkvh + (size_t)seg*Dd*Dd) : g_woh;
        float4 v = reinterpret_cast<const float4*>(s)[off];
        __half2* o = reinterpret_cast<__half2*>(d) + 2*off;
        o[0] = __floats2half2_rn(v.x, v.y);
        o[1] = __floats2half2_rn(v.z, v.w);
    } else if (i < T1){
        long long j = i - T0;
        const float* s; __half* d; int off; float scale = 1.f;
        if (j < W)          { s = w1;   d = g_w1h;   off = (int)j; }
        else if (j < 2*W)   { s = w2;   d = g_w2h;   off = (int)(j - W); }
        else                { s = proj; d = g_projh; off = (int)(j - 2*W); scale = NORM_C; }
        float4 v = reinterpret_cast<const float4*>(s)[off];
        __half2* o = reinterpret_cast<__half2*>(d) + 2*off;
        o[0] = __floats2half2_rn(v.x*scale, v.y*scale);
        o[1] = __floats2half2_rn(v.z*scale, v.w*scale);
    } else if (i < T2){
        const int j = (int)(i - T1);
        const int sel = j/Dd, c = j - sel*Dd;
        g_bqkv[j] = sel==0 ? bq[c] : (sel==1 ? bk[c] : bv[c]);
    } else if (i == T2){
        g_gmax_u = 0u;
    }
}
#define SETUP_N (4LL*(Dd*Dd/4) + 2LL*((long long)FFH*Dd/4) + Mm*DhD/4 + 3*Dd + 1)

// ---------------- LayerNorm (row=768), half output ----------------
__global__ void ln_kernel(const float* __restrict__ x, const float* __restrict__ g,
                          const float* __restrict__ b, __half* __restrict__ out)
{
    const int row = blockIdx.x;
    const float* xr = x + (long long)row*Dd;
    float v[3]; float s=0.f, ss=0.f;
    #pragma unroll
    for (int i=0;i<3;i++){ v[i]=xr[threadIdx.x + i*256]; s+=v[i]; ss+=v[i]*v[i]; }
    #pragma unroll
    for (int o=16;o;o>>=1){ s+=__shfl_xor_sync(0xffffffffu,s,o); ss+=__shfl_xor_sync(0xffffffffu,ss,o); }
    __shared__ float rs_[8], rss_[8];
    const int lane = threadIdx.x & 31, w = threadIdx.x >> 5;
    if (lane==0){ rs_[w]=s; rss_[w]=ss; }
    __syncthreads();
    s=0.f; ss=0.f;
    #pragma unroll
    for (int i=0;i<8;i++){ s+=rs_[i]; ss+=rss_[i]; }
    const float mu  = s*(1.0f/Dd);
    const float var = ss*(1.0f/Dd) - mu*mu;
    const float rstd = rsqrtf(var + LN_EPS);
    __half* outr = out + (long long)row*Dd;
    #pragma unroll
    for (int i=0;i<3;i++){
        int c = threadIdx.x + i*256;
        outr[c] = __float2half((v[i]-mu)*rstd*g[c] + b[c]);
    }
}

// ---------------- d_inv: half qp, fp32 ksum (warp per row) ----------------
__global__ void dinv_kernel(const __half* __restrict__ qp, float* __restrict__ dinv)
{
    const int lane = threadIdx.x & 31, w = threadIdx.x >> 5;
    const long long row = (long long)blockIdx.x*8 + w;
    const int bh = (int)(row >> 12);
    const __half2* p = reinterpret_cast<const __half2*>(qp + row*Mm);
    const float4* ks = reinterpret_cast<const float4*>(g_ksum + (long long)bh*Mm);
    float s = 0.f;
    #pragma unroll
    for (int h=0; h<2; ++h){
        const int li = lane + h*32;
        float2 a0 = __half22float2(p[2*li]), a1 = __half22float2(p[2*li+1]);
        float4 k4 = ks[li];
        s += a0.x*k4.x + a0.y*k4.y + a1.x*k4.z + a1.y*k4.w;
    }
    #pragma unroll
    for (int o=16;o;o>>=1) s += __shfl_xor_sync(0xffffffffu,s,o);
    if (lane==0) dinv[row] = 1.0f/s;
}

// ---------------- host ----------------
extern "C" void kernel_launch(void* const* d_in, const int* in_sizes, int n_in,
                              void* d_out, int out_size)
{
    const float* x    = (const float*)d_in[0];
    const float* proj = (const float*)d_in[1];
    const float* wq   = (const float*)d_in[2];
    const float* bq   = (const float*)d_in[3];
    const float* wk   = (const float*)d_in[4];
    const float* bk   = (const float*)d_in[5];
    const float* wv   = (const float*)d_in[6];
    const float* bv   = (const float*)d_in[7];
    const float* wo   = (const float*)d_in[8];
    const float* bo   = (const float*)d_in[9];
    const float* ln1g = (const float*)d_in[10];
    const float* ln1b = (const float*)d_in[11];
    const float* ln2g = (const float*)d_in[12];
    const float* ln2b = (const float*)d_in[13];
    const float* w1   = (const float*)d_in[14];
    const float* b1   = (const float*)d_in[15];
    const float* w2   = (const float*)d_in[16];
    const float* b2   = (const float*)d_in[17];
    float* out = (float*)d_out;

    void *p;
    __half *wqkvh, *h1h, *qkvh, *qkph, *midh, *ctxTh, *attn2h, *woh, *w1h, *w2h, *projh;
    float *ddiag, *rowf, *x2, *dinv, *ksum, *bqkv;
    cudaGetSymbolAddress(&p, g_wqkvh);  wqkvh  = (__half*)p;
    cudaGetSymbolAddress(&p, g_woh);    woh    = (__half*)p;
    cudaGetSymbolAddress(&p, g_w1h);    w1h    = (__half*)p;
    cudaGetSymbolAddress(&p, g_w2h);    w2h    = (__half*)p;
    cudaGetSymbolAddress(&p, g_projh);  projh  = (__half*)p;
    cudaGetSymbolAddress(&p, g_h1h);    h1h    = (__half*)p;
    cudaGetSymbolAddress(&p, g_qkvh);   qkvh   = (__half*)p;
    cudaGetSymbolAddress(&p, g_qkph);   qkph   = (__half*)p;
    cudaGetSymbolAddress(&p, g_midh);   midh   = (__half*)p;
    cudaGetSymbolAddress(&p, g_ctxTh);  ctxTh  = (__half*)p;
    cudaGetSymbolAddress(&p, g_attn2h); attn2h = (__half*)p;
    cudaGetSymbolAddress(&p, g_x2);     x2     = (float*)p;
    cudaGetSymbolAddress(&p, g_diag);   ddiag  = (float*)p;
    cudaGetSymbolAddress(&p, g_rowf);   rowf   = (float*)p;
    cudaGetSymbolAddress(&p, g_dinv);   dinv   = (float*)p;
    cudaGetSymbolAddress(&p, g_ksum);   ksum   = (float*)p;
    cudaGetSymbolAddress(&p, g_bqkv);   bqkv   = (float*)p;

    __half* qh = qkvh;
    __half* vh = qkvh + 2*(size_t)NHR*DhD;
    __half* qph = qkph;
    __half* kph = qkph + (size_t)NHR*Mm;

    cudaFuncSetAttribute(hgemm<128,128,EPI_QKV,true>,       cudaFuncAttributeMaxDynamicSharedMemorySize, SMEM_H128x128);
    cudaFuncSetAttribute(hgemm<64,256,EPI_FEAT,true>,       cudaFuncAttributeMaxDynamicSharedMemorySize, SMEM_H64x256);
    cudaFuncSetAttribute(hgemm<128,64,EPI_ATTN,true>,       cudaFuncAttributeMaxDynamicSharedMemorySize, SMEM_H128x64);
    cudaFuncSetAttribute(hgemm<128,128,EPI_BIAS_RES,false>, cudaFuncAttributeMaxDynamicSharedMemorySize, SMEM_H128x128);
    cudaFuncSetAttribute(hgemm<128,128,EPI_BIAS_GELU,true>, cudaFuncAttributeMaxDynamicSharedMemorySize, SMEM_H128x128);

    // fork: setup (weights) on s2 concurrent with LN1 on the main stream
    static cudaStream_t s2 = nullptr;
    static cudaEvent_t evf = nullptr, evj = nullptr;
    if (!s2){
        cudaStreamCreateWithFlags(&s2, cudaStreamNonBlocking);
        cudaEventCreateWithFlags(&evf, cudaEventDisableTiming);
        cudaEventCreateWithFlags(&evj, cudaEventDisableTiming);
    }
    cudaEventRecord(evf, 0);
    cudaStreamWaitEvent(s2, evf, 0);
    setup_kernel<<<(int)((SETUP_N + 255)/256), 256, 0, s2>>>(wq,wk,wv,wo,w1,w2,proj,bq,bk,bv);
    cudaEventRecord(evj, s2);
    ln_kernel<<<NROWS, 256>>>(x, ln1g, ln1b, h1h);
    cudaStreamWaitEvent(0, evj, 0);

    // fused QKV (N=2304) + fused diag (q,k), staged coalesced stores
    hgemm<128,128,EPI_QKV,true><<<dim3(18,128,1),256,SMEM_H128x128>>>(
        h1h,Dd,0, wqkvh,Dd,0, qkvh,DhD,0, NROWS,3*Dd,Dd, bqkv,nullptr,nullptr,0.f);

    // q+k features in ONE launch (z=0: q, z=1: k); GEMM + rowmax + exp, staged stores
    hgemm<64,256,EPI_FEAT,true><<<dim3(1,NHR/64,2),256,SMEM_H64x256>>>(
        qh,DhD,(long long)NHR*DhD, projh,DhD,0, qkph,Mm,(long long)NHR*Mm,
        NHR,Mm,DhD, nullptr,rowf,ddiag,1.f);

    // ctx (tensor mma, TN, 4-way m split) + fused ksum
    ctx_mma<<<dim3(4,NBH), 256, SMEM_CTX>>>(kph, vh, rowf, ctxTh, ksum);

    // d_inv
    dinv_kernel<<<NHR/8, 256>>>(qph, dinv);

    // attn = d_inv * (qp @ ctx), fused transpose -> attn2h [b,s,D]
    hgemm<128,64,EPI_ATTN,true><<<dim3(1,Ss/128,NBH),128,SMEM_H128x64>>>(
        qph,Mm,(long long)Ss*Mm, ctxTh,Mm,(long long)DhD*Mm, attn2h,DhD,0,
        Ss,DhD,Mm, nullptr,nullptr,dinv,0.f);

    // x2 = x + attn @ wo^T + bo (fp32)
    hgemm<128,128,EPI_BIAS_RES,false><<<dim3(6,128,1),256,SMEM_H128x128>>>(
        attn2h,Dd,0, woh,Dd,0, x2,Dd,0, NROWS,Dd,Dd, bo,x,nullptr,0.f);

    // LN2 -> half
    ln_kernel<<<NROWS, 256>>>(x2, ln2g, ln2b, h1h);

    // mid = gelu(h1 @ w1^T + b1) -> half
    hgemm<128,128,EPI_BIAS_GELU,true><<<dim3(FFH/128,128,1),256,SMEM_H128x128>>>(
        h1h,Dd,0, w1h,Dd,0, midh,FFH,0, NROWS,FFH,Dd, b1,nullptr,nullptr,0.f);

    // out = x2 + mid @ w2^T + b2 (fp32)
    hgemm<128,128,EPI_BIAS_RES,false><<<dim3(6,128,1),256,SMEM_H128x128>>>(
        midh,FFH,0, w2h,FFH,0, out,Dd,0, NROWS,Dd,FFH, b2,x2,nullptr,0.f);
}

// round 15
// speedup vs baseline: 1.0382x; 1.0235x over previous
#include <cuda_runtime.h>
#include <cuda_fp16.h>
#include <math.h>
#include <stdint.h>

// ---------------- problem constants ----------------
#define Bb   4
#define Ss   4096
#define Dd   768
#define Hh   12
#define Mm   256
#define DhD  64
#define NROWS (Bb*Ss)        // 16384
#define NBH   (Bb*Hh)        // 48
#define NHR   (NBH*Ss)       // 196608
#define FFH   (4*Dd)         // 3072

#define NORM_C   0.35355339059327373f
#define RATIO_C  0.0625f
#define DIAG_C   0.0625f
#define EPS_K    1e-4f
#define EPSR_C   (RATIO_C*EPS_K)
#define LN_EPS   1e-5f

// ---------------- scratch (device globals; allocation-free) ----------------
__device__ __half g_wqkvh[3*Dd*Dd];
__device__ float  g_bqkv[3*Dd];
__device__ __half g_woh[Dd*Dd];
__device__ __half g_w1h[FFH*Dd];
__device__ __half g_w2h[Dd*FFH];
__device__ __half g_projh[Mm*DhD];               // pre-scaled by NORM_C
__device__ __half g_h1h[NROWS*Dd];
__device__ __half g_qkvh[3*(size_t)NHR*DhD];      // q,k,v in [sel][b,h,s,dh]
__device__ __half g_qkph[2*(size_t)NHR*Mm];       // [qp | kp(exp(dd-rowmax))]
__device__ __half g_midh[(size_t)NROWS*FFH];
__device__ __half g_ctxTh[NBH*DhD*Mm];            // [bh][dh][m]
__device__ __half g_attn2h[(size_t)NROWS*Dd];     // [b,s,D]
__device__ float  g_x2[NROWS*Dd];
__device__ float  g_diag[2*NHR];                  // [q rows | k rows]
__device__ float  g_rowf[NHR];                    // rowmax(dd_k) - diag_k
__device__ float  g_ksum[NBH*Mm];
__device__ unsigned g_gmax_u;

// ---------------- epilogue modes ----------------
enum { EPI_BIAS_RES=1, EPI_BIAS_GELU=2, EPI_QKV=5, EPI_FEAT=6, EPI_ATTN=8 };

__device__ __forceinline__ void cpa16(uint32_t smem_dst, const void* gsrc){
    asm volatile("cp.async.cg.shared.global [%0], [%1], 16;" :: "r"(smem_dst), "l"(gsrc));
}
#define CP_COMMIT() asm volatile("cp.async.commit_group;" ::: "memory")
#define CP_WAIT0()  asm volatile("cp.async.wait_group 0;" ::: "memory")
#define CP_WAIT1()  asm volatile("cp.async.wait_group 1;" ::: "memory")

__device__ __forceinline__ uint32_t smem_u32(const void* p){
    uint32_t a;
    asm("{ .reg .u64 t; cvta.to.shared.u64 t, %1; cvt.u32.u64 %0, t; }" : "=r"(a) : "l"(p));
    return a;
}

__device__ __forceinline__ void mma_f16(float* d, const uint32_t* a, const uint32_t* b){
    asm volatile("mma.sync.aligned.m16n8k16.row.col.f32.f16.f16.f32 "
        "{%0,%1,%2,%3}, {%4,%5,%6,%7}, {%8,%9}, {%0,%1,%2,%3};"
        : "+f"(d[0]),"+f"(d[1]),"+f"(d[2]),"+f"(d[3])
        : "r"(a[0]),"r"(a[1]),"r"(a[2]),"r"(a[3]), "r"(b[0]),"r"(b[1]));
}
#define LDSM4(r0,r1,r2,r3,addr) \
    asm volatile("ldmatrix.sync.aligned.m8n8.x4.shared.b16 {%0,%1,%2,%3}, [%4];" \
        : "=r"(r0),"=r"(r1),"=r"(r2),"=r"(r3) : "r"(addr))
#define LDSM4T(r0,r1,r2,r3,addr) \
    asm volatile("ldmatrix.sync.aligned.m8n8.x4.trans.shared.b16 {%0,%1,%2,%3}, [%4];" \
        : "=r"(r0),"=r"(r1),"=r"(r2),"=r"(r3) : "r"(addr))

__device__ __forceinline__ float gmax_decode(unsigned u){
    return (u & 0x80000000u) ? __uint_as_float(u ^ 0x80000000u) : __uint_as_float(~u);
}

// ================= fp16 NT GEMM: mma.sync m16n8k16, BK=64, 2-stage cp.async ============
// EPI_ATTN: rowscale = g_ksum base; denominator fused (dinv computed in-kernel).
template<int BM,int BN,int EPI,bool OUTH>
__global__ void __launch_bounds__(32*(BM/64)*(BN/32), (BM==128 && BN==64) ? 3 : 2)
hgemm(const __half* __restrict__ A, int lda, long long strA,
      const __half* __restrict__ B, int ldb, long long strB,
      void* __restrict__ Cv, int ldc, long long strC,
      int M, int N, int K,
      const float* __restrict__ bias,
      const float* __restrict__ res,
      const float* __restrict__ rowscale,
      float alpha)
{
    constexpr int WY = BM/64, WX = BN/32, THREADS = 32*WY*WX;
    constexpr int LDKW = 36;                 // 32 data words (64 halfs) + 4 pad
    constexpr int AW = BM*LDKW;
    constexpr int SW = (BM+BN)*LDKW;
    constexpr int ALD = (BM*8)/THREADS;
    constexpr int BLD = (BN*8)/THREADS;

    extern __shared__ uint32_t sh[];
    const uint32_t smb = smem_u32(sh);

    const int z = blockIdx.z;
    A += (long long)z*strA;  B += (long long)z*strB;
    float*  Cf = (float*)Cv  + (long long)z*strC;
    __half* Ch = (__half*)Cv + (long long)z*strC;

    const int brow = blockIdx.y*BM;
    const int bcol = blockIdx.x*BN;
    const int tid  = threadIdx.x;
    const int wid  = tid >> 5;
    const int lane = tid & 31;
    const int wx   = wid % WX, wy = wid / WX;
    const int warp_m = wy*64, warp_n = wx*32;
    const int g = lane >> 2, t = lane & 3;

    const uint32_t aoff = (uint32_t)(((warp_m + (lane&15))*LDKW + (lane>>4)*4))*4u;
    const uint32_t boff = (uint32_t)((AW + (warp_n + (lane>>4)*8 + (lane&7))*LDKW + ((lane>>3)&1)*4))*4u;

    float acc[4][4][4];
    #pragma unroll
    for (int i=0;i<4;i++)
        #pragma unroll
        for (int j=0;j<4;j++)
            #pragma unroll
            for (int u=0;u<4;u++) acc[i][j][u]=0.f;

    float den = 0.f;
    if (EPI==EPI_ATTN){
        // stage ksum[bh] into smem (after the 2 tile stages)
        float* sks = (float*)(sh + 2*SW);
        #pragma unroll
        for (int l=0; l<(Mm+THREADS-1)/THREADS; ++l){
            const int idx = tid + l*THREADS;
            if (idx < Mm) sks[idx] = rowscale[(long long)z*Mm + idx];
        }
    }

    const int nc = K >> 6;

    #define HISSUE(chunk) do{                                                  \
        const uint32_t bA_ = smb + (uint32_t)(((chunk)&1)*SW)*4u;              \
        const uint32_t bB_ = bA_ + (uint32_t)AW*4u;                            \
        const __half* Ap_ = A + (long long)brow*lda + (chunk)*64;              \
        const __half* Bp_ = B + (long long)bcol*ldb + (chunk)*64;              \
        _Pragma("unroll")                                                      \
        for (int l=0;l<ALD;l++){                                               \
            const int idx = tid + l*THREADS, r = idx>>3, c4 = idx&7;           \
            cpa16(bA_ + (uint32_t)(r*LDKW + c4*4)*4u,                          \
                  Ap_ + (long long)r*lda + c4*8);                              \
        }                                                                      \
        _Pragma("unroll")                                                      \
        for (int l=0;l<BLD;l++){                                               \
            const int idx = tid + l*THREADS, r = idx>>3, c4 = idx&7;           \
            cpa16(bB_ + (uint32_t)(r*LDKW + c4*4)*4u,                          \
                  Bp_ + (long long)r*ldb + c4*8);                              \
        }                                                                      \
    }while(0)

    HISSUE(0);
    CP_COMMIT();

    for (int i=0; i<nc; ++i){
        if (i+1 < nc){ HISSUE(i+1); CP_COMMIT(); CP_WAIT1(); }
        else         { CP_WAIT0(); }
        __syncthreads();

        const uint32_t stg = smb + (uint32_t)((i&1)*SW)*4u;

        if (EPI==EPI_ATTN){
            // denominator: row tid dot ksum over this chunk's 64 cols
            const float* sks = (const float*)(sh + 2*SW) + i*64;
            const uint4* arow4 = reinterpret_cast<const uint4*>(sh + (i&1)*SW + tid*LDKW);
            #pragma unroll
            for (int j=0;j<8;j++){
                uint4 w4 = arow4[j];
                float2 f0 = __half22float2(*reinterpret_cast<__half2*>(&w4.x));
                float2 f1 = __half22float2(*reinterpret_cast<__half2*>(&w4.y));
                float2 f2 = __half22float2(*reinterpret_cast<__half2*>(&w4.z));
                float2 f3 = __half22float2(*reinterpret_cast<__half2*>(&w4.w));
                den += f0.x*sks[8*j]   + f0.y*sks[8*j+1]
                     + f1.x*sks[8*j+2] + f1.y*sks[8*j+3]
                     + f2.x*sks[8*j+4] + f2.y*sks[8*j+5]
                     + f3.x*sks[8*j+6] + f3.y*sks[8*j+7];
            }
        }

        #pragma unroll
        for (int kk=0; kk<4; ++kk){
            uint32_t af[4][4], bf[4][2];
            #pragma unroll
            for (int mt=0; mt<4; ++mt)
                LDSM4(af[mt][0],af[mt][1],af[mt][2],af[mt][3],
                      stg + aoff + (uint32_t)((mt*16*LDKW + kk*8))*4u);
            LDSM4(bf[0][0],bf[0][1],bf[1][0],bf[1][1],
                  stg + boff + (uint32_t)(kk*8)*4u);
            LDSM4(bf[2][0],bf[2][1],bf[3][0],bf[3][1],
                  stg + boff + (uint32_t)((16*LDKW + kk*8))*4u);
            #pragma unroll
            for (int mt=0; mt<4; ++mt)
                #pragma unroll
                for (int nt=0; nt<4; ++nt)
                    mma_f16(acc[mt][nt], af[mt], bf[nt]);
        }
        __syncthreads();
    }
    #undef HISSUE

    // ================= epilogues =================
    if (EPI==EPI_FEAT){
        constexpr int LDS_C = 264;             // 256 + 8 pad (halfs)
        float mxs[4][2];
        #pragma unroll
        for (int mt=0; mt<4; ++mt){
            float m0=-3.402823466e38f, m1=m0;
            #pragma unroll
            for (int nt=0; nt<4; ++nt){
                m0 = fmaxf(m0, fmaxf(acc[mt][nt][0], acc[mt][nt][1]));
                m1 = fmaxf(m1, fmaxf(acc[mt][nt][2], acc[mt][nt][3]));
            }
            m0 = fmaxf(m0, __shfl_xor_sync(0xffffffffu,m0,1));
            m0 = fmaxf(m0, __shfl_xor_sync(0xffffffffu,m0,2));
            m1 = fmaxf(m1, __shfl_xor_sync(0xffffffffu,m1,1));
            m1 = fmaxf(m1, __shfl_xor_sync(0xffffffffu,m1,2));
            mxs[mt][0]=m0; mxs[mt][1]=m1;
        }
        __syncthreads();
        float* red = (float*)sh;               // [64][8]
        if (t==0){
            #pragma unroll
            for (int mt=0; mt<4; ++mt){
                red[(mt*16+g)*8 + wid]   = mxs[mt][0];
                red[(mt*16+8+g)*8 + wid] = mxs[mt][1];
            }
        }
        __syncthreads();
        float dd0[4], dd1[4];
        #pragma unroll
        for (int mt=0; mt<4; ++mt){
            const int grow = brow + mt*16 + g;
            float mx0 = red[(mt*16+g)*8], mx1 = red[(mt*16+8+g)*8];
            #pragma unroll
            for (int w=1; w<8; ++w){
                mx0 = fmaxf(mx0, red[(mt*16+g)*8+w]);
                mx1 = fmaxf(mx1, red[(mt*16+8+g)*8+w]);
            }
            mxs[mt][0]=mx0; mxs[mt][1]=mx1;
            if (z==0){ dd0[mt] = rowscale[grow] + mx0; dd1[mt] = rowscale[grow+8] + mx1; }
            else     { dd0[mt] = mx0;                  dd1[mt] = mx1; }
            if (z==1 && wid==0 && t==0){
                float* rowf = const_cast<float*>(res);
                rowf[grow]   = mx0 - rowscale[(long long)NHR + grow];
                rowf[grow+8] = mx1 - rowscale[(long long)NHR + grow+8];
            }
        }
        if (z==1 && wid==0){
            float bm = fmaxf(fmaxf(mxs[0][0],mxs[0][1]), fmaxf(mxs[1][0],mxs[1][1]));
            bm = fmaxf(bm, fmaxf(fmaxf(mxs[2][0],mxs[2][1]), fmaxf(mxs[3][0],mxs[3][1])));
            #pragma unroll
            for (int o=16;o;o>>=1) bm = fmaxf(bm, __shfl_xor_sync(0xffffffffu,bm,o));
            if (lane==0){
                unsigned b = __float_as_uint(bm);
                unsigned u = (b & 0x80000000u) ? ~b : (b | 0x80000000u);
                atomicMax(&g_gmax_u, u);
            }
        }
        __syncthreads();
        __half* sm16 = (__half*)sh;           // [64][LDS_C]
        #pragma unroll
        for (int mt=0; mt<4; ++mt){
            #pragma unroll
            for (int nt=0; nt<4; ++nt){
                const int c0 = warp_n + nt*8 + 2*t;
                __half2 o0, o1;
                if (z==0){
                    o0 = __floats2half2_rn(fmaf(__expf(acc[mt][nt][0]-dd0[mt]), RATIO_C, EPSR_C),
                                           fmaf(__expf(acc[mt][nt][1]-dd0[mt]), RATIO_C, EPSR_C));
                    o1 = __floats2half2_rn(fmaf(__expf(acc[mt][nt][2]-dd1[mt]), RATIO_C, EPSR_C),
                                           fmaf(__expf(acc[mt][nt][3]-dd1[mt]), RATIO_C, EPSR_C));
                } else {
                    o0 = __floats2half2_rn(__expf(acc[mt][nt][0]-dd0[mt]), __expf(acc[mt][nt][1]-dd0[mt]));
                    o1 = __floats2half2_rn(__expf(acc[mt][nt][2]-dd1[mt]), __expf(acc[mt][nt][3]-dd1[mt]));
                }
                *reinterpret_cast<__half2*>(sm16 + (mt*16+g)*LDS_C + c0)   = o0;
                *reinterpret_cast<__half2*>(sm16 + (mt*16+8+g)*LDS_C + c0) = o1;
            }
        }
        __syncthreads();
        #pragma unroll
        for (int it=0; it<8; ++it){
            const int idx = tid + it*256;
            const int row = idx >> 5, cc = idx & 31;
            uint4 v4 = *reinterpret_cast<const uint4*>(sm16 + row*LDS_C + cc*8);
            *reinterpret_cast<uint4*>(Ch + (long long)(brow+row)*ldc + cc*8) = v4;
        }
        return;
    }

    float* sden = nullptr;
    if (EPI==EPI_ATTN){
        sden = (float*)(sh + 2*SW) + Mm;
        sden[tid] = 1.0f/den;
        __syncthreads();
    }

    float sq[4][2];
    if (EPI==EPI_QKV){
        #pragma unroll
        for (int mt=0; mt<4; ++mt){ sq[mt][0]=0.f; sq[mt][1]=0.f; }
    }
    __half* sm16q = (__half*)sh;               // QKV stage: [128][136]

    #pragma unroll
    for (int mt=0; mt<4; ++mt){
        const int r0 = brow + warp_m + mt*16 + g;
        const int r1 = r0 + 8;
        float rs0 = 1.f, rs1 = 1.f;
        if (EPI==EPI_ATTN){
            rs0 = sden[warp_m + mt*16 + g];
            rs1 = sden[warp_m + mt*16 + 8 + g];
        }
        #pragma unroll
        for (int nt=0; nt<4; ++nt){
            const int c0 = bcol + warp_n + nt*8 + 2*t;
            float v00 = acc[mt][nt][0], v01 = acc[mt][nt][1];
            float v10 = acc[mt][nt][2], v11 = acc[mt][nt][3];
            if (EPI==EPI_BIAS_RES || EPI==EPI_BIAS_GELU || EPI==EPI_QKV){
                const float b0 = bias[c0], b1 = bias[c0+1];
                v00 += b0; v01 += b1; v10 += b0; v11 += b1;
            }
            if (EPI==EPI_BIAS_RES){
                v00 += res[(long long)r0*ldc + c0];   v01 += res[(long long)r0*ldc + c0+1];
                v10 += res[(long long)r1*ldc + c0];   v11 += res[(long long)r1*ldc + c0+1];
            }
            if (EPI==EPI_BIAS_GELU){
                v00 = 0.5f*v00*(1.0f+erff(v00*0.70710678118654752f));
                v01 = 0.5f*v01*(1.0f+erff(v01*0.70710678118654752f));
                v10 = 0.5f*v10*(1.0f+erff(v10*0.70710678118654752f));
                v11 = 0.5f*v11*(1.0f+erff(v11*0.70710678118654752f));
            }
            if (EPI==EPI_ATTN){ v00*=rs0; v01*=rs0; v10*=rs1; v11*=rs1; }

            if (EPI==EPI_QKV){
                sq[mt][0] += v00*v00 + v01*v01;
                sq[mt][1] += v10*v10 + v11*v11;
                const int rl0 = warp_m + mt*16 + g;
                const int cl  = warp_n + nt*8 + 2*t;
                *reinterpret_cast<__half2*>(sm16q + rl0*136 + cl)     = __floats2half2_rn(v00,v01);
                *reinterpret_cast<__half2*>(sm16q + (rl0+8)*136 + cl) = __floats2half2_rn(v10,v11);
            } else if (EPI==EPI_ATTN){
                const int bb = z/Hh, hh = z - (z/Hh)*Hh;
                __half* base = (__half*)Cv;
                const long long o0 = ((long long)(bb*Ss + r0))*Dd + hh*64 + c0;
                const long long o1 = ((long long)(bb*Ss + r1))*Dd + hh*64 + c0;
                *reinterpret_cast<__half2*>(base + o0) = __floats2half2_rn(v00,v01);
                *reinterpret_cast<__half2*>(base + o1) = __floats2half2_rn(v10,v11);
            } else if (OUTH){
                *reinterpret_cast<__half2*>(Ch + (long long)r0*ldc + c0) = __floats2half2_rn(v00,v01);
                *reinterpret_cast<__half2*>(Ch + (long long)r1*ldc + c0) = __floats2half2_rn(v10,v11);
            } else {
                float2 o0; o0.x=v00; o0.y=v01;
                float2 o1; o1.x=v10; o1.y=v11;
                *reinterpret_cast<float2*>(Cf + (long long)r0*ldc + c0) = o0;
                *reinterpret_cast<float2*>(Cf + (long long)r1*ldc + c0) = o1;
            }
        }
    }

    // QKV: diag reduce + coalesced copy-out of the staged tile (2 heads x 128 rows)
    if (EPI==EPI_QKV){
        const int sel_t = bcol/Dd;
        const int cc0   = bcol - sel_t*Dd;
        float* red = (float*)(sh + 8704);      // after 128*68-word tile
        #pragma unroll
        for (int mt=0; mt<4; ++mt){
            #pragma unroll
            for (int j=0;j<2;j++){
                float v = sq[mt][j];
                v += __shfl_xor_sync(0xffffffffu, v, 1);
                v += __shfl_xor_sync(0xffffffffu, v, 2);
                if (t==0) red[(warp_m + mt*16 + j*8 + g)*4 + wx] = v;
            }
        }
        __syncthreads();
        if (sel_t < 2){
            const int row  = tid >> 1;
            const int head = tid & 1;
            const float ssum = red[row*4 + 2*head] + red[row*4 + 2*head + 1];
            const int gr = brow + row;
            const int b_ = gr>>12, s_ = gr&4095;
            const int h_ = (cc0>>6) + head;
            g_diag[(size_t)sel_t*NHR + (((long long)(b_*Hh+h_))<<12) + s_] = DIAG_C*ssum;
        }
        const int b_ = brow>>12, s0 = brow&4095;
        __half* base = (__half*)Cv + (size_t)sel_t*NHR*DhD;
        #pragma unroll
        for (int it=0; it<8; ++it){
            const int idx = tid + it*256;          // 0..2047
            const int head = idx >> 10;
            const int rem = idx & 1023;
            const int row = rem >> 3, ch = rem & 7;
            uint4 v4 = *reinterpret_cast<const uint4*>(sm16q + row*136 + head*64 + ch*8);
            const int h_ = (cc0>>6) + head;
            *reinterpret_cast<uint4*>(base + ((((long long)(b_*Hh+h_))<<12) + s0 + row)*DhD + ch*8) = v4;
        }
    }
}

#define SMEM_H128x128 (2*(128+128)*36*4)                  // 73728
#define SMEM_H64x256  (2*(64+256)*36*4)                   // 92160
#define SMEM_H128x64  (2*(128+64)*36*4 + (Mm+128)*4)      // 55296 + 1536

// ================ ctx TN mma kernel, 4-way m split (BK=32, 3-stage) ====================
#define CTX_LDV 36
#define CTX_LDP 36
#define CTX_VW  (32*CTX_LDV)
#define CTX_PW  (32*CTX_LDP)
#define SMEM_CTX (3*(CTX_VW+CTX_PW)*4)     // 27648

__global__ void __launch_bounds__(256, 2)
ctx_mma(const __half* __restrict__ kpe, const __half* __restrict__ vh,
        const float* __restrict__ rowf,
        __half* __restrict__ ctxT, float* __restrict__ ksum)
{
    extern __shared__ uint32_t sh[];
    const uint32_t smb = smem_u32(sh);
    const uint32_t pbase = smb + (uint32_t)(3*CTX_VW)*4u;

    const int z = blockIdx.y;
    const int ntile = blockIdx.x;               // 0..3, 64 m-cols each
    const int tid = threadIdx.x, wid = tid>>5, lane = tid&31;
    const int warp_m = (wid & 3)*16;            // dh tile
    const int warp_n = (wid >> 2)*32;           // m tile
    const int g = lane>>2, t = lane&3;
    const int quad = lane>>3, r8 = lane&7;

    const __half* kpb = kpe + (long long)z*Ss*Mm + ntile*64;
    const __half* vhb = vh  + (long long)z*Ss*DhD;
    const float*  rfb = rowf + (long long)z*Ss;

    const float gmax = gmax_decode(g_gmax_u);
    const float epsr = EPSR_C;

    const uint32_t a_off0 = (uint32_t)((r8 + ((quad>>1)&1)*8)*CTX_LDV + (warp_m + (quad&1)*8)/2);
    const uint32_t b_off0 = (uint32_t)((r8 + (quad&1)*8)*CTX_LDP + (warp_n + (quad>>1)*8)/2);

    const int srow = tid >> 3;     // 0..31
    const int c8   = tid & 7;      // 8-half group

    float acc[4][4];
    #pragma unroll
    for (int j=0;j<4;j++)
        #pragma unroll
        for (int u=0;u<4;u++) acc[j][u]=0.f;
    float ks[8];
    #pragma unroll
    for (int j=0;j<8;j++) ks[j]=0.f;

    #define VISSUE(c) do{ \
        const uint32_t bV = smb + (uint32_t)(((c)%3)*CTX_VW)*4u; \
        cpa16(bV + (uint32_t)(srow*CTX_LDV + c8*4)*4u, \
              vhb + (long long)((c)*32 + srow)*DhD + c8*8); \
    }while(0)

    uint4 cur; float curf;
    cur  = *reinterpret_cast<const uint4*>(kpb + (long long)srow*Mm + c8*8);
    curf = rfb[srow];
    VISSUE(0); CP_COMMIT();
    VISSUE(1); CP_COMMIT();

    for (int i=0; i<Ss/32; ++i){
        {
            const float As = RATIO_C*__expf(curf - gmax);
            uint32_t rw[4] = {cur.x,cur.y,cur.z,cur.w};
            uint32_t ow[4];
            #pragma unroll
            for (int j=0;j<4;j++){
                float2 f = __half22float2(*reinterpret_cast<__half2*>(&rw[j]));
                f.x = fmaf(f.x, As, epsr);
                f.y = fmaf(f.y, As, epsr);
                __half2 h = __floats2half2_rn(f.x, f.y);
                float2 fr = __half22float2(h);
                ks[2*j]   += fr.x;
                ks[2*j+1] += fr.y;
                ow[j] = *reinterpret_cast<uint32_t*>(&h);
            }
            const uint32_t bP = pbase + (uint32_t)((i%3)*CTX_PW)*4u
                              + (uint32_t)(srow*CTX_LDP + c8*4)*4u;
            uint4 s0 = {ow[0],ow[1],ow[2],ow[3]};
            *reinterpret_cast<uint4*>((char*)sh + (bP - smb)) = s0;
        }
        CP_WAIT1();
        __syncthreads();
        if (i+2 < Ss/32) VISSUE(i+2);
        CP_COMMIT();
        if (i+1 < Ss/32){
            cur  = *reinterpret_cast<const uint4*>(kpb + (long long)((i+1)*32 + srow)*Mm + c8*8);
            curf = rfb[(i+1)*32 + srow];
        }

        const uint32_t vstg = smb + (uint32_t)((i%3)*CTX_VW)*4u;
        const uint32_t pstg = pbase + (uint32_t)((i%3)*CTX_PW)*4u;

        #pragma unroll
        for (int kk=0; kk<2; ++kk){
            uint32_t af[4], bf[4][2];
            LDSM4T(af[0],af[1],af[2],af[3],
                   vstg + (a_off0 + (uint32_t)(kk*16*CTX_LDV))*4u);
            #pragma unroll
            for (int pp2=0; pp2<2; ++pp2)
                LDSM4T(bf[2*pp2][0],bf[2*pp2][1],bf[2*pp2+1][0],bf[2*pp2+1][1],
                       pstg + (b_off0 + (uint32_t)(kk*16*CTX_LDP + pp2*8))*4u);
            #pragma unroll
            for (int nt=0; nt<4; ++nt)
                mma_f16(acc[nt], af, bf[nt]);
        }
    }
    #undef VISSUE

    const int dh0 = warp_m + g;
    const int dh1 = dh0 + 8;
    #pragma unroll
    for (int nt=0; nt<4; ++nt){
        const int col = ntile*64 + warp_n + nt*8 + 2*t;
        *reinterpret_cast<__half2*>(ctxT + (long long)z*DhD*Mm + (long long)dh0*Mm + col)
            = __floats2half2_rn(acc[nt][0], acc[nt][1]);
        *reinterpret_cast<__half2*>(ctxT + (long long)z*DhD*Mm + (long long)dh1*Mm + col)
            = __floats2half2_rn(acc[nt][2], acc[nt][3]);
    }

    __syncthreads();
    float* red = (float*)sh;                // [32][64]
    #pragma unroll
    for (int j=0;j<8;j++) red[srow*64 + c8*8 + j] = ks[j];
    __syncthreads();
    if (tid < 64){
        float s = 0.f;
        #pragma unroll
        for (int r=0;r<32;r++) s += red[r*64 + tid];
        ksum[z*Mm + ntile*64 + tid] = s;
    }
}

// ---------------- single setup kernel: all weight f2h + bias pack + gmax reset --------
__global__ void setup_kernel(const float* __restrict__ wq, const float* __restrict__ wk,
                             const float* __restrict__ wv, const float* __restrict__ wo,
                             const float* __restrict__ w1, const float* __restrict__ w2,
                             const float* __restrict__ proj,
                             const float* __restrict__ bq, const float* __restrict__ bk,
                             const float* __restrict__ bv)
{
    const long long i = (long long)blockIdx.x*256 + threadIdx.x;
    const long long Q = Dd*Dd/4;
    const long long W = (long long)FFH*Dd/4;
    const long long P = Mm*DhD/4;
    const long long T0 = 4*Q, T1 = T0 + 2*W + P, T2 = T1 + 3*Dd;
    if (i < T0){
        const int seg = (int)(i/Q), off = (int)(i - seg*Q);
        const float* s = (seg==0)?wq:(seg==1)?wk:(seg==2)?wv:wo;
        __half* d = (seg<3) ? (g_wqkvh + (size_t)seg*Dd*Dd) : g_woh;
        float4 v = reinterpret_cast<const float4*>(s)[off];
        __half2* o = reinterpret_cast<__half2*>(d) + 2*off;
        o[0] = __floats2half2_rn(v.x, v.y);
        o[1] = __floats2half2_rn(v.z, v.w);
    } else if (i < T1){
        long long j = i - T0;
        const float* s; __half* d; int off; float scale = 1.f;
        if (j < W)          { s = w1;   d = g_w1h;   off = (int)j; }
        else if (j < 2*W)   { s = w2;   d = g_w2h;   off = (int)(j - W); }
        else                { s = proj; d = g_projh; off = (int)(j - 2*W); scale = NORM_C; }
        float4 v = reinterpret_cast<const float4*>(s)[off];
        __half2* o = reinterpret_cast<__half2*>(d) + 2*off;
        o[0] = __floats2half2_rn(v.x*scale, v.y*scale);
        o[1] = __floats2half2_rn(v.z*scale, v.w*scale);
    } else if (i < T2){
        const int j = (int)(i - T1);
        const int sel = j/Dd, c = j - sel*Dd;
        g_bqkv[j] = sel==0 ? bq[c] : (sel==1 ? bk[c] : bv[c]);
    } else if (i == T2){
        g_gmax_u = 0u;
    }
}
#define SETUP_N (4LL*(Dd*Dd/4) + 2LL*((long long)FFH*Dd/4) + Mm*DhD/4 + 3*Dd + 1)

// ---------------- LayerNorm (row=768), half output ----------------
__global__ void ln_kernel(const float* __restrict__ x, const float* __restrict__ g,
                          const float* __restrict__ b, __half* __restrict__ out)
{
    const int row = blockIdx.x;
    const float* xr = x + (long long)row*Dd;
    float v[3]; float s=0.f, ss=0.f;
    #pragma unroll
    for (int i=0;i<3;i++){ v[i]=xr[threadIdx.x + i*256]; s+=v[i]; ss+=v[i]*v[i]; }
    #pragma unroll
    for (int o=16;o;o>>=1){ s+=__shfl_xor_sync(0xffffffffu,s,o); ss+=__shfl_xor_sync(0xffffffffu,ss,o); }
    __shared__ float rs_[8], rss_[8];
    const int lane = threadIdx.x & 31, w = threadIdx.x >> 5;
    if (lane==0){ rs_[w]=s; rss_[w]=ss; }
    __syncthreads();
    s=0.f; ss=0.f;
    #pragma unroll
    for (int i=0;i<8;i++){ s+=rs_[i]; ss+=rss_[i]; }
    const float mu  = s*(1.0f/Dd);
    const float var = ss*(1.0f/Dd) - mu*mu;
    const float rstd = rsqrtf(var + LN_EPS);
    __half* outr = out + (long long)row*Dd;
    #pragma unroll
    for (int i=0;i<3;i++){
        int c = threadIdx.x + i*256;
        outr[c] = __float2half((v[i]-mu)*rstd*g[c] + b[c]);
    }
}

// ---------------- host ----------------
extern "C" void kernel_launch(void* const* d_in, const int* in_sizes, int n_in,
                              void* d_out, int out_size)
{
    const float* x    = (const float*)d_in[0];
    const float* proj = (const float*)d_in[1];
    const float* wq   = (const float*)d_in[2];
    const float* bq   = (const float*)d_in[3];
    const float* wk   = (const float*)d_in[4];
    const float* bk   = (const float*)d_in[5];
    const float* wv   = (const float*)d_in[6];
    const float* bv   = (const float*)d_in[7];
    const float* wo   = (const float*)d_in[8];
    const float* bo   = (const float*)d_in[9];
    const float* ln1g = (const float*)d_in[10];
    const float* ln1b = (const float*)d_in[11];
    const float* ln2g = (const float*)d_in[12];
    const float* ln2b = (const float*)d_in[13];
    const float* w1   = (const float*)d_in[14];
    const float* b1   = (const float*)d_in[15];
    const float* w2   = (const float*)d_in[16];
    const float* b2   = (const float*)d_in[17];
    float* out = (float*)d_out;

    void *p;
    __half *wqkvh, *h1h, *qkvh, *qkph, *midh, *ctxTh, *attn2h, *woh, *w1h, *w2h, *projh;
    float *ddiag, *rowf, *x2, *ksum, *bqkv;
    cudaGetSymbolAddress(&p, g_wqkvh);  wqkvh  = (__half*)p;
    cudaGetSymbolAddress(&p, g_woh);    woh    = (__half*)p;
    cudaGetSymbolAddress(&p, g_w1h);    w1h    = (__half*)p;
    cudaGetSymbolAddress(&p, g_w2h);    w2h    = (__half*)p;
    cudaGetSymbolAddress(&p, g_projh);  projh  = (__half*)p;
    cudaGetSymbolAddress(&p, g_h1h);    h1h    = (__half*)p;
    cudaGetSymbolAddress(&p, g_qkvh);   qkvh   = (__half*)p;
    cudaGetSymbolAddress(&p, g_qkph);   qkph   = (__half*)p;
    cudaGetSymbolAddress(&p, g_midh);   midh   = (__half*)p;
    cudaGetSymbolAddress(&p, g_ctxTh);  ctxTh  = (__half*)p;
    cudaGetSymbolAddress(&p, g_attn2h); attn2h = (__half*)p;
    cudaGetSymbolAddress(&p, g_x2);     x2     = (float*)p;
    cudaGetSymbolAddress(&p, g_diag);   ddiag  = (float*)p;
    cudaGetSymbolAddress(&p, g_rowf);   rowf   = (float*)p;
    cudaGetSymbolAddress(&p, g_ksum);   ksum   = (float*)p;
    cudaGetSymbolAddress(&p, g_bqkv);   bqkv   = (float*)p;

    __half* qh = qkvh;
    __half* vh = qkvh + 2*(size_t)NHR*DhD;
    __half* qph = qkph;
    __half* kph = qkph + (size_t)NHR*Mm;

    cudaFuncSetAttribute(hgemm<128,128,EPI_QKV,true>,       cudaFuncAttributeMaxDynamicSharedMemorySize, SMEM_H128x128);
    cudaFuncSetAttribute(hgemm<64,256,EPI_FEAT,true>,       cudaFuncAttributeMaxDynamicSharedMemorySize, SMEM_H64x256);
    cudaFuncSetAttribute(hgemm<128,64,EPI_ATTN,true>,       cudaFuncAttributeMaxDynamicSharedMemorySize, SMEM_H128x64);
    cudaFuncSetAttribute(hgemm<128,128,EPI_BIAS_RES,false>, cudaFuncAttributeMaxDynamicSharedMemorySize, SMEM_H128x128);
    cudaFuncSetAttribute(hgemm<128,128,EPI_BIAS_GELU,true>, cudaFuncAttributeMaxDynamicSharedMemorySize, SMEM_H128x128);

    // fork: setup (weights) on s2 concurrent with LN1 on the main stream
    static cudaStream_t s2 = nullptr;
    static cudaEvent_t evf = nullptr, evj = nullptr;
    if (!s2){
        cudaStreamCreateWithFlags(&s2, cudaStreamNonBlocking);
        cudaEventCreateWithFlags(&evf, cudaEventDisableTiming);
        cudaEventCreateWithFlags(&evj, cudaEventDisableTiming);
    }
    cudaEventRecord(evf, 0);
    cudaStreamWaitEvent(s2, evf, 0);
    setup_kernel<<<(int)((SETUP_N + 255)/256), 256, 0, s2>>>(wq,wk,wv,wo,w1,w2,proj,bq,bk,bv);
    cudaEventRecord(evj, s2);
    ln_kernel<<<NROWS, 256>>>(x, ln1g, ln1b, h1h);
    cudaStreamWaitEvent(0, evj, 0);

    // fused QKV (N=2304) + fused diag (q,k), staged coalesced stores
    hgemm<128,128,EPI_QKV,true><<<dim3(18,128,1),256,SMEM_H128x128>>>(
        h1h,Dd,0, wqkvh,Dd,0, qkvh,DhD,0, NROWS,3*Dd,Dd, bqkv,nullptr,nullptr,0.f);

    // q+k features in ONE launch (z=0: q, z=1: k); GEMM + rowmax + exp, staged stores
    hgemm<64,256,EPI_FEAT,true><<<dim3(1,NHR/64,2),256,SMEM_H64x256>>>(
        qh,DhD,(long long)NHR*DhD, projh,DhD,0, qkph,Mm,(long long)NHR*Mm,
        NHR,Mm,DhD, nullptr,rowf,ddiag,1.f);

    // ctx (tensor mma, TN, 4-way m split) + fused ksum
    ctx_mma<<<dim3(4,NBH), 256, SMEM_CTX>>>(kph, vh, rowf, ctxTh, ksum);

    // attn = (qp @ ctx) / (qp . ksum)  [denominator fused], transpose -> attn2h [b,s,D]
    hgemm<128,64,EPI_ATTN,true><<<dim3(1,Ss/128,NBH),128,SMEM_H128x64>>>(
        qph,Mm,(long long)Ss*Mm, ctxTh,Mm,(long long)DhD*Mm, attn2h,DhD,0,
        Ss,DhD,Mm, nullptr,nullptr,ksum,0.f);

    // x2 = x + attn @ wo^T + bo (fp32)
    hgemm<128,128,EPI_BIAS_RES,false><<<dim3(6,128,1),256,SMEM_H128x128>>>(
        attn2h,Dd,0, woh,Dd,0, x2,Dd,0, NROWS,Dd,Dd, bo,x,nullptr,0.f);

    // LN2 -> half
    ln_kernel<<<NROWS, 256>>>(x2, ln2g, ln2b, h1h);

    // mid = gelu(h1 @ w1^T + b1) -> half
    hgemm<128,128,EPI_BIAS_GELU,true><<<dim3(FFH/128,128,1),256,SMEM_H128x128>>>(
        h1h,Dd,0, w1h,Dd,0, midh,FFH,0, NROWS,FFH,Dd, b1,nullptr,nullptr,0.f);

    // out = x2 + mid @ w2^T + b2 (fp32)
    hgemm<128,128,EPI_BIAS_RES,false><<<dim3(6,128,1),256,SMEM_H128x128>>>(
        midh,FFH,0, w2h,FFH,0, out,Dd,0, NROWS,Dd,FFH, b2,x2,nullptr,0.f);
}

// round 16
// speedup vs baseline: 1.0383x; 1.0000x over previous
#include <cuda_runtime.h>
#include <cuda_fp16.h>
#include <math.h>
#include <stdint.h>

// ---------------- problem constants ----------------
#define Bb   4
#define Ss   4096
#define Dd   768
#define Hh   12
#define Mm   256
#define DhD  64
#define NROWS (Bb*Ss)        // 16384
#define NBH   (Bb*Hh)        // 48
#define NHR   (NBH*Ss)       // 196608
#define FFH   (4*Dd)         // 3072

#define NORM_C   0.35355339059327373f
#define RATIO_C  0.0625f
#define DIAG_C   0.0625f
#define EPS_K    1e-4f
#define EPSR_C   (RATIO_C*EPS_K)
#define LN_EPS   1e-5f

// ---------------- scratch (device globals; allocation-free) ----------------
__device__ __half g_wqkvh[3*Dd*Dd];
__device__ float  g_bqkv[3*Dd];
__device__ __half g_woh[Dd*Dd];
__device__ __half g_w1h[FFH*Dd];
__device__ __half g_w2h[Dd*FFH];
__device__ __half g_projh[Mm*DhD];               // pre-scaled by NORM_C
__device__ __half g_h1h[NROWS*Dd];
__device__ __half g_qkvh[3*(size_t)NHR*DhD];      // q,k,v in [sel][b,h,s,dh]
__device__ __half g_qkph[2*(size_t)NHR*Mm];       // [qp | kp(exp(dd-rowmax))]
__device__ __half g_midh[(size_t)NROWS*FFH];
__device__ __half g_ctxTh[NBH*DhD*Mm];            // [bh][dh][m]
__device__ __half g_attn2h[(size_t)NROWS*Dd];     // [b,s,D]
__device__ float  g_x2[NROWS*Dd];
__device__ float  g_diag[2*NHR];                  // [q rows | k rows]
__device__ float  g_rowf[NHR];                    // rowmax(dd_k) - diag_k
__device__ float  g_ksum[NBH*Mm];
__device__ unsigned g_gmax_u;

// ---------------- epilogue modes ----------------
enum { EPI_BIAS_RES=1, EPI_BIAS_GELU=2, EPI_QKV=5, EPI_ATTN=8 };

__device__ __forceinline__ void cpa16(uint32_t smem_dst, const void* gsrc){
    asm volatile("cp.async.cg.shared.global [%0], [%1], 16;" :: "r"(smem_dst), "l"(gsrc));
}
#define CP_COMMIT() asm volatile("cp.async.commit_group;" ::: "memory")
#define CP_WAIT0()  asm volatile("cp.async.wait_group 0;" ::: "memory")
#define CP_WAIT1()  asm volatile("cp.async.wait_group 1;" ::: "memory")

__device__ __forceinline__ uint32_t smem_u32(const void* p){
    uint32_t a;
    asm("{ .reg .u64 t; cvta.to.shared.u64 t, %1; cvt.u32.u64 %0, t; }" : "=r"(a) : "l"(p));
    return a;
}

__device__ __forceinline__ void mma_f16(float* d, const uint32_t* a, const uint32_t* b){
    asm volatile("mma.sync.aligned.m16n8k16.row.col.f32.f16.f16.f32 "
        "{%0,%1,%2,%3}, {%4,%5,%6,%7}, {%8,%9}, {%0,%1,%2,%3};"
        : "+f"(d[0]),"+f"(d[1]),"+f"(d[2]),"+f"(d[3])
        : "r"(a[0]),"r"(a[1]),"r"(a[2]),"r"(a[3]), "r"(b[0]),"r"(b[1]));
}
#define LDSM4(r0,r1,r2,r3,addr) \
    asm volatile("ldmatrix.sync.aligned.m8n8.x4.shared.b16 {%0,%1,%2,%3}, [%4];" \
        : "=r"(r0),"=r"(r1),"=r"(r2),"=r"(r3) : "r"(addr))
#define LDSM4T(r0,r1,r2,r3,addr) \
    asm volatile("ldmatrix.sync.aligned.m8n8.x4.trans.shared.b16 {%0,%1,%2,%3}, [%4];" \
        : "=r"(r0),"=r"(r1),"=r"(r2),"=r"(r3) : "r"(addr))

__device__ __forceinline__ float gmax_decode(unsigned u){
    return (u & 0x80000000u) ? __uint_as_float(u ^ 0x80000000u) : __uint_as_float(~u);
}

// ================= fp16 NT GEMM: mma.sync m16n8k16, BK=64, 2-stage cp.async ============
// EPI_ATTN: rowscale = g_ksum base; denominator fused.
template<int BM,int BN,int EPI,bool OUTH>
__global__ void __launch_bounds__(32*(BM/64)*(BN/32), (BM==128 && BN==64) ? 3 : 2)
hgemm(const __half* __restrict__ A, int lda, long long strA,
      const __half* __restrict__ B, int ldb, long long strB,
      void* __restrict__ Cv, int ldc, long long strC,
      int M, int N, int K,
      const float* __restrict__ bias,
      const float* __restrict__ res,
      const float* __restrict__ rowscale,
      float alpha)
{
    constexpr int WY = BM/64, WX = BN/32, THREADS = 32*WY*WX;
    constexpr int LDKW = 36;
    constexpr int AW = BM*LDKW;
    constexpr int SW = (BM+BN)*LDKW;
    constexpr int ALD = (BM*8)/THREADS;
    constexpr int BLD = (BN*8)/THREADS;

    extern __shared__ uint32_t sh[];
    const uint32_t smb = smem_u32(sh);

    const int z = blockIdx.z;
    A += (long long)z*strA;  B += (long long)z*strB;
    float*  Cf = (float*)Cv  + (long long)z*strC;
    __half* Ch = (__half*)Cv + (long long)z*strC;

    const int brow = blockIdx.y*BM;
    const int bcol = blockIdx.x*BN;
    const int tid  = threadIdx.x;
    const int wid  = tid >> 5;
    const int lane = tid & 31;
    const int wx   = wid % WX, wy = wid / WX;
    const int warp_m = wy*64, warp_n = wx*32;
    const int g = lane >> 2, t = lane & 3;

    const uint32_t aoff = (uint32_t)(((warp_m + (lane&15))*LDKW + (lane>>4)*4))*4u;
    const uint32_t boff = (uint32_t)((AW + (warp_n + (lane>>4)*8 + (lane&7))*LDKW + ((lane>>3)&1)*4))*4u;

    float acc[4][4][4];
    #pragma unroll
    for (int i=0;i<4;i++)
        #pragma unroll
        for (int j=0;j<4;j++)
            #pragma unroll
            for (int u=0;u<4;u++) acc[i][j][u]=0.f;

    float den = 0.f;
    if (EPI==EPI_ATTN){
        float* sks = (float*)(sh + 2*SW);
        #pragma unroll
        for (int l=0; l<(Mm+THREADS-1)/THREADS; ++l){
            const int idx = tid + l*THREADS;
            if (idx < Mm) sks[idx] = rowscale[(long long)z*Mm + idx];
        }
    }

    const int nc = K >> 6;

    #define HISSUE(chunk) do{                                                  \
        const uint32_t bA_ = smb + (uint32_t)(((chunk)&1)*SW)*4u;              \
        const uint32_t bB_ = bA_ + (uint32_t)AW*4u;                            \
        const __half* Ap_ = A + (long long)brow*lda + (chunk)*64;              \
        const __half* Bp_ = B + (long long)bcol*ldb + (chunk)*64;              \
        _Pragma("unroll")                                                      \
        for (int l=0;l<ALD;l++){                                               \
            const int idx = tid + l*THREADS, r = idx>>3, c4 = idx&7;           \
            cpa16(bA_ + (uint32_t)(r*LDKW + c4*4)*4u,                          \
                  Ap_ + (long long)r*lda + c4*8);                              \
        }                                                                      \
        _Pragma("unroll")                                                      \
        for (int l=0;l<BLD;l++){                                               \
            const int idx = tid + l*THREADS, r = idx>>3, c4 = idx&7;           \
            cpa16(bB_ + (uint32_t)(r*LDKW + c4*4)*4u,                          \
                  Bp_ + (long long)r*ldb + c4*8);                              \
        }                                                                      \
    }while(0)

    HISSUE(0);
    CP_COMMIT();

    for (int i=0; i<nc; ++i){
        if (i+1 < nc){ HISSUE(i+1); CP_COMMIT(); CP_WAIT1(); }
        else         { CP_WAIT0(); }
        __syncthreads();

        const uint32_t stg = smb + (uint32_t)((i&1)*SW)*4u;

        if (EPI==EPI_ATTN){
            const float* sks = (const float*)(sh + 2*SW) + i*64;
            const uint4* arow4 = reinterpret_cast<const uint4*>(sh + (i&1)*SW + tid*LDKW);
            #pragma unroll
            for (int j=0;j<8;j++){
                uint4 w4 = arow4[j];
                float2 f0 = __half22float2(*reinterpret_cast<__half2*>(&w4.x));
                float2 f1 = __half22float2(*reinterpret_cast<__half2*>(&w4.y));
                float2 f2 = __half22float2(*reinterpret_cast<__half2*>(&w4.z));
                float2 f3 = __half22float2(*reinterpret_cast<__half2*>(&w4.w));
                den += f0.x*sks[8*j]   + f0.y*sks[8*j+1]
                     + f1.x*sks[8*j+2] + f1.y*sks[8*j+3]
                     + f2.x*sks[8*j+4] + f2.y*sks[8*j+5]
                     + f3.x*sks[8*j+6] + f3.y*sks[8*j+7];
            }
        }

        #pragma unroll
        for (int kk=0; kk<4; ++kk){
            uint32_t af[4][4], bf[4][2];
            #pragma unroll
            for (int mt=0; mt<4; ++mt)
                LDSM4(af[mt][0],af[mt][1],af[mt][2],af[mt][3],
                      stg + aoff + (uint32_t)((mt*16*LDKW + kk*8))*4u);
            LDSM4(bf[0][0],bf[0][1],bf[1][0],bf[1][1],
                  stg + boff + (uint32_t)(kk*8)*4u);
            LDSM4(bf[2][0],bf[2][1],bf[3][0],bf[3][1],
                  stg + boff + (uint32_t)((16*LDKW + kk*8))*4u);
            #pragma unroll
            for (int mt=0; mt<4; ++mt)
                #pragma unroll
                for (int nt=0; nt<4; ++nt)
                    mma_f16(acc[mt][nt], af[mt], bf[nt]);
        }
        __syncthreads();
    }
    #undef HISSUE

    float* sden = nullptr;
    if (EPI==EPI_ATTN){
        sden = (float*)(sh + 2*SW) + Mm;
        sden[tid] = 1.0f/den;
        __syncthreads();
    }

    float sq[4][2];
    if (EPI==EPI_QKV){
        #pragma unroll
        for (int mt=0; mt<4; ++mt){ sq[mt][0]=0.f; sq[mt][1]=0.f; }
    }
    __half* sm16q = (__half*)sh;               // QKV stage: [128][136]

    #pragma unroll
    for (int mt=0; mt<4; ++mt){
        const int r0 = brow + warp_m + mt*16 + g;
        const int r1 = r0 + 8;
        float rs0 = 1.f, rs1 = 1.f;
        if (EPI==EPI_ATTN){
            rs0 = sden[warp_m + mt*16 + g];
            rs1 = sden[warp_m + mt*16 + 8 + g];
        }
        #pragma unroll
        for (int nt=0; nt<4; ++nt){
            const int c0 = bcol + warp_n + nt*8 + 2*t;
            float v00 = acc[mt][nt][0], v01 = acc[mt][nt][1];
            float v10 = acc[mt][nt][2], v11 = acc[mt][nt][3];
            if (EPI==EPI_BIAS_RES || EPI==EPI_BIAS_GELU || EPI==EPI_QKV){
                const float b0 = bias[c0], b1 = bias[c0+1];
                v00 += b0; v01 += b1; v10 += b0; v11 += b1;
            }
            if (EPI==EPI_BIAS_RES){
                v00 += res[(long long)r0*ldc + c0];   v01 += res[(long long)r0*ldc + c0+1];
                v10 += res[(long long)r1*ldc + c0];   v11 += res[(long long)r1*ldc + c0+1];
            }
            if (EPI==EPI_BIAS_GELU){
                v00 = 0.5f*v00*(1.0f+erff(v00*0.70710678118654752f));
                v01 = 0.5f*v01*(1.0f+erff(v01*0.70710678118654752f));
                v10 = 0.5f*v10*(1.0f+erff(v10*0.70710678118654752f));
                v11 = 0.5f*v11*(1.0f+erff(v11*0.70710678118654752f));
            }
            if (EPI==EPI_ATTN){ v00*=rs0; v01*=rs0; v10*=rs1; v11*=rs1; }

            if (EPI==EPI_QKV){
                sq[mt][0] += v00*v00 + v01*v01;
                sq[mt][1] += v10*v10 + v11*v11;
                const int rl0 = warp_m + mt*16 + g;
                const int cl  = warp_n + nt*8 + 2*t;
                *reinterpret_cast<__half2*>(sm16q + rl0*136 + cl)     = __floats2half2_rn(v00,v01);
                *reinterpret_cast<__half2*>(sm16q + (rl0+8)*136 + cl) = __floats2half2_rn(v10,v11);
            } else if (EPI==EPI_ATTN){
                const int bb = z/Hh, hh = z - (z/Hh)*Hh;
                __half* base = (__half*)Cv;
                const long long o0 = ((long long)(bb*Ss + r0))*Dd + hh*64 + c0;
                const long long o1 = ((long long)(bb*Ss + r1))*Dd + hh*64 + c0;
                *reinterpret_cast<__half2*>(base + o0) = __floats2half2_rn(v00,v01);
                *reinterpret_cast<__half2*>(base + o1) = __floats2half2_rn(v10,v11);
            } else if (OUTH){
                *reinterpret_cast<__half2*>(Ch + (long long)r0*ldc + c0) = __floats2half2_rn(v00,v01);
                *reinterpret_cast<__half2*>(Ch + (long long)r1*ldc + c0) = __floats2half2_rn(v10,v11);
            } else {
                float2 o0; o0.x=v00; o0.y=v01;
                float2 o1; o1.x=v10; o1.y=v11;
                *reinterpret_cast<float2*>(Cf + (long long)r0*ldc + c0) = o0;
                *reinterpret_cast<float2*>(Cf + (long long)r1*ldc + c0) = o1;
            }
        }
    }

    if (EPI==EPI_QKV){
        const int sel_t = bcol/Dd;
        const int cc0   = bcol - sel_t*Dd;
        float* red = (float*)(sh + 8704);
        #pragma unroll
        for (int mt=0; mt<4; ++mt){
            #pragma unroll
            for (int j=0;j<2;j++){
                float v = sq[mt][j];
                v += __shfl_xor_sync(0xffffffffu, v, 1);
                v += __shfl_xor_sync(0xffffffffu, v, 2);
                if (t==0) red[(warp_m + mt*16 + j*8 + g)*4 + wx] = v;
            }
        }
        __syncthreads();
        if (sel_t < 2){
            const int row  = tid >> 1;
            const int head = tid & 1;
            const float ssum = red[row*4 + 2*head] + red[row*4 + 2*head + 1];
            const int gr = brow + row;
            const int b_ = gr>>12, s_ = gr&4095;
            const int h_ = (cc0>>6) + head;
            g_diag[(size_t)sel_t*NHR + (((long long)(b_*Hh+h_))<<12) + s_] = DIAG_C*ssum;
        }
        const int b_ = brow>>12, s0 = brow&4095;
        __half* base = (__half*)Cv + (size_t)sel_t*NHR*DhD;
        #pragma unroll
        for (int it=0; it<8; ++it){
            const int idx = tid + it*256;
            const int head = idx >> 10;
            const int rem = idx & 1023;
            const int row = rem >> 3, ch = rem & 7;
            uint4 v4 = *reinterpret_cast<const uint4*>(sm16q + row*136 + head*64 + ch*8);
            const int h_ = (cc0>>6) + head;
            *reinterpret_cast<uint4*>(base + ((((long long)(b_*Hh+h_))<<12) + s0 + row)*DhD + ch*8) = v4;
        }
    }
}

#define SMEM_H128x128 (2*(128+128)*36*4)                  // 73728
#define SMEM_H128x64  (2*(128+64)*36*4 + (Mm+128)*4)      // 55296 + 1536

// ================ dedicated FEAT kernel: 2 A-tiles per CTA, B staged once =============
// z=0: q features RATIO*(exp(dd-diag-rowmax)+eps); z=1: k features exp(dd-rowmax),
// rowf = rowmax - diag, gmax atomic. A = q|k [128 rows], B = proj (pre-scaled).
#define F_LDKW 36
#define F_AW   (64*F_LDKW)          // words per A stage (2304)
#define F_BOFF (2*F_AW)             // B at word 4608
#define F_BW   (256*F_LDKW)         // 9216 words
#define F_EPW  (F_BOFF + F_BW)      // epilogue region start (word 13824)
#define SMEM_FEAT (F_EPW*4 + 64*264*2 + 64*8*4)   // 55296+33792+2048 = 91136

__global__ void __launch_bounds__(256, 2)
feat_kernel(const __half* __restrict__ qk, const __half* __restrict__ projh,
            __half* __restrict__ qkp, const float* __restrict__ ddiag,
            float* __restrict__ rowf)
{
    extern __shared__ uint32_t sh[];
    const uint32_t smb = smem_u32(sh);

    const int z = blockIdx.y;
    const int brow0 = blockIdx.x*128;
    const __half* A = qk + (size_t)z*NHR*DhD;
    __half* Ch = qkp + (size_t)z*NHR*Mm;

    const int tid = threadIdx.x, wid = tid>>5, lane = tid&31;
    const int warp_n = wid*32;
    const int g = lane>>2, t = lane&3;

    const uint32_t aoff = (uint32_t)(((lane&15)*F_LDKW + (lane>>4)*4))*4u;
    const uint32_t boff = (uint32_t)((F_BOFF + (warp_n + (lane>>4)*8 + (lane&7))*F_LDKW + ((lane>>3)&1)*4))*4u;

    __half* smE = (__half*)sh + F_EPW*2;                       // [64][264]
    float*  red = (float*)((char*)sh + F_EPW*4 + 64*264*2);    // [64][8]

    // group 1: B (proj) + A0;  group 2: A1
    #pragma unroll
    for (int l=0;l<8;l++){
        const int idx = tid + l*256, r = idx>>3, c4 = idx&7;
        cpa16(smb + (uint32_t)(F_BOFF + r*F_LDKW + c4*4)*4u, projh + (long long)r*DhD + c4*8);
    }
    #pragma unroll
    for (int l=0;l<2;l++){
        const int idx = tid + l*256, r = idx>>3, c4 = idx&7;
        cpa16(smb + (uint32_t)(r*F_LDKW + c4*4)*4u, A + (long long)(brow0+r)*DhD + c4*8);
    }
    CP_COMMIT();
    #pragma unroll
    for (int l=0;l<2;l++){
        const int idx = tid + l*256, r = idx>>3, c4 = idx&7;
        cpa16(smb + (uint32_t)(F_AW + r*F_LDKW + c4*4)*4u, A + (long long)(brow0+64+r)*DhD + c4*8);
    }
    CP_COMMIT();
    CP_WAIT1();
    __syncthreads();

    #pragma unroll
    for (int rb=0; rb<2; ++rb){
        if (rb==1){ CP_WAIT0(); __syncthreads(); }
        const uint32_t stg = smb + (uint32_t)(rb*F_AW)*4u;

        float acc[4][4][4];
        #pragma unroll
        for (int i=0;i<4;i++)
            #pragma unroll
            for (int j=0;j<4;j++)
                #pragma unroll
                for (int u=0;u<4;u++) acc[i][j][u]=0.f;

        #pragma unroll
        for (int kk=0; kk<4; ++kk){
            uint32_t af[4][4], bf[4][2];
            #pragma unroll
            for (int mt=0; mt<4; ++mt)
                LDSM4(af[mt][0],af[mt][1],af[mt][2],af[mt][3],
                      stg + aoff + (uint32_t)((mt*16*F_LDKW + kk*8))*4u);
            LDSM4(bf[0][0],bf[0][1],bf[1][0],bf[1][1],
                  smb + boff + (uint32_t)(kk*8)*4u);
            LDSM4(bf[2][0],bf[2][1],bf[3][0],bf[3][1],
                  smb + boff + (uint32_t)((16*F_LDKW + kk*8))*4u);
            #pragma unroll
            for (int mt=0; mt<4; ++mt)
                #pragma unroll
                for (int nt=0; nt<4; ++nt)
                    mma_f16(acc[mt][nt], af[mt], bf[nt]);
        }

        // ---- epilogue for rows brow0 + rb*64 ----
        const int brow = brow0 + rb*64;
        float mxs[4][2];
        #pragma unroll
        for (int mt=0; mt<4; ++mt){
            float m0=-3.402823466e38f, m1=m0;
            #pragma unroll
            for (int nt=0; nt<4; ++nt){
                m0 = fmaxf(m0, fmaxf(acc[mt][nt][0], acc[mt][nt][1]));
                m1 = fmaxf(m1, fmaxf(acc[mt][nt][2], acc[mt][nt][3]));
            }
            m0 = fmaxf(m0, __shfl_xor_sync(0xffffffffu,m0,1));
            m0 = fmaxf(m0, __shfl_xor_sync(0xffffffffu,m0,2));
            m1 = fmaxf(m1, __shfl_xor_sync(0xffffffffu,m1,1));
            m1 = fmaxf(m1, __shfl_xor_sync(0xffffffffu,m1,2));
            mxs[mt][0]=m0; mxs[mt][1]=m1;
        }
        __syncthreads();
        if (t==0){
            #pragma unroll
            for (int mt=0; mt<4; ++mt){
                red[(mt*16+g)*8 + wid]   = mxs[mt][0];
                red[(mt*16+8+g)*8 + wid] = mxs[mt][1];
            }
        }
        __syncthreads();
        float dd0[4], dd1[4];
        #pragma unroll
        for (int mt=0; mt<4; ++mt){
            const int grow = brow + mt*16 + g;
            float mx0 = red[(mt*16+g)*8], mx1 = red[(mt*16+8+g)*8];
            #pragma unroll
            for (int w=1; w<8; ++w){
                mx0 = fmaxf(mx0, red[(mt*16+g)*8+w]);
                mx1 = fmaxf(mx1, red[(mt*16+8+g)*8+w]);
            }
            mxs[mt][0]=mx0; mxs[mt][1]=mx1;
            if (z==0){ dd0[mt] = ddiag[grow] + mx0; dd1[mt] = ddiag[grow+8] + mx1; }
            else     { dd0[mt] = mx0;               dd1[mt] = mx1; }
            if (z==1 && wid==0 && t==0){
                rowf[grow]   = mx0 - ddiag[(long long)NHR + grow];
                rowf[grow+8] = mx1 - ddiag[(long long)NHR + grow+8];
            }
        }
        if (z==1 && wid==0){
            float bm = fmaxf(fmaxf(mxs[0][0],mxs[0][1]), fmaxf(mxs[1][0],mxs[1][1]));
            bm = fmaxf(bm, fmaxf(fmaxf(mxs[2][0],mxs[2][1]), fmaxf(mxs[3][0],mxs[3][1])));
            #pragma unroll
            for (int o=16;o;o>>=1) bm = fmaxf(bm, __shfl_xor_sync(0xffffffffu,bm,o));
            if (lane==0){
                unsigned b = __float_as_uint(bm);
                unsigned u = (b & 0x80000000u) ? ~b : (b | 0x80000000u);
                atomicMax(&g_gmax_u, u);
            }
        }
        __syncthreads();
        #pragma unroll
        for (int mt=0; mt<4; ++mt){
            #pragma unroll
            for (int nt=0; nt<4; ++nt){
                const int c0 = warp_n + nt*8 + 2*t;
                __half2 o0, o1;
                if (z==0){
                    o0 = __floats2half2_rn(fmaf(__expf(acc[mt][nt][0]-dd0[mt]), RATIO_C, EPSR_C),
                                           fmaf(__expf(acc[mt][nt][1]-dd0[mt]), RATIO_C, EPSR_C));
                    o1 = __floats2half2_rn(fmaf(__expf(acc[mt][nt][2]-dd1[mt]), RATIO_C, EPSR_C),
                                           fmaf(__expf(acc[mt][nt][3]-dd1[mt]), RATIO_C, EPSR_C));
                } else {
                    o0 = __floats2half2_rn(__expf(acc[mt][nt][0]-dd0[mt]), __expf(acc[mt][nt][1]-dd0[mt]));
                    o1 = __floats2half2_rn(__expf(acc[mt][nt][2]-dd1[mt]), __expf(acc[mt][nt][3]-dd1[mt]));
                }
                *reinterpret_cast<__half2*>(smE + (mt*16+g)*264 + c0)   = o0;
                *reinterpret_cast<__half2*>(smE + (mt*16+8+g)*264 + c0) = o1;
            }
        }
        __syncthreads();
        #pragma unroll
        for (int it=0; it<8; ++it){
            const int idx = tid + it*256;
            const int row = idx >> 5, cc = idx & 31;
            uint4 v4 = *reinterpret_cast<const uint4*>(smE + row*264 + cc*8);
            *reinterpret_cast<uint4*>(Ch + (long long)(brow+row)*Mm + cc*8) = v4;
        }
    }
}

// ================ ctx TN mma kernel, 4-way m split (BK=32, 3-stage) ====================
#define CTX_LDV 36
#define CTX_LDP 36
#define CTX_VW  (32*CTX_LDV)
#define CTX_PW  (32*CTX_LDP)
#define SMEM_CTX (3*(CTX_VW+CTX_PW)*4)     // 27648

__global__ void __launch_bounds__(256, 2)
ctx_mma(const __half* __restrict__ kpe, const __half* __restrict__ vh,
        const float* __restrict__ rowf,
        __half* __restrict__ ctxT, float* __restrict__ ksum)
{
    extern __shared__ uint32_t sh[];
    const uint32_t smb = smem_u32(sh);
    const uint32_t pbase = smb + (uint32_t)(3*CTX_VW)*4u;

    const int z = blockIdx.y;
    const int ntile = blockIdx.x;
    const int tid = threadIdx.x, wid = tid>>5, lane = tid&31;
    const int warp_m = (wid & 3)*16;
    const int warp_n = (wid >> 2)*32;
    const int g = lane>>2, t = lane&3;
    const int quad = lane>>3, r8 = lane&7;

    const __half* kpb = kpe + (long long)z*Ss*Mm + ntile*64;
    const __half* vhb = vh  + (long long)z*Ss*DhD;
    const float*  rfb = rowf + (long long)z*Ss;

    const float gmax = gmax_decode(g_gmax_u);
    const float epsr = EPSR_C;

    const uint32_t a_off0 = (uint32_t)((r8 + ((quad>>1)&1)*8)*CTX_LDV + (warp_m + (quad&1)*8)/2);
    const uint32_t b_off0 = (uint32_t)((r8 + (quad&1)*8)*CTX_LDP + (warp_n + (quad>>1)*8)/2);

    const int srow = tid >> 3;
    const int c8   = tid & 7;

    float acc[4][4];
    #pragma unroll
    for (int j=0;j<4;j++)
        #pragma unroll
        for (int u=0;u<4;u++) acc[j][u]=0.f;
    float ks[8];
    #pragma unroll
    for (int j=0;j<8;j++) ks[j]=0.f;

    #define VISSUE(c) do{ \
        const uint32_t bV = smb + (uint32_t)(((c)%3)*CTX_VW)*4u; \
        cpa16(bV + (uint32_t)(srow*CTX_LDV + c8*4)*4u, \
              vhb + (long long)((c)*32 + srow)*DhD + c8*8); \
    }while(0)

    uint4 cur; float curf;
    cur  = *reinterpret_cast<const uint4*>(kpb + (long long)srow*Mm + c8*8);
    curf = rfb[srow];
    VISSUE(0); CP_COMMIT();
    VISSUE(1); CP_COMMIT();

    for (int i=0; i<Ss/32; ++i){
        {
            const float As = RATIO_C*__expf(curf - gmax);
            uint32_t rw[4] = {cur.x,cur.y,cur.z,cur.w};
            uint32_t ow[4];
            #pragma unroll
            for (int j=0;j<4;j++){
                float2 f = __half22float2(*reinterpret_cast<__half2*>(&rw[j]));
                f.x = fmaf(f.x, As, epsr);
                f.y = fmaf(f.y, As, epsr);
                __half2 h = __floats2half2_rn(f.x, f.y);
                float2 fr = __half22float2(h);
                ks[2*j]   += fr.x;
                ks[2*j+1] += fr.y;
                ow[j] = *reinterpret_cast<uint32_t*>(&h);
            }
            const uint32_t bP = pbase + (uint32_t)((i%3)*CTX_PW)*4u
                              + (uint32_t)(srow*CTX_LDP + c8*4)*4u;
            uint4 s0 = {ow[0],ow[1],ow[2],ow[3]};
            *reinterpret_cast<uint4*>((char*)sh + (bP - smb)) = s0;
        }
        CP_WAIT1();
        __syncthreads();
        if (i+2 < Ss/32) VISSUE(i+2);
        CP_COMMIT();
        if (i+1 < Ss/32){
            cur  = *reinterpret_cast<const uint4*>(kpb + (long long)((i+1)*32 + srow)*Mm + c8*8);
            curf = rfb[(i+1)*32 + srow];
        }

        const uint32_t vstg = smb + (uint32_t)((i%3)*CTX_VW)*4u;
        const uint32_t pstg = pbase + (uint32_t)((i%3)*CTX_PW)*4u;

        #pragma unroll
        for (int kk=0; kk<2; ++kk){
            uint32_t af[4], bf[4][2];
            LDSM4T(af[0],af[1],af[2],af[3],
                   vstg + (a_off0 + (uint32_t)(kk*16*CTX_LDV))*4u);
            #pragma unroll
            for (int pp2=0; pp2<2; ++pp2)
                LDSM4T(bf[2*pp2][0],bf[2*pp2][1],bf[2*pp2+1][0],bf[2*pp2+1][1],
                       pstg + (b_off0 + (uint32_t)(kk*16*CTX_LDP + pp2*8))*4u);
            #pragma unroll
            for (int nt=0; nt<4; ++nt)
                mma_f16(acc[nt], af, bf[nt]);
        }
    }
    #undef VISSUE

    const int dh0 = warp_m + g;
    const int dh1 = dh0 + 8;
    #pragma unroll
    for (int nt=0; nt<4; ++nt){
        const int col = ntile*64 + warp_n + nt*8 + 2*t;
        *reinterpret_cast<__half2*>(ctxT + (long long)z*DhD*Mm + (long long)dh0*Mm + col)
            = __floats2half2_rn(acc[nt][0], acc[nt][1]);
        *reinterpret_cast<__half2*>(ctxT + (long long)z*DhD*Mm + (long long)dh1*Mm + col)
            = __floats2half2_rn(acc[nt][2], acc[nt][3]);
    }

    __syncthreads();
    float* red = (float*)sh;
    #pragma unroll
    for (int j=0;j<8;j++) red[srow*64 + c8*8 + j] = ks[j];
    __syncthreads();
    if (tid < 64){
        float s = 0.f;
        #pragma unroll
        for (int r=0;r<32;r++) s += red[r*64 + tid];
        ksum[z*Mm + ntile*64 + tid] = s;
    }
}

// ---------------- single setup kernel: all weight f2h + bias pack + gmax reset --------
__global__ void setup_kernel(const float* __restrict__ wq, const float* __restrict__ wk,
                             const float* __restrict__ wv, const float* __restrict__ wo,
                             const float* __restrict__ w1, const float* __restrict__ w2,
                             const float* __restrict__ proj,
                             const float* __restrict__ bq, const float* __restrict__ bk,
                             const float* __restrict__ bv)
{
    const long long i = (long long)blockIdx.x*256 + threadIdx.x;
    const long long Q = Dd*Dd/4;
    const long long W = (long long)FFH*Dd/4;
    const long long P = Mm*DhD/4;
    const long long T0 = 4*Q, T1 = T0 + 2*W + P, T2 = T1 + 3*Dd;
    if (i < T0){
        const int seg = (int)(i/Q), off = (int)(i - seg*Q);
        const float* s = (seg==0)?wq:(seg==1)?wk:(seg==2)?wv:wo;
        __half* d = (seg<3) ? (g_wqkvh + (size_t)seg*Dd*Dd) : g_woh;
        float4 v = reinterpret_cast<const float4*>(s)[off];
        __half2* o = reinterpret_cast<__half2*>(d) + 2*off;
        o[0] = __floats2half2_rn(v.x, v.y);
        o[1] = __floats2half2_rn(v.z, v.w);
    } else if (i < T1){
        long long j = i - T0;
        const float* s; __half* d; int off; float scale = 1.f;
        if (j < W)          { s = w1;   d = g_w1h;   off = (int)j; }
        else if (j < 2*W)   { s = w2;   d = g_w2h;   off = (int)(j - W); }
        else                { s = proj; d = g_projh; off = (int)(j - 2*W); scale = NORM_C; }
        float4 v = reinterpret_cast<const float4*>(s)[off];
        __half2* o = reinterpret_cast<__half2*>(d) + 2*off;
        o[0] = __floats2half2_rn(v.x*scale, v.y*scale);
        o[1] = __floats2half2_rn(v.z*scale, v.w*scale);
    } else if (i < T2){
        const int j = (int)(i - T1);
        const int sel = j/Dd, c = j - sel*Dd;
        g_bqkv[j] = sel==0 ? bq[c] : (sel==1 ? bk[c] : bv[c]);
    } else if (i == T2){
        g_gmax_u = 0u;
    }
}
#define SETUP_N (4LL*(Dd*Dd/4) + 2LL*((long long)FFH*Dd/4) + Mm*DhD/4 + 3*Dd + 1)

// ---------------- LayerNorm (row=768), half output ----------------
__global__ void ln_kernel(const float* __restrict__ x, const float* __restrict__ g,
                          const float* __restrict__ b, __half* __restrict__ out)
{
    const int row = blockIdx.x;
    const float* xr = x + (long long)row*Dd;
    float v[3]; float s=0.f, ss=0.f;
    #pragma unroll
    for (int i=0;i<3;i++){ v[i]=xr[threadIdx.x + i*256]; s+=v[i]; ss+=v[i]*v[i]; }
    #pragma unroll
    for (int o=16;o;o>>=1){ s+=__shfl_xor_sync(0xffffffffu,s,o); ss+=__shfl_xor_sync(0xffffffffu,ss,o); }
    __shared__ float rs_[8], rss_[8];
    const int lane = threadIdx.x & 31, w = threadIdx.x >> 5;
    if (lane==0){ rs_[w]=s; rss_[w]=ss; }
    __syncthreads();
    s=0.f; ss=0.f;
    #pragma unroll
    for (int i=0;i<8;i++){ s+=rs_[i]; ss+=rss_[i]; }
    const float mu  = s*(1.0f/Dd);
    const float var = ss*(1.0f/Dd) - mu*mu;
    const float rstd = rsqrtf(var + LN_EPS);
    __half* outr = out + (long long)row*Dd;
    #pragma unroll
    for (int i=0;i<3;i++){
        int c = threadIdx.x + i*256;
        outr[c] = __float2half((v[i]-mu)*rstd*g[c] + b[c]);
    }
}

// ---------------- host ----------------
extern "C" void kernel_launch(void* const* d_in, const int* in_sizes, int n_in,
                              void* d_out, int out_size)
{
    const float* x    = (const float*)d_in[0];
    const float* proj = (const float*)d_in[1];
    const float* wq   = (const float*)d_in[2];
    const float* bq   = (const float*)d_in[3];
    const float* wk   = (const float*)d_in[4];
    const float* bk   = (const float*)d_in[5];
    const float* wv   = (const float*)d_in[6];
    const float* bv   = (const float*)d_in[7];
    const float* wo   = (const float*)d_in[8];
    const float* bo   = (const float*)d_in[9];
    const float* ln1g = (const float*)d_in[10];
    const float* ln1b = (const float*)d_in[11];
    const float* ln2g = (const float*)d_in[12];
    const float* ln2b = (const float*)d_in[13];
    const float* w1   = (const float*)d_in[14];
    const float* b1   = (const float*)d_in[15];
    const float* w2   = (const float*)d_in[16];
    const float* b2   = (const float*)d_in[17];
    float* out = (float*)d_out;

    void *p;
    __half *wqkvh, *h1h, *qkvh, *qkph, *midh, *ctxTh, *attn2h, *woh, *w1h, *w2h, *projh;
    float *ddiag, *rowf, *x2, *ksum, *bqkv;
    cudaGetSymbolAddress(&p, g_wqkvh);  wqkvh  = (__half*)p;
    cudaGetSymbolAddress(&p, g_woh);    woh    = (__half*)p;
    cudaGetSymbolAddress(&p, g_w1h);    w1h    = (__half*)p;
    cudaGetSymbolAddress(&p, g_w2h);    w2h    = (__half*)p;
    cudaGetSymbolAddress(&p, g_projh);  projh  = (__half*)p;
    cudaGetSymbolAddress(&p, g_h1h);    h1h    = (__half*)p;
    cudaGetSymbolAddress(&p, g_qkvh);   qkvh   = (__half*)p;
    cudaGetSymbolAddress(&p, g_qkph);   qkph   = (__half*)p;
    cudaGetSymbolAddress(&p, g_midh);   midh   = (__half*)p;
    cudaGetSymbolAddress(&p, g_ctxTh);  ctxTh  = (__half*)p;
    cudaGetSymbolAddress(&p, g_attn2h); attn2h = (__half*)p;
    cudaGetSymbolAddress(&p, g_x2);     x2     = (float*)p;
    cudaGetSymbolAddress(&p, g_diag);   ddiag  = (float*)p;
    cudaGetSymbolAddress(&p, g_rowf);   rowf   = (float*)p;
    cudaGetSymbolAddress(&p, g_ksum);   ksum   = (float*)p;
    cudaGetSymbolAddress(&p, g_bqkv);   bqkv   = (float*)p;

    __half* qh = qkvh;
    __half* vh = qkvh + 2*(size_t)NHR*DhD;
    __half* qph = qkph;
    __half* kph = qkph + (size_t)NHR*Mm;

    cudaFuncSetAttribute(hgemm<128,128,EPI_QKV,true>,       cudaFuncAttributeMaxDynamicSharedMemorySize, SMEM_H128x128);
    cudaFuncSetAttribute(feat_kernel,                       cudaFuncAttributeMaxDynamicSharedMemorySize, SMEM_FEAT);
    cudaFuncSetAttribute(hgemm<128,64,EPI_ATTN,true>,       cudaFuncAttributeMaxDynamicSharedMemorySize, SMEM_H128x64);
    cudaFuncSetAttribute(hgemm<128,128,EPI_BIAS_RES,false>, cudaFuncAttributeMaxDynamicSharedMemorySize, SMEM_H128x128);
    cudaFuncSetAttribute(hgemm<128,128,EPI_BIAS_GELU,true>, cudaFuncAttributeMaxDynamicSharedMemorySize, SMEM_H128x128);

    // fork: setup (weights) on s2 concurrent with LN1 on the main stream
    static cudaStream_t s2 = nullptr;
    static cudaEvent_t evf = nullptr, evj = nullptr;
    if (!s2){
        cudaStreamCreateWithFlags(&s2, cudaStreamNonBlocking);
        cudaEventCreateWithFlags(&evf, cudaEventDisableTiming);
        cudaEventCreateWithFlags(&evj, cudaEventDisableTiming);
    }
    cudaEventRecord(evf, 0);
    cudaStreamWaitEvent(s2, evf, 0);
    setup_kernel<<<(int)((SETUP_N + 255)/256), 256, 0, s2>>>(wq,wk,wv,wo,w1,w2,proj,bq,bk,bv);
    cudaEventRecord(evj, s2);
    ln_kernel<<<NROWS, 256>>>(x, ln1g, ln1b, h1h);
    cudaStreamWaitEvent(0, evj, 0);

    // fused QKV (N=2304) + fused diag (q,k), staged coalesced stores
    hgemm<128,128,EPI_QKV,true><<<dim3(18,128,1),256,SMEM_H128x128>>>(
        h1h,Dd,0, wqkvh,Dd,0, qkvh,DhD,0, NROWS,3*Dd,Dd, bqkv,nullptr,nullptr,0.f);

    // q+k features: dedicated kernel, 2 A-tiles/CTA, B staged once
    feat_kernel<<<dim3(NHR/128, 2), 256, SMEM_FEAT>>>(qh, projh, qkph, ddiag, rowf);

    // ctx (tensor mma, TN, 4-way m split) + fused ksum
    ctx_mma<<<dim3(4,NBH), 256, SMEM_CTX>>>(kph, vh, rowf, ctxTh, ksum);

    // attn = (qp @ ctx) / (qp . ksum)  [denominator fused], transpose -> attn2h [b,s,D]
    hgemm<128,64,EPI_ATTN,true><<<dim3(1,Ss/128,NBH),128,SMEM_H128x64>>>(
        qph,Mm,(long long)Ss*Mm, ctxTh,Mm,(long long)DhD*Mm, attn2h,DhD,0,
        Ss,DhD,Mm, nullptr,nullptr,ksum,0.f);

    // x2 = x + attn @ wo^T + bo (fp32)
    hgemm<128,128,EPI_BIAS_RES,false><<<dim3(6,128,1),256,SMEM_H128x128>>>(
        attn2h,Dd,0, woh,Dd,0, x2,Dd,0, NROWS,Dd,Dd, bo,x,nullptr,0.f);

    // LN2 -> half
    ln_kernel<<<NROWS, 256>>>(x2, ln2g, ln2b, h1h);

    // mid = gelu(h1 @ w1^T + b1) -> half
    hgemm<128,128,EPI_BIAS_GELU,true><<<dim3(FFH/128,128,1),256,SMEM_H128x128>>>(
        h1h,Dd,0, w1h,Dd,0, midh,FFH,0, NROWS,FFH,Dd, b1,nullptr,nullptr,0.f);

    // out = x2 + mid @ w2^T + b2 (fp32)
    hgemm<128,128,EPI_BIAS_RES,false><<<dim3(6,128,1),256,SMEM_H128x128>>>(
        midh,FFH,0, w2h,FFH,0, out,Dd,0, NROWS,Dd,FFH, b2,x2,nullptr,0.f);
}

// round 17
// speedup vs baseline: 1.0529x; 1.0141x over previous
#include <cuda_runtime.h>
#include <cuda_fp16.h>
#include <math.h>
#include <stdint.h>

// ---------------- problem constants ----------------
#define Bb   4
#define Ss   4096
#define Dd   768
#define Hh   12
#define Mm   256
#define DhD  64
#define NROWS (Bb*Ss)        // 16384
#define NBH   (Bb*Hh)        // 48
#define NHR   (NBH*Ss)       // 196608
#define FFH   (4*Dd)         // 3072

#define NORM_C   0.35355339059327373f
#define RATIO_C  0.0625f
#define DIAG_C   0.0625f
#define EPS_K    1e-4f
#define EPSR_C   (RATIO_C*EPS_K)
#define LN_EPS   1e-5f

// ---------------- scratch (device globals; allocation-free) ----------------
__device__ __half g_wqkvh[3*Dd*Dd];
__device__ float  g_bqkv[3*Dd];
__device__ __half g_woh[Dd*Dd];
__device__ __half g_w1h[FFH*Dd];
__device__ __half g_w2h[Dd*FFH];
__device__ __half g_projh[Mm*DhD];               // pre-scaled by NORM_C
__device__ __half g_h1h[NROWS*Dd];
__device__ __half g_qkvh[3*(size_t)NHR*DhD];      // q,k,v in [sel][b,h,s,dh]
__device__ __half g_qkph[2*(size_t)NHR*Mm];       // [qp | kp(exp(dd-rowmax))]
__device__ __half g_midh[(size_t)NROWS*FFH];
__device__ __half g_ctxTh[NBH*DhD*Mm];            // [bh][dh][m]
__device__ __half g_attn2h[(size_t)NROWS*Dd];     // [b,s,D]
__device__ float  g_x2[NROWS*Dd];
__device__ float  g_diag[2*NHR];                  // [q rows | k rows]
__device__ float  g_rowf[NHR];                    // rowmax(dd_k) - diag_k
__device__ float  g_ksum[NBH*Mm];
__device__ unsigned g_gmax_u;

// ---------------- epilogue modes ----------------
enum { EPI_BIAS_RES=1, EPI_BIAS_GELU=2, EPI_QKV=5, EPI_ATTN=8 };

__device__ __forceinline__ void cpa16(uint32_t smem_dst, const void* gsrc){
    asm volatile("cp.async.cg.shared.global [%0], [%1], 16;" :: "r"(smem_dst), "l"(gsrc));
}
#define CP_COMMIT() asm volatile("cp.async.commit_group;" ::: "memory")
#define CP_WAIT0()  asm volatile("cp.async.wait_group 0;" ::: "memory")
#define CP_WAIT1()  asm volatile("cp.async.wait_group 1;" ::: "memory")

__device__ __forceinline__ uint32_t smem_u32(const void* p){
    uint32_t a;
    asm("{ .reg .u64 t; cvta.to.shared.u64 t, %1; cvt.u32.u64 %0, t; }" : "=r"(a) : "l"(p));
    return a;
}

__device__ __forceinline__ void mma_f16(float* d, const uint32_t* a, const uint32_t* b){
    asm volatile("mma.sync.aligned.m16n8k16.row.col.f32.f16.f16.f32 "
        "{%0,%1,%2,%3}, {%4,%5,%6,%7}, {%8,%9}, {%0,%1,%2,%3};"
        : "+f"(d[0]),"+f"(d[1]),"+f"(d[2]),"+f"(d[3])
        : "r"(a[0]),"r"(a[1]),"r"(a[2]),"r"(a[3]), "r"(b[0]),"r"(b[1]));
}
#define LDSM4(r0,r1,r2,r3,addr) \
    asm volatile("ldmatrix.sync.aligned.m8n8.x4.shared.b16 {%0,%1,%2,%3}, [%4];" \
        : "=r"(r0),"=r"(r1),"=r"(r2),"=r"(r3) : "r"(addr))
#define LDSM4T(r0,r1,r2,r3,addr) \
    asm volatile("ldmatrix.sync.aligned.m8n8.x4.trans.shared.b16 {%0,%1,%2,%3}, [%4];" \
        : "=r"(r0),"=r"(r1),"=r"(r2),"=r"(r3) : "r"(addr))

__device__ __forceinline__ float gmax_decode(unsigned u){
    return (u & 0x80000000u) ? __uint_as_float(u ^ 0x80000000u) : __uint_as_float(~u);
}

// ================= fp16 NT GEMM: mma.sync m16n8k16, BK=64, 2-stage cp.async ============
// EPI_ATTN: rowscale = g_ksum base; denominator fused.
template<int BM,int BN,int EPI,bool OUTH>
__global__ void __launch_bounds__(32*(BM/64)*(BN/32), (BM==128 && BN==64) ? 3 : 2)
hgemm(const __half* __restrict__ A, int lda, long long strA,
      const __half* __restrict__ B, int ldb, long long strB,
      void* __restrict__ Cv, int ldc, long long strC,
      int M, int N, int K,
      const float* __restrict__ bias,
      const float* __restrict__ res,
      const float* __restrict__ rowscale,
      float alpha)
{
    constexpr int WY = BM/64, WX = BN/32, THREADS = 32*WY*WX;
    constexpr int LDKW = 36;
    constexpr int AW = BM*LDKW;
    constexpr int SW = (BM+BN)*LDKW;
    constexpr int ALD = (BM*8)/THREADS;
    constexpr int BLD = (BN*8)/THREADS;

    extern __shared__ uint32_t sh[];
    const uint32_t smb = smem_u32(sh);

    const int z = blockIdx.z;
    A += (long long)z*strA;  B += (long long)z*strB;
    float*  Cf = (float*)Cv  + (long long)z*strC;
    __half* Ch = (__half*)Cv + (long long)z*strC;

    const int brow = blockIdx.y*BM;
    const int bcol = blockIdx.x*BN;
    const int tid  = threadIdx.x;
    const int wid  = tid >> 5;
    const int lane = tid & 31;
    const int wx   = wid % WX, wy = wid / WX;
    const int warp_m = wy*64, warp_n = wx*32;
    const int g = lane >> 2, t = lane & 3;

    const uint32_t aoff = (uint32_t)(((warp_m + (lane&15))*LDKW + (lane>>4)*4))*4u;
    const uint32_t boff = (uint32_t)((AW + (warp_n + (lane>>4)*8 + (lane&7))*LDKW + ((lane>>3)&1)*4))*4u;

    float acc[4][4][4];
    #pragma unroll
    for (int i=0;i<4;i++)
        #pragma unroll
        for (int j=0;j<4;j++)
            #pragma unroll
            for (int u=0;u<4;u++) acc[i][j][u]=0.f;

    float den = 0.f;
    if (EPI==EPI_ATTN){
        float* sks = (float*)(sh + 2*SW);
        #pragma unroll
        for (int l=0; l<(Mm+THREADS-1)/THREADS; ++l){
            const int idx = tid + l*THREADS;
            if (idx < Mm) sks[idx] = rowscale[(long long)z*Mm + idx];
        }
    }

    const int nc = K >> 6;

    #define HISSUE(chunk) do{                                                  \
        const uint32_t bA_ = smb + (uint32_t)(((chunk)&1)*SW)*4u;              \
        const uint32_t bB_ = bA_ + (uint32_t)AW*4u;                            \
        const __half* Ap_ = A + (long long)brow*lda + (chunk)*64;              \
        const __half* Bp_ = B + (long long)bcol*ldb + (chunk)*64;              \
        _Pragma("unroll")                                                      \
        for (int l=0;l<ALD;l++){                                               \
            const int idx = tid + l*THREADS, r = idx>>3, c4 = idx&7;           \
            cpa16(bA_ + (uint32_t)(r*LDKW + c4*4)*4u,                          \
                  Ap_ + (long long)r*lda + c4*8);                              \
        }                                                                      \
        _Pragma("unroll")                                                      \
        for (int l=0;l<BLD;l++){                                               \
            const int idx = tid + l*THREADS, r = idx>>3, c4 = idx&7;           \
            cpa16(bB_ + (uint32_t)(r*LDKW + c4*4)*4u,                          \
                  Bp_ + (long long)r*ldb + c4*8);                              \
        }                                                                      \
    }while(0)

    HISSUE(0);
    CP_COMMIT();

    for (int i=0; i<nc; ++i){
        if (i+1 < nc){ HISSUE(i+1); CP_COMMIT(); CP_WAIT1(); }
        else         { CP_WAIT0(); }
        __syncthreads();

        const uint32_t stg = smb + (uint32_t)((i&1)*SW)*4u;

        if (EPI==EPI_ATTN){
            const float* sks = (const float*)(sh + 2*SW) + i*64;
            const uint4* arow4 = reinterpret_cast<const uint4*>(sh + (i&1)*SW + tid*LDKW);
            #pragma unroll
            for (int j=0;j<8;j++){
                uint4 w4 = arow4[j];
                float2 f0 = __half22float2(*reinterpret_cast<__half2*>(&w4.x));
                float2 f1 = __half22float2(*reinterpret_cast<__half2*>(&w4.y));
                float2 f2 = __half22float2(*reinterpret_cast<__half2*>(&w4.z));
                float2 f3 = __half22float2(*reinterpret_cast<__half2*>(&w4.w));
                den += f0.x*sks[8*j]   + f0.y*sks[8*j+1]
                     + f1.x*sks[8*j+2] + f1.y*sks[8*j+3]
                     + f2.x*sks[8*j+4] + f2.y*sks[8*j+5]
                     + f3.x*sks[8*j+6] + f3.y*sks[8*j+7];
            }
        }

        #pragma unroll
        for (int kk=0; kk<4; ++kk){
            uint32_t af[4][4], bf[4][2];
            #pragma unroll
            for (int mt=0; mt<4; ++mt)
                LDSM4(af[mt][0],af[mt][1],af[mt][2],af[mt][3],
                      stg + aoff + (uint32_t)((mt*16*LDKW + kk*8))*4u);
            LDSM4(bf[0][0],bf[0][1],bf[1][0],bf[1][1],
                  stg + boff + (uint32_t)(kk*8)*4u);
            LDSM4(bf[2][0],bf[2][1],bf[3][0],bf[3][1],
                  stg + boff + (uint32_t)((16*LDKW + kk*8))*4u);
            #pragma unroll
            for (int mt=0; mt<4; ++mt)
                #pragma unroll
                for (int nt=0; nt<4; ++nt)
                    mma_f16(acc[mt][nt], af[mt], bf[nt]);
        }
        __syncthreads();
    }
    #undef HISSUE

    float* sden = nullptr;
    if (EPI==EPI_ATTN){
        sden = (float*)(sh + 2*SW) + Mm;
        sden[tid] = 1.0f/den;
        __syncthreads();
    }

    float sq[4][2];
    if (EPI==EPI_QKV){
        #pragma unroll
        for (int mt=0; mt<4; ++mt){ sq[mt][0]=0.f; sq[mt][1]=0.f; }
    }
    __half* sm16q = (__half*)sh;               // QKV stage: [128][136]

    #pragma unroll
    for (int mt=0; mt<4; ++mt){
        const int r0 = brow + warp_m + mt*16 + g;
        const int r1 = r0 + 8;
        float rs0 = 1.f, rs1 = 1.f;
        if (EPI==EPI_ATTN){
            rs0 = sden[warp_m + mt*16 + g];
            rs1 = sden[warp_m + mt*16 + 8 + g];
        }
        #pragma unroll
        for (int nt=0; nt<4; ++nt){
            const int c0 = bcol + warp_n + nt*8 + 2*t;
            float v00 = acc[mt][nt][0], v01 = acc[mt][nt][1];
            float v10 = acc[mt][nt][2], v11 = acc[mt][nt][3];
            if (EPI==EPI_BIAS_RES || EPI==EPI_BIAS_GELU || EPI==EPI_QKV){
                const float b0 = bias[c0], b1 = bias[c0+1];
                v00 += b0; v01 += b1; v10 += b0; v11 += b1;
            }
            if (EPI==EPI_BIAS_RES){
                v00 += res[(long long)r0*ldc + c0];   v01 += res[(long long)r0*ldc + c0+1];
                v10 += res[(long long)r1*ldc + c0];   v11 += res[(long long)r1*ldc + c0+1];
            }
            if (EPI==EPI_BIAS_GELU){
                v00 = 0.5f*v00*(1.0f+erff(v00*0.70710678118654752f));
                v01 = 0.5f*v01*(1.0f+erff(v01*0.70710678118654752f));
                v10 = 0.5f*v10*(1.0f+erff(v10*0.70710678118654752f));
                v11 = 0.5f*v11*(1.0f+erff(v11*0.70710678118654752f));
            }
            if (EPI==EPI_ATTN){ v00*=rs0; v01*=rs0; v10*=rs1; v11*=rs1; }

            if (EPI==EPI_QKV){
                sq[mt][0] += v00*v00 + v01*v01;
                sq[mt][1] += v10*v10 + v11*v11;
                const int rl0 = warp_m + mt*16 + g;
                const int cl  = warp_n + nt*8 + 2*t;
                *reinterpret_cast<__half2*>(sm16q + rl0*136 + cl)     = __floats2half2_rn(v00,v01);
                *reinterpret_cast<__half2*>(sm16q + (rl0+8)*136 + cl) = __floats2half2_rn(v10,v11);
            } else if (EPI==EPI_ATTN){
                const int bb = z/Hh, hh = z - (z/Hh)*Hh;
                __half* base = (__half*)Cv;
                const long long o0 = ((long long)(bb*Ss + r0))*Dd + hh*64 + c0;
                const long long o1 = ((long long)(bb*Ss + r1))*Dd + hh*64 + c0;
                *reinterpret_cast<__half2*>(base + o0) = __floats2half2_rn(v00,v01);
                *reinterpret_cast<__half2*>(base + o1) = __floats2half2_rn(v10,v11);
            } else if (OUTH){
                *reinterpret_cast<__half2*>(Ch + (long long)r0*ldc + c0) = __floats2half2_rn(v00,v01);
                *reinterpret_cast<__half2*>(Ch + (long long)r1*ldc + c0) = __floats2half2_rn(v10,v11);
            } else {
                float2 o0; o0.x=v00; o0.y=v01;
                float2 o1; o1.x=v10; o1.y=v11;
                *reinterpret_cast<float2*>(Cf + (long long)r0*ldc + c0) = o0;
                *reinterpret_cast<float2*>(Cf + (long long)r1*ldc + c0) = o1;
            }
        }
    }

    if (EPI==EPI_QKV){
        const int sel_t = bcol/Dd;
        const int cc0   = bcol - sel_t*Dd;
        float* red = (float*)(sh + 8704);
        #pragma unroll
        for (int mt=0; mt<4; ++mt){
            #pragma unroll
            for (int j=0;j<2;j++){
                float v = sq[mt][j];
                v += __shfl_xor_sync(0xffffffffu, v, 1);
                v += __shfl_xor_sync(0xffffffffu, v, 2);
                if (t==0) red[(warp_m + mt*16 + j*8 + g)*4 + wx] = v;
            }
        }
        __syncthreads();
        if (sel_t < 2){
            const int row  = tid >> 1;
            const int head = tid & 1;
            const float ssum = red[row*4 + 2*head] + red[row*4 + 2*head + 1];
            const int gr = brow + row;
            const int b_ = gr>>12, s_ = gr&4095;
            const int h_ = (cc0>>6) + head;
            g_diag[(size_t)sel_t*NHR + (((long long)(b_*Hh+h_))<<12) + s_] = DIAG_C*ssum;
        }
        const int b_ = brow>>12, s0 = brow&4095;
        __half* base = (__half*)Cv + (size_t)sel_t*NHR*DhD;
        #pragma unroll
        for (int it=0; it<8; ++it){
            const int idx = tid + it*256;
            const int head = idx >> 10;
            const int rem = idx & 1023;
            const int row = rem >> 3, ch = rem & 7;
            uint4 v4 = *reinterpret_cast<const uint4*>(sm16q + row*136 + head*64 + ch*8);
            const int h_ = (cc0>>6) + head;
            *reinterpret_cast<uint4*>(base + ((((long long)(b_*Hh+h_))<<12) + s0 + row)*DhD + ch*8) = v4;
        }
    }
}

#define SMEM_H128x128 (2*(128+128)*36*4)                  // 73728
#define SMEM_H128x64  (2*(128+64)*36*4 + (Mm+128)*4)      // 55296 + 1536

// ================ dedicated FEAT kernel: 2 A-tiles per CTA, B staged once =============
// zp=0: q features RATIO*(exp(dd-diag-rowmax)+eps); zp=1: k features exp(dd-rowmax),
// rowf = rowmax - diag, gmax atomic.
#define F_LDKW 36
#define F_AW   (64*F_LDKW)
#define F_BOFF (2*F_AW)
#define F_BW   (256*F_LDKW)
#define F_EPW  (F_BOFF + F_BW)
#define SMEM_FEAT (F_EPW*4 + 64*264*2 + 64*8*4)   // 91136

__global__ void __launch_bounds__(256, 2)
feat_kernel(const __half* __restrict__ qk, const __half* __restrict__ projh,
            __half* __restrict__ qkp, const float* __restrict__ ddiag,
            float* __restrict__ rowf, const int z)
{
    extern __shared__ uint32_t sh[];
    const uint32_t smb = smem_u32(sh);

    const int brow0 = blockIdx.x*128;
    const __half* A = qk + (size_t)z*NHR*DhD;
    __half* Ch = qkp + (size_t)z*NHR*Mm;

    const int tid = threadIdx.x, wid = tid>>5, lane = tid&31;
    const int warp_n = wid*32;
    const int g = lane>>2, t = lane&3;

    const uint32_t aoff = (uint32_t)(((lane&15)*F_LDKW + (lane>>4)*4))*4u;
    const uint32_t boff = (uint32_t)((F_BOFF + (warp_n + (lane>>4)*8 + (lane&7))*F_LDKW + ((lane>>3)&1)*4))*4u;

    __half* smE = (__half*)sh + F_EPW*2;
    float*  red = (float*)((char*)sh + F_EPW*4 + 64*264*2);

    #pragma unroll
    for (int l=0;l<8;l++){
        const int idx = tid + l*256, r = idx>>3, c4 = idx&7;
        cpa16(smb + (uint32_t)(F_BOFF + r*F_LDKW + c4*4)*4u, projh + (long long)r*DhD + c4*8);
    }
    #pragma unroll
    for (int l=0;l<2;l++){
        const int idx = tid + l*256, r = idx>>3, c4 = idx&7;
        cpa16(smb + (uint32_t)(r*F_LDKW + c4*4)*4u, A + (long long)(brow0+r)*DhD + c4*8);
    }
    CP_COMMIT();
    #pragma unroll
    for (int l=0;l<2;l++){
        const int idx = tid + l*256, r = idx>>3, c4 = idx&7;
        cpa16(smb + (uint32_t)(F_AW + r*F_LDKW + c4*4)*4u, A + (long long)(brow0+64+r)*DhD + c4*8);
    }
    CP_COMMIT();
    CP_WAIT1();
    __syncthreads();

    #pragma unroll
    for (int rb=0; rb<2; ++rb){
        if (rb==1){ CP_WAIT0(); __syncthreads(); }
        const uint32_t stg = smb + (uint32_t)(rb*F_AW)*4u;

        float acc[4][4][4];
        #pragma unroll
        for (int i=0;i<4;i++)
            #pragma unroll
            for (int j=0;j<4;j++)
                #pragma unroll
                for (int u=0;u<4;u++) acc[i][j][u]=0.f;

        #pragma unroll
        for (int kk=0; kk<4; ++kk){
            uint32_t af[4][4], bf[4][2];
            #pragma unroll
            for (int mt=0; mt<4; ++mt)
                LDSM4(af[mt][0],af[mt][1],af[mt][2],af[mt][3],
                      stg + aoff + (uint32_t)((mt*16*F_LDKW + kk*8))*4u);
            LDSM4(bf[0][0],bf[0][1],bf[1][0],bf[1][1],
                  smb + boff + (uint32_t)(kk*8)*4u);
            LDSM4(bf[2][0],bf[2][1],bf[3][0],bf[3][1],
                  smb + boff + (uint32_t)((16*F_LDKW + kk*8))*4u);
            #pragma unroll
            for (int mt=0; mt<4; ++mt)
                #pragma unroll
                for (int nt=0; nt<4; ++nt)
                    mma_f16(acc[mt][nt], af[mt], bf[nt]);
        }

        const int brow = brow0 + rb*64;
        float mxs[4][2];
        #pragma unroll
        for (int mt=0; mt<4; ++mt){
            float m0=-3.402823466e38f, m1=m0;
            #pragma unroll
            for (int nt=0; nt<4; ++nt){
                m0 = fmaxf(m0, fmaxf(acc[mt][nt][0], acc[mt][nt][1]));
                m1 = fmaxf(m1, fmaxf(acc[mt][nt][2], acc[mt][nt][3]));
            }
            m0 = fmaxf(m0, __shfl_xor_sync(0xffffffffu,m0,1));
            m0 = fmaxf(m0, __shfl_xor_sync(0xffffffffu,m0,2));
            m1 = fmaxf(m1, __shfl_xor_sync(0xffffffffu,m1,1));
            m1 = fmaxf(m1, __shfl_xor_sync(0xffffffffu,m1,2));
            mxs[mt][0]=m0; mxs[mt][1]=m1;
        }
        __syncthreads();
        if (t==0){
            #pragma unroll
            for (int mt=0; mt<4; ++mt){
                red[(mt*16+g)*8 + wid]   = mxs[mt][0];
                red[(mt*16+8+g)*8 + wid] = mxs[mt][1];
            }
        }
        __syncthreads();
        float dd0[4], dd1[4];
        #pragma unroll
        for (int mt=0; mt<4; ++mt){
            const int grow = brow + mt*16 + g;
            float mx0 = red[(mt*16+g)*8], mx1 = red[(mt*16+8+g)*8];
            #pragma unroll
            for (int w=1; w<8; ++w){
                mx0 = fmaxf(mx0, red[(mt*16+g)*8+w]);
                mx1 = fmaxf(mx1, red[(mt*16+8+g)*8+w]);
            }
            mxs[mt][0]=mx0; mxs[mt][1]=mx1;
            if (z==0){ dd0[mt] = ddiag[grow] + mx0; dd1[mt] = ddiag[grow+8] + mx1; }
            else     { dd0[mt] = mx0;               dd1[mt] = mx1; }
            if (z==1 && wid==0 && t==0){
                rowf[grow]   = mx0 - ddiag[(long long)NHR + grow];
                rowf[grow+8] = mx1 - ddiag[(long long)NHR + grow+8];
            }
        }
        if (z==1 && wid==0){
            float bm = fmaxf(fmaxf(mxs[0][0],mxs[0][1]), fmaxf(mxs[1][0],mxs[1][1]));
            bm = fmaxf(bm, fmaxf(fmaxf(mxs[2][0],mxs[2][1]), fmaxf(mxs[3][0],mxs[3][1])));
            #pragma unroll
            for (int o=16;o;o>>=1) bm = fmaxf(bm, __shfl_xor_sync(0xffffffffu,bm,o));
            if (lane==0){
                unsigned b = __float_as_uint(bm);
                unsigned u = (b & 0x80000000u) ? ~b : (b | 0x80000000u);
                atomicMax(&g_gmax_u, u);
            }
        }
        __syncthreads();
        #pragma unroll
        for (int mt=0; mt<4; ++mt){
            #pragma unroll
            for (int nt=0; nt<4; ++nt){
                const int c0 = warp_n + nt*8 + 2*t;
                __half2 o0, o1;
                if (z==0){
                    o0 = __floats2half2_rn(fmaf(__expf(acc[mt][nt][0]-dd0[mt]), RATIO_C, EPSR_C),
                                           fmaf(__expf(acc[mt][nt][1]-dd0[mt]), RATIO_C, EPSR_C));
                    o1 = __floats2half2_rn(fmaf(__expf(acc[mt][nt][2]-dd1[mt]), RATIO_C, EPSR_C),
                                           fmaf(__expf(acc[mt][nt][3]-dd1[mt]), RATIO_C, EPSR_C));
                } else {
                    o0 = __floats2half2_rn(__expf(acc[mt][nt][0]-dd0[mt]), __expf(acc[mt][nt][1]-dd0[mt]));
                    o1 = __floats2half2_rn(__expf(acc[mt][nt][2]-dd1[mt]), __expf(acc[mt][nt][3]-dd1[mt]));
                }
                *reinterpret_cast<__half2*>(smE + (mt*16+g)*264 + c0)   = o0;
                *reinterpret_cast<__half2*>(smE + (mt*16+8+g)*264 + c0) = o1;
            }
        }
        __syncthreads();
        #pragma unroll
        for (int it=0; it<8; ++it){
            const int idx = tid + it*256;
            const int row = idx >> 5, cc = idx & 31;
            uint4 v4 = *reinterpret_cast<const uint4*>(smE + row*264 + cc*8);
            *reinterpret_cast<uint4*>(Ch + (long long)(brow+row)*Mm + cc*8) = v4;
        }
    }
}

// ================ ctx TN mma kernel, 4-way m split (BK=32, 3-stage) ====================
#define CTX_LDV 36
#define CTX_LDP 36
#define CTX_VW  (32*CTX_LDV)
#define CTX_PW  (32*CTX_LDP)
#define SMEM_CTX (3*(CTX_VW+CTX_PW)*4)     // 27648

__global__ void __launch_bounds__(256, 2)
ctx_mma(const __half* __restrict__ kpe, const __half* __restrict__ vh,
        const float* __restrict__ rowf,
        __half* __restrict__ ctxT, float* __restrict__ ksum)
{
    extern __shared__ uint32_t sh[];
    const uint32_t smb = smem_u32(sh);
    const uint32_t pbase = smb + (uint32_t)(3*CTX_VW)*4u;

    const int z = blockIdx.y;
    const int ntile = blockIdx.x;
    const int tid = threadIdx.x, wid = tid>>5, lane = tid&31;
    const int warp_m = (wid & 3)*16;
    const int warp_n = (wid >> 2)*32;
    const int g = lane>>2, t = lane&3;
    const int quad = lane>>3, r8 = lane&7;

    const __half* kpb = kpe + (long long)z*Ss*Mm + ntile*64;
    const __half* vhb = vh  + (long long)z*Ss*DhD;
    const float*  rfb = rowf + (long long)z*Ss;

    const float gmax = gmax_decode(g_gmax_u);
    const float epsr = EPSR_C;

    const uint32_t a_off0 = (uint32_t)((r8 + ((quad>>1)&1)*8)*CTX_LDV + (warp_m + (quad&1)*8)/2);
    const uint32_t b_off0 = (uint32_t)((r8 + (quad&1)*8)*CTX_LDP + (warp_n + (quad>>1)*8)/2);

    const int srow = tid >> 3;
    const int c8   = tid & 7;

    float acc[4][4];
    #pragma unroll
    for (int j=0;j<4;j++)
        #pragma unroll
        for (int u=0;u<4;u++) acc[j][u]=0.f;
    float ks[8];
    #pragma unroll
    for (int j=0;j<8;j++) ks[j]=0.f;

    #define VISSUE(c) do{ \
        const uint32_t bV = smb + (uint32_t)(((c)%3)*CTX_VW)*4u; \
        cpa16(bV + (uint32_t)(srow*CTX_LDV + c8*4)*4u, \
              vhb + (long long)((c)*32 + srow)*DhD + c8*8); \
    }while(0)

    uint4 cur; float curf;
    cur  = *reinterpret_cast<const uint4*>(kpb + (long long)srow*Mm + c8*8);
    curf = rfb[srow];
    VISSUE(0); CP_COMMIT();
    VISSUE(1); CP_COMMIT();

    for (int i=0; i<Ss/32; ++i){
        {
            const float As = RATIO_C*__expf(curf - gmax);
            uint32_t rw[4] = {cur.x,cur.y,cur.z,cur.w};
            uint32_t ow[4];
            #pragma unroll
            for (int j=0;j<4;j++){
                float2 f = __half22float2(*reinterpret_cast<__half2*>(&rw[j]));
                f.x = fmaf(f.x, As, epsr);
                f.y = fmaf(f.y, As, epsr);
                __half2 h = __floats2half2_rn(f.x, f.y);
                float2 fr = __half22float2(h);
                ks[2*j]   += fr.x;
                ks[2*j+1] += fr.y;
                ow[j] = *reinterpret_cast<uint32_t*>(&h);
            }
            const uint32_t bP = pbase + (uint32_t)((i%3)*CTX_PW)*4u
                              + (uint32_t)(srow*CTX_LDP + c8*4)*4u;
            uint4 s0 = {ow[0],ow[1],ow[2],ow[3]};
            *reinterpret_cast<uint4*>((char*)sh + (bP - smb)) = s0;
        }
        CP_WAIT1();
        __syncthreads();
        if (i+2 < Ss/32) VISSUE(i+2);
        CP_COMMIT();
        if (i+1 < Ss/32){
            cur  = *reinterpret_cast<const uint4*>(kpb + (long long)((i+1)*32 + srow)*Mm + c8*8);
            curf = rfb[(i+1)*32 + srow];
        }

        const uint32_t vstg = smb + (uint32_t)((i%3)*CTX_VW)*4u;
        const uint32_t pstg = pbase + (uint32_t)((i%3)*CTX_PW)*4u;

        #pragma unroll
        for (int kk=0; kk<2; ++kk){
            uint32_t af[4], bf[4][2];
            LDSM4T(af[0],af[1],af[2],af[3],
                   vstg + (a_off0 + (uint32_t)(kk*16*CTX_LDV))*4u);
            #pragma unroll
            for (int pp2=0; pp2<2; ++pp2)
                LDSM4T(bf[2*pp2][0],bf[2*pp2][1],bf[2*pp2+1][0],bf[2*pp2+1][1],
                       pstg + (b_off0 + (uint32_t)(kk*16*CTX_LDP + pp2*8))*4u);
            #pragma unroll
            for (int nt=0; nt<4; ++nt)
                mma_f16(acc[nt], af, bf[nt]);
        }
    }
    #undef VISSUE

    const int dh0 = warp_m + g;
    const int dh1 = dh0 + 8;
    #pragma unroll
    for (int nt=0; nt<4; ++nt){
        const int col = ntile*64 + warp_n + nt*8 + 2*t;
        *reinterpret_cast<__half2*>(ctxT + (long long)z*DhD*Mm + (long long)dh0*Mm + col)
            = __floats2half2_rn(acc[nt][0], acc[nt][1]);
        *reinterpret_cast<__half2*>(ctxT + (long long)z*DhD*Mm + (long long)dh1*Mm + col)
            = __floats2half2_rn(acc[nt][2], acc[nt][3]);
    }

    __syncthreads();
    float* red = (float*)sh;
    #pragma unroll
    for (int j=0;j<8;j++) red[srow*64 + c8*8 + j] = ks[j];
    __syncthreads();
    if (tid < 64){
        float s = 0.f;
        #pragma unroll
        for (int r=0;r<32;r++) s += red[r*64 + tid];
        ksum[z*Mm + ntile*64 + tid] = s;
    }
}

// ---------------- single setup kernel: all weight f2h + bias pack + gmax reset --------
__global__ void setup_kernel(const float* __restrict__ wq, const float* __restrict__ wk,
                             const float* __restrict__ wv, const float* __restrict__ wo,
                             const float* __restrict__ w1, const float* __restrict__ w2,
                             const float* __restrict__ proj,
                             const float* __restrict__ bq, const float* __restrict__ bk,
                             const float* __restrict__ bv)
{
    const long long i = (long long)blockIdx.x*256 + threadIdx.x;
    const long long Q = Dd*Dd/4;
    const long long W = (long long)FFH*Dd/4;
    const long long P = Mm*DhD/4;
    const long long T0 = 4*Q, T1 = T0 + 2*W + P, T2 = T1 + 3*Dd;
    if (i < T0){
        const int seg = (int)(i/Q), off = (int)(i - seg*Q);
        const float* s = (seg==0)?wq:(seg==1)?wk:(seg==2)?wv:wo;
        __half* d = (seg<3) ? (g_wqkvh + (size_t)seg*Dd*Dd) : g_woh;
        float4 v = reinterpret_cast<const float4*>(s)[off];
        __half2* o = reinterpret_cast<__half2*>(d) + 2*off;
        o[0] = __floats2half2_rn(v.x, v.y);
        o[1] = __floats2half2_rn(v.z, v.w);
    } else if (i < T1){
        long long j = i - T0;
        const float* s; __half* d; int off; float scale = 1.f;
        if (j < W)          { s = w1;   d = g_w1h;   off = (int)j; }
        else if (j < 2*W)   { s = w2;   d = g_w2h;   off = (int)(j - W); }
        else                { s = proj; d = g_projh; off = (int)(j - 2*W); scale = NORM_C; }
        float4 v = reinterpret_cast<const float4*>(s)[off];
        __half2* o = reinterpret_cast<__half2*>(d) + 2*off;
        o[0] = __floats2half2_rn(v.x*scale, v.y*scale);
        o[1] = __floats2half2_rn(v.z*scale, v.w*scale);
    } else if (i < T2){
        const int j = (int)(i - T1);
        const int sel = j/Dd, c = j - sel*Dd;
        g_bqkv[j] = sel==0 ? bq[c] : (sel==1 ? bk[c] : bv[c]);
    } else if (i == T2){
        g_gmax_u = 0u;
    }
}
#define SETUP_N (4LL*(Dd*Dd/4) + 2LL*((long long)FFH*Dd/4) + Mm*DhD/4 + 3*Dd + 1)

// ---------------- LayerNorm (row=768), half output ----------------
__global__ void ln_kernel(const float* __restrict__ x, const float* __restrict__ g,
                          const float* __restrict__ b, __half* __restrict__ out)
{
    const int row = blockIdx.x;
    const float* xr = x + (long long)row*Dd;
    float v[3]; float s=0.f, ss=0.f;
    #pragma unroll
    for (int i=0;i<3;i++){ v[i]=xr[threadIdx.x + i*256]; s+=v[i]; ss+=v[i]*v[i]; }
    #pragma unroll
    for (int o=16;o;o>>=1){ s+=__shfl_xor_sync(0xffffffffu,s,o); ss+=__shfl_xor_sync(0xffffffffu,ss,o); }
    __shared__ float rs_[8], rss_[8];
    const int lane = threadIdx.x & 31, w = threadIdx.x >> 5;
    if (lane==0){ rs_[w]=s; rss_[w]=ss; }
    __syncthreads();
    s=0.f; ss=0.f;
    #pragma unroll
    for (int i=0;i<8;i++){ s+=rs_[i]; ss+=rss_[i]; }
    const float mu  = s*(1.0f/Dd);
    const float var = ss*(1.0f/Dd) - mu*mu;
    const float rstd = rsqrtf(var + LN_EPS);
    __half* outr = out + (long long)row*Dd;
    #pragma unroll
    for (int i=0;i<3;i++){
        int c = threadIdx.x + i*256;
        outr[c] = __float2half((v[i]-mu)*rstd*g[c] + b[c]);
    }
}

// ---------------- host ----------------
extern "C" void kernel_launch(void* const* d_in, const int* in_sizes, int n_in,
                              void* d_out, int out_size)
{
    const float* x    = (const float*)d_in[0];
    const float* proj = (const float*)d_in[1];
    const float* wq   = (const float*)d_in[2];
    const float* bq   = (const float*)d_in[3];
    const float* wk   = (const float*)d_in[4];
    const float* bk   = (const float*)d_in[5];
    const float* wv   = (const float*)d_in[6];
    const float* bv   = (const float*)d_in[7];
    const float* wo   = (const float*)d_in[8];
    const float* bo   = (const float*)d_in[9];
    const float* ln1g = (const float*)d_in[10];
    const float* ln1b = (const float*)d_in[11];
    const float* ln2g = (const float*)d_in[12];
    const float* ln2b = (const float*)d_in[13];
    const float* w1   = (const float*)d_in[14];
    const float* b1   = (const float*)d_in[15];
    const float* w2   = (const float*)d_in[16];
    const float* b2   = (const float*)d_in[17];
    float* out = (float*)d_out;

    void *p;
    __half *wqkvh, *h1h, *qkvh, *qkph, *midh, *ctxTh, *attn2h, *woh, *w1h, *w2h, *projh;
    float *ddiag, *rowf, *x2, *ksum, *bqkv;
    cudaGetSymbolAddress(&p, g_wqkvh);  wqkvh  = (__half*)p;
    cudaGetSymbolAddress(&p, g_woh);    woh    = (__half*)p;
    cudaGetSymbolAddress(&p, g_w1h);    w1h    = (__half*)p;
    cudaGetSymbolAddress(&p, g_w2h);    w2h    = (__half*)p;
    cudaGetSymbolAddress(&p, g_projh);  projh  = (__half*)p;
    cudaGetSymbolAddress(&p, g_h1h);    h1h    = (__half*)p;
    cudaGetSymbolAddress(&p, g_qkvh);   qkvh   = (__half*)p;
    cudaGetSymbolAddress(&p, g_qkph);   qkph   = (__half*)p;
    cudaGetSymbolAddress(&p, g_midh);   midh   = (__half*)p;
    cudaGetSymbolAddress(&p, g_ctxTh);  ctxTh  = (__half*)p;
    cudaGetSymbolAddress(&p, g_attn2h); attn2h = (__half*)p;
    cudaGetSymbolAddress(&p, g_x2);     x2     = (float*)p;
    cudaGetSymbolAddress(&p, g_diag);   ddiag  = (float*)p;
    cudaGetSymbolAddress(&p, g_rowf);   rowf   = (float*)p;
    cudaGetSymbolAddress(&p, g_ksum);   ksum   = (float*)p;
    cudaGetSymbolAddress(&p, g_bqkv);   bqkv   = (float*)p;

    __half* qh = qkvh;
    __half* vh = qkvh + 2*(size_t)NHR*DhD;
    __half* qph = qkph;
    __half* kph = qkph + (size_t)NHR*Mm;

    cudaFuncSetAttribute(hgemm<128,128,EPI_QKV,true>,       cudaFuncAttributeMaxDynamicSharedMemorySize, SMEM_H128x128);
    cudaFuncSetAttribute(feat_kernel,                       cudaFuncAttributeMaxDynamicSharedMemorySize, SMEM_FEAT);
    cudaFuncSetAttribute(hgemm<128,64,EPI_ATTN,true>,       cudaFuncAttributeMaxDynamicSharedMemorySize, SMEM_H128x64);
    cudaFuncSetAttribute(hgemm<128,128,EPI_BIAS_RES,false>, cudaFuncAttributeMaxDynamicSharedMemorySize, SMEM_H128x128);
    cudaFuncSetAttribute(hgemm<128,128,EPI_BIAS_GELU,true>, cudaFuncAttributeMaxDynamicSharedMemorySize, SMEM_H128x128);

    // streams/events (created once, outside capture)
    static cudaStream_t s2 = nullptr;
    static cudaEvent_t evf = nullptr, evj = nullptr, evq = nullptr, evj2 = nullptr;
    if (!s2){
        cudaStreamCreateWithFlags(&s2, cudaStreamNonBlocking);
        cudaEventCreateWithFlags(&evf, cudaEventDisableTiming);
        cudaEventCreateWithFlags(&evj, cudaEventDisableTiming);
        cudaEventCreateWithFlags(&evq, cudaEventDisableTiming);
        cudaEventCreateWithFlags(&evj2, cudaEventDisableTiming);
    }

    // fork 1: setup (weights) on s2 concurrent with LN1 on the main stream
    cudaEventRecord(evf, 0);
    cudaStreamWaitEvent(s2, evf, 0);
    setup_kernel<<<(int)((SETUP_N + 255)/256), 256, 0, s2>>>(wq,wk,wv,wo,w1,w2,proj,bq,bk,bv);
    cudaEventRecord(evj, s2);
    ln_kernel<<<NROWS, 256>>>(x, ln1g, ln1b, h1h);
    cudaStreamWaitEvent(0, evj, 0);

    // fused QKV (N=2304) + fused diag (q,k), staged coalesced stores
    hgemm<128,128,EPI_QKV,true><<<dim3(18,128,1),256,SMEM_H128x128>>>(
        h1h,Dd,0, wqkvh,Dd,0, qkvh,DhD,0, NROWS,3*Dd,Dd, bqkv,nullptr,nullptr,0.f);

    // fork 2: q-features on s2 concurrent with {k-features -> ctx} on stream 0
    cudaEventRecord(evq, 0);
    cudaStreamWaitEvent(s2, evq, 0);
    feat_kernel<<<NHR/128, 256, SMEM_FEAT, s2>>>(qh, projh, qkph, ddiag, rowf, 0);
    cudaEventRecord(evj2, s2);

    feat_kernel<<<NHR/128, 256, SMEM_FEAT>>>(qh, projh, qkph, ddiag, rowf, 1);
    ctx_mma<<<dim3(4,NBH), 256, SMEM_CTX>>>(kph, vh, rowf, ctxTh, ksum);
    cudaStreamWaitEvent(0, evj2, 0);

    // attn = (qp @ ctx) / (qp . ksum)  [denominator fused], transpose -> attn2h [b,s,D]
    hgemm<128,64,EPI_ATTN,true><<<dim3(1,Ss/128,NBH),128,SMEM_H128x64>>>(
        qph,Mm,(long long)Ss*Mm, ctxTh,Mm,(long long)DhD*Mm, attn2h,DhD,0,
        Ss,DhD,Mm, nullptr,nullptr,ksum,0.f);

    // x2 = x + attn @ wo^T + bo (fp32)
    hgemm<128,128,EPI_BIAS_RES,false><<<dim3(6,128,1),256,SMEM_H128x128>>>(
        attn2h,Dd,0, woh,Dd,0, x2,Dd,0, NROWS,Dd,Dd, bo,x,nullptr,0.f);

    // LN2 -> half
    ln_kernel<<<NROWS, 256>>>(x2, ln2g, ln2b, h1h);

    // mid = gelu(h1 @ w1^T + b1) -> half
    hgemm<128,128,EPI_BIAS_GELU,true><<<dim3(FFH/128,128,1),256,SMEM_H128x128>>>(
        h1h,Dd,0, w1h,Dd,0, midh,FFH,0, NROWS,FFH,Dd, b1,nullptr,nullptr,0.f);

    // out = x2 + mid @ w2^T + b2 (fp32)
    hgemm<128,128,EPI_BIAS_RES,false><<<dim3(6,128,1),256,SMEM_H128x128>>>(
        midh,FFH,0, w2h,FFH,0, out,Dd,0, NROWS,Dd,FFH, b2,x2,nullptr,0.f);
}